// round 2
// baseline (speedup 1.0000x reference)
#include <cuda_runtime.h>
#include <cuda_bf16.h>
#include <math.h>

// Problem constants (fixed by the reference setup)
#define BATCH 2
#define SEQ   2048
#define DMODEL 1024
#define NHEAD 16
#define HDIM  64
#define M_ROWS (BATCH * SEQ)          // 4096
#define N_QKV  (3 * DMODEL)           // 3072
#define INV_SCALE 0.125f              // 1/sqrt(64)

// Scratch: q/k/v in [B,H,S,HD] layout, attn output in [B,S,D] (merged heads)
__device__ float g_q[BATCH * NHEAD * SEQ * HDIM];
__device__ float g_k[BATCH * NHEAD * SEQ * HDIM];
__device__ float g_v[BATCH * NHEAD * SEQ * HDIM];
__device__ float g_att[M_ROWS * DMODEL];

// ---------------------------------------------------------------------------
// SGEMM: C[M,N] = A[M,K] @ W[K,N] + bias.
// MODE 0: A = x param, epilogue scatters into g_q/g_k/g_v ([B,H,S,HD])
// MODE 1: A = g_att,   epilogue writes Cout (d_out) with bias
// BM=BN=128, BK=8, 256 threads, 8x8 per thread.
// ---------------------------------------------------------------------------
template <int MODE>
__global__ __launch_bounds__(256) void sgemm_kernel(
    const float* __restrict__ A, const float* __restrict__ W,
    const float* __restrict__ bias, float* __restrict__ Cout,
    int M, int N, int K)
{
    __shared__ float As[8][128];   // transposed A tile
    __shared__ float Bs[8][128];

    const int tid = threadIdx.x;
    const int mBase = blockIdx.y * 128;
    const int nBase = blockIdx.x * 128;
    const int tx = tid & 15;       // 16 thread-cols
    const int ty = tid >> 4;       // 16 thread-rows

    const float* Aeff = (MODE == 0) ? A : g_att;

    float acc[8][8];
#pragma unroll
    for (int i = 0; i < 8; i++)
#pragma unroll
        for (int j = 0; j < 8; j++) acc[i][j] = 0.f;

    const int arow = tid >> 1;            // 0..127
    const int acol = (tid & 1) * 4;       // 0 or 4
    const int brow = tid >> 5;            // 0..7
    const int bcol = (tid & 31) * 4;      // 0..124

    const float* Aptr = Aeff + (size_t)(mBase + arow) * K + acol;
    const float* Bptr = W + (size_t)brow * N + nBase + bcol;

    for (int k0 = 0; k0 < K; k0 += 8) {
        float4 av = *(const float4*)Aptr;   Aptr += 8;
        float4 bv = *(const float4*)Bptr;   Bptr += (size_t)8 * N;

        __syncthreads();   // previous compute done before overwriting smem
        As[acol + 0][arow] = av.x;
        As[acol + 1][arow] = av.y;
        As[acol + 2][arow] = av.z;
        As[acol + 3][arow] = av.w;
        *(float4*)&Bs[brow][bcol] = bv;
        __syncthreads();

#pragma unroll
        for (int k = 0; k < 8; k++) {
            float ra[8], rb[8];
            *(float4*)&ra[0] = *(const float4*)&As[k][ty * 8];
            *(float4*)&ra[4] = *(const float4*)&As[k][ty * 8 + 4];
            *(float4*)&rb[0] = *(const float4*)&Bs[k][tx * 8];
            *(float4*)&rb[4] = *(const float4*)&Bs[k][tx * 8 + 4];
#pragma unroll
            for (int i = 0; i < 8; i++)
#pragma unroll
                for (int j = 0; j < 8; j++)
                    acc[i][j] = fmaf(ra[i], rb[j], acc[i][j]);
        }
    }

    if (MODE == 1) {
        // plain epilogue: Cout[m][n] = acc + bias[n]
#pragma unroll
        for (int i = 0; i < 8; i++) {
            size_t row = (size_t)(mBase + ty * 8 + i);
            float* cp = Cout + row * N + nBase + tx * 8;
#pragma unroll
            for (int j = 0; j < 8; j++)
                cp[j] = acc[i][j] + bias[nBase + tx * 8 + j];
        }
    } else {
        // scatter q/k/v into [B,H,S,HD]
#pragma unroll
        for (int i = 0; i < 8; i++) {
            int m = mBase + ty * 8 + i;
            int b = m >> 11;          // /SEQ
            int s = m & 2047;
#pragma unroll
            for (int j = 0; j < 8; j++) {
                int n = nBase + tx * 8 + j;
                float v = acc[i][j] + bias[n];
                int sec = n >> 10;    // 0=q 1=k 2=v
                int dd  = n & 1023;
                int h   = dd >> 6;
                int hd  = dd & 63;
                float* dst = (sec == 0) ? g_q : (sec == 1) ? g_k : g_v;
                dst[(((size_t)(b * NHEAD + h)) * SEQ + s) * HDIM + hd] = v;
            }
        }
    }
}

// ---------------------------------------------------------------------------
// Flash attention: one block per (q-tile of 64 rows, head, batch).
// 256 threads as 16x16; each thread owns a 4x4 fragment.
// smem: Qt[d][r], KPt (K transposed, reused as P transposed), Vs[k][c] = 48KB.
// ---------------------------------------------------------------------------
__global__ __launch_bounds__(256) void flash_kernel(const float* __restrict__ mask)
{
    __shared__ float Qt[64][64];    // Qt[d][r]
    __shared__ float KPt[64][64];   // Kt[d][c] then Pt[k][r]
    __shared__ float Vs[64][64];    // Vs[k][c]

    const int qb = blockIdx.x * 64;
    const int h  = blockIdx.y;
    const int b  = blockIdx.z;
    const int tid = threadIdx.x;
    const int tx = tid & 15;
    const int ty = tid >> 4;

    const size_t headBase = ((size_t)(b * NHEAD + h)) * SEQ * HDIM;
    const float* Qg = g_q + headBase;
    const float* Kg = g_k + headBase;
    const float* Vg = g_v + headBase;
    const float* maskb = mask + (size_t)b * SEQ;

    // load Q tile transposed
    for (int i = tid; i < 64 * 16; i += 256) {
        int r  = i >> 4;
        int d4 = (i & 15) << 2;
        float4 v = *(const float4*)(Qg + (size_t)(qb + r) * HDIM + d4);
        Qt[d4 + 0][r] = v.x;
        Qt[d4 + 1][r] = v.y;
        Qt[d4 + 2][r] = v.z;
        Qt[d4 + 3][r] = v.w;
    }

    float m_i[4], l_i[4], o[4][4];
#pragma unroll
    for (int i = 0; i < 4; i++) {
        m_i[i] = -INFINITY;
        l_i[i] = 0.f;
#pragma unroll
        for (int j = 0; j < 4; j++) o[i][j] = 0.f;
    }

    for (int kb = 0; kb < SEQ; kb += 64) {
        __syncthreads();   // previous iter's PV reads done (also covers Qt stores)
        for (int i = tid; i < 64 * 16; i += 256) {
            int r  = i >> 4;
            int d4 = (i & 15) << 2;
            float4 kv = *(const float4*)(Kg + (size_t)(kb + r) * HDIM + d4);
            KPt[d4 + 0][r] = kv.x;
            KPt[d4 + 1][r] = kv.y;
            KPt[d4 + 2][r] = kv.z;
            KPt[d4 + 3][r] = kv.w;
            float4 vv = *(const float4*)(Vg + (size_t)(kb + r) * HDIM + d4);
            *(float4*)&Vs[r][d4] = vv;
        }
        __syncthreads();

        // scores: S[4ty+i][4tx+j] = sum_d Qt[d][4ty+i] * Kt[d][4tx+j]
        float s[4][4];
#pragma unroll
        for (int i = 0; i < 4; i++)
#pragma unroll
            for (int j = 0; j < 4; j++) s[i][j] = 0.f;

#pragma unroll 8
        for (int d = 0; d < 64; d++) {
            float4 qv = *(const float4*)&Qt[d][ty << 2];
            float4 kv = *(const float4*)&KPt[d][tx << 2];
            float qa[4] = {qv.x, qv.y, qv.z, qv.w};
            float ka[4] = {kv.x, kv.y, kv.z, kv.w};
#pragma unroll
            for (int i = 0; i < 4; i++)
#pragma unroll
                for (int j = 0; j < 4; j++)
                    s[i][j] = fmaf(qa[i], ka[j], s[i][j]);
        }

        float mk[4];
#pragma unroll
        for (int j = 0; j < 4; j++) mk[j] = maskb[kb + (tx << 2) + j];

        // online softmax per row (16 lanes share each row)
#pragma unroll
        for (int i = 0; i < 4; i++) {
            float tmax = -INFINITY;
#pragma unroll
            for (int j = 0; j < 4; j++) {
                s[i][j] = fmaf(s[i][j], INV_SCALE, mk[j]);
                tmax = fmaxf(tmax, s[i][j]);
            }
#pragma unroll
            for (int off = 8; off >= 1; off >>= 1)
                tmax = fmaxf(tmax, __shfl_xor_sync(0xffffffffu, tmax, off, 16));
            float mnew  = fmaxf(m_i[i], tmax);
            float alpha = __expf(m_i[i] - mnew);
            m_i[i] = mnew;
            float ts = 0.f;
#pragma unroll
            for (int j = 0; j < 4; j++) {
                s[i][j] = __expf(s[i][j] - mnew);
                ts += s[i][j];
            }
#pragma unroll
            for (int off = 8; off >= 1; off >>= 1)
                ts += __shfl_xor_sync(0xffffffffu, ts, off, 16);
            l_i[i] = l_i[i] * alpha + ts;
#pragma unroll
            for (int j = 0; j < 4; j++) o[i][j] *= alpha;
        }

        __syncthreads();   // done reading KPt as K
        // write P transposed: Pt[col][row]
#pragma unroll
        for (int i = 0; i < 4; i++)
#pragma unroll
            for (int j = 0; j < 4; j++)
                KPt[(tx << 2) + j][(ty << 2) + i] = s[i][j];
        __syncthreads();

        // O += P @ V : o[i][j] += Pt[k][4ty+i] * Vs[k][4tx+j]
#pragma unroll 8
        for (int k = 0; k < 64; k++) {
            float4 pv = *(const float4*)&KPt[k][ty << 2];
            float4 vv = *(const float4*)&Vs[k][tx << 2];
            float pa[4] = {pv.x, pv.y, pv.z, pv.w};
            float va[4] = {vv.x, vv.y, vv.z, vv.w};
#pragma unroll
            for (int i = 0; i < 4; i++)
#pragma unroll
                for (int j = 0; j < 4; j++)
                    o[i][j] = fmaf(pa[i], va[j], o[i][j]);
        }
    }

    // epilogue: merge heads -> g_att[b][s][h*64 + c]
#pragma unroll
    for (int i = 0; i < 4; i++) {
        float inv = 1.f / l_i[i];
        size_t row = (size_t)b * SEQ + qb + (ty << 2) + i;
        float* dst = g_att + row * DMODEL + h * HDIM + (tx << 2);
#pragma unroll
        for (int j = 0; j < 4; j++) dst[j] = o[i][j] * inv;
    }
}

// ---------------------------------------------------------------------------
extern "C" void kernel_launch(void* const* d_in, const int* in_sizes, int n_in,
                              void* d_out, int out_size)
{
    (void)in_sizes; (void)n_in; (void)out_size;
    const float* x       = (const float*)d_in[0];
    const float* mask    = (const float*)d_in[1];
    const float* w_attn  = (const float*)d_in[2];
    const float* b_attn  = (const float*)d_in[3];
    const float* w_proj  = (const float*)d_in[4];
    const float* b_proj  = (const float*)d_in[5];
    float* out = (float*)d_out;

    // 1) QKV GEMM: [4096,1024] @ [1024,3072] -> scatter to g_q/g_k/g_v
    {
        dim3 grid(N_QKV / 128, M_ROWS / 128);
        sgemm_kernel<0><<<grid, 256>>>(x, w_attn, b_attn, nullptr,
                                       M_ROWS, N_QKV, DMODEL);
    }
    // 2) Flash attention per (q-tile, head, batch) -> g_att [B,S,D]
    {
        dim3 grid(SEQ / 64, NHEAD, BATCH);
        flash_kernel<<<grid, 256>>>(mask);
    }
    // 3) Proj GEMM: g_att [4096,1024] @ [1024,1024] + b_proj -> out
    {
        dim3 grid(DMODEL / 128, M_ROWS / 128);
        sgemm_kernel<1><<<grid, 256>>>(nullptr, w_proj, b_proj, out,
                                       M_ROWS, DMODEL, DMODEL);
    }
}

// round 4
// speedup vs baseline: 1.6654x; 1.6654x over previous
#include <cuda_runtime.h>
#include <cuda_bf16.h>
#include <math.h>
#include <stdint.h>

// Problem constants
#define BATCH 2
#define SEQ   2048
#define DMODEL 1024
#define NHEAD 16
#define HDIM  64
#define M_ROWS (BATCH * SEQ)          // 4096
#define N_QKV  (3 * DMODEL)           // 3072
#define INV_SCALE 0.125f

// ---------------------------------------------------------------------------
// Scratch buffers
// ---------------------------------------------------------------------------
__device__ __align__(256) float g_q[BATCH * NHEAD * SEQ * HDIM];
__device__ __align__(256) float g_k[BATCH * NHEAD * SEQ * HDIM];
__device__ __align__(256) float g_v[BATCH * NHEAD * SEQ * HDIM];
__device__ __align__(256) float g_att[M_ROWS * DMODEL];
__device__ __align__(256) __nv_bfloat16 g_xh[M_ROWS * DMODEL], g_xl[M_ROWS * DMODEL];
__device__ __align__(256) __nv_bfloat16 g_ah[M_ROWS * DMODEL], g_al[M_ROWS * DMODEL];
__device__ __align__(256) __nv_bfloat16 g_wqh[N_QKV * DMODEL], g_wql[N_QKV * DMODEL];
__device__ __align__(256) __nv_bfloat16 g_wph[DMODEL * DMODEL], g_wpl[DMODEL * DMODEL];

// ---------------------------------------------------------------------------
// PTX helpers (sm_80-era: valid on compute_100 base target)
// ---------------------------------------------------------------------------
__device__ __forceinline__ uint32_t smem_u32(const void* p) {
    uint32_t a;
    asm("{ .reg .u64 t; cvta.to.shared.u64 t, %1; cvt.u32.u64 %0, t; }" : "=r"(a) : "l"(p));
    return a;
}
__device__ __forceinline__ void cp16(uint32_t saddr, const void* gaddr) {
    asm volatile("cp.async.cg.shared.global [%0], [%1], 16;" :: "r"(saddr), "l"(gaddr) : "memory");
}
__device__ __forceinline__ void cp_commit() { asm volatile("cp.async.commit_group;" ::: "memory"); }
__device__ __forceinline__ void cp_wait0()  { asm volatile("cp.async.wait_group 0;" ::: "memory"); }

__device__ __forceinline__ void ldm_x4(uint32_t* r, uint32_t addr) {
    asm volatile("ldmatrix.sync.aligned.m8n8.x4.shared.b16 {%0,%1,%2,%3}, [%4];"
        : "=r"(r[0]), "=r"(r[1]), "=r"(r[2]), "=r"(r[3]) : "r"(addr));
}
__device__ __forceinline__ void mma_bf16(float* c, const uint32_t* a, uint32_t b0, uint32_t b1) {
    asm volatile("mma.sync.aligned.m16n8k16.row.col.f32.bf16.bf16.f32 "
        "{%0,%1,%2,%3}, {%4,%5,%6,%7}, {%8,%9}, {%0,%1,%2,%3};"
        : "+f"(c[0]), "+f"(c[1]), "+f"(c[2]), "+f"(c[3])
        : "r"(a[0]), "r"(a[1]), "r"(a[2]), "r"(a[3]), "r"(b0), "r"(b1));
}

// ---------------------------------------------------------------------------
// fp32 -> (hi, lo) bf16 split, vectorized x4
// ---------------------------------------------------------------------------
__global__ void split_kernel(const float* __restrict__ src,
                             __nv_bfloat16* __restrict__ hi,
                             __nv_bfloat16* __restrict__ lo, int n4)
{
    int i = blockIdx.x * blockDim.x + threadIdx.x;
    if (i >= n4) return;
    float4 v = ((const float4*)src)[i];
    __nv_bfloat16 h0 = __float2bfloat16_rn(v.x), h1 = __float2bfloat16_rn(v.y);
    __nv_bfloat16 h2 = __float2bfloat16_rn(v.z), h3 = __float2bfloat16_rn(v.w);
    __nv_bfloat16 l0 = __float2bfloat16_rn(v.x - __bfloat162float(h0));
    __nv_bfloat16 l1 = __float2bfloat16_rn(v.y - __bfloat162float(h1));
    __nv_bfloat16 l2 = __float2bfloat16_rn(v.z - __bfloat162float(h2));
    __nv_bfloat16 l3 = __float2bfloat16_rn(v.w - __bfloat162float(h3));
    ((__nv_bfloat162*)hi)[i * 2 + 0] = __nv_bfloat162(h0, h1);
    ((__nv_bfloat162*)hi)[i * 2 + 1] = __nv_bfloat162(h2, h3);
    ((__nv_bfloat162*)lo)[i * 2 + 0] = __nv_bfloat162(l0, l1);
    ((__nv_bfloat162*)lo)[i * 2 + 1] = __nv_bfloat162(l2, l3);
}

// ---------------------------------------------------------------------------
// W[K][N] fp32 -> Th/Tl[N][K] bf16 (transpose + split), 32x32 tiles
// ---------------------------------------------------------------------------
__global__ void transpose_split_kernel(const float* __restrict__ W,
                                       __nv_bfloat16* __restrict__ Th,
                                       __nv_bfloat16* __restrict__ Tl,
                                       int K, int N)
{
    __shared__ float t[32][33];
    int nb = blockIdx.x * 32, kb = blockIdx.y * 32;
    int tx = threadIdx.x, ty = threadIdx.y;   // 32 x 8
#pragma unroll
    for (int i = 0; i < 32; i += 8)
        t[ty + i][tx] = W[(size_t)(kb + ty + i) * N + nb + tx];
    __syncthreads();
#pragma unroll
    for (int i = 0; i < 32; i += 8) {
        float v = t[tx][ty + i];
        __nv_bfloat16 h = __float2bfloat16_rn(v);
        __nv_bfloat16 l = __float2bfloat16_rn(v - __bfloat162float(h));
        size_t o = (size_t)(nb + ty + i) * K + kb + tx;
        Th[o] = h;  Tl[o] = l;
    }
}

// ---------------------------------------------------------------------------
// bf16 mma.sync GEMM, 3-pass split: C = Ah@Bh^T + Al@Bh^T + Ah@Bl^T (+bias)
// A[M,K] row-major, B[N,K] row-major (K-major). Block 128x128, Kc=32,
// double-buffered cp.async, 8 warps as 2(M)x4(N), warp tile 64x32.
// MODE 0: scatter q/k/v.  MODE 1: write Cout.
// ---------------------------------------------------------------------------
#define AS_STR 40          // bf16 elems per smem row (80 B)

template <int MODE>
__global__ __launch_bounds__(256, 2) void gemm_kernel(const float* __restrict__ bias,
                                                      float* __restrict__ Cout, int Ndim)
{
    __shared__ __align__(16) __nv_bfloat16 As[2][128 * AS_STR];
    __shared__ __align__(16) __nv_bfloat16 Bs[2][128 * AS_STR];

    const int tid = threadIdx.x;
    const int wid = tid >> 5, lane = tid & 31;
    const int wm = wid >> 2, wn = wid & 3;
    const int mBase = blockIdx.y * 128;
    const int nBase = blockIdx.x * 128;

    const __nv_bfloat16* Ah = (MODE == 0) ? g_xh : g_ah;
    const __nv_bfloat16* Al = (MODE == 0) ? g_xl : g_al;
    const __nv_bfloat16* Bh = (MODE == 0) ? g_wqh : g_wph;
    const __nv_bfloat16* Bl = (MODE == 0) ? g_wql : g_wpl;
    const __nv_bfloat16* Aps[3] = {Ah, Al, Ah};
    const __nv_bfloat16* Bps[3] = {Bh, Bh, Bl};

    // loader indices: 512 16B chunks per tile; thread does 2 for A, 2 for B
    const int r0 = tid >> 2, kb0 = (tid & 3);          // chunks tid, tid+256
    const int r1 = (tid + 256) >> 2, kb1 = ((tid + 256) & 3);

    const uint32_t sA = smem_u32(As), sB = smem_u32(Bs);

    auto load_stage = [&](int cc, int st) {
        const int pass = cc >> 5;
        const int k0 = (cc & 31) * 32;
        const __nv_bfloat16* Ag = Aps[pass] + (size_t)mBase * DMODEL + k0;
        const __nv_bfloat16* Bg = Bps[pass] + (size_t)nBase * DMODEL + k0;
        uint32_t sa = sA + st * (128 * AS_STR * 2);
        uint32_t sbb = sB + st * (128 * AS_STR * 2);
        cp16(sa + (r0 * AS_STR + kb0 * 8) * 2, Ag + (size_t)r0 * DMODEL + kb0 * 8);
        cp16(sa + (r1 * AS_STR + kb1 * 8) * 2, Ag + (size_t)r1 * DMODEL + kb1 * 8);
        cp16(sbb + (r0 * AS_STR + kb0 * 8) * 2, Bg + (size_t)r0 * DMODEL + kb0 * 8);
        cp16(sbb + (r1 * AS_STR + kb1 * 8) * 2, Bg + (size_t)r1 * DMODEL + kb1 * 8);
        cp_commit();
    };

    float acc[4][4][4];
#pragma unroll
    for (int mi = 0; mi < 4; mi++)
#pragma unroll
        for (int ni = 0; ni < 4; ni++)
#pragma unroll
            for (int e = 0; e < 4; e++) acc[mi][ni][e] = 0.f;

    // ldmatrix source addresses (per-thread constants modulo stage/kstep)
    // A: row = wm*64 + mi*16 + (lane&15), kcol = ks*16 + (lane>>4)*8
    const int a_row = wm * 64 + (lane & 15);
    const int a_koff = (lane >> 4) * 8;
    // B: n = wn*32 + ((lane>>4)&1)*8 + (lane&7), k = ks*16 + ((lane>>3)&1)*8
    const int b_row = wn * 32 + ((lane >> 4) & 1) * 8 + (lane & 7);
    const int b_koff = ((lane >> 3) & 1) * 8;

    load_stage(0, 0);

    for (int cc = 0; cc < 96; ++cc) {
        const int st = cc & 1;
        cp_wait0();
        __syncthreads();
        if (cc + 1 < 96) load_stage(cc + 1, 1 - st);

        const uint32_t sa = sA + st * (128 * AS_STR * 2);
        const uint32_t sbb = sB + st * (128 * AS_STR * 2);
#pragma unroll
        for (int ks = 0; ks < 2; ++ks) {
            uint32_t a[4][4];
#pragma unroll
            for (int mi = 0; mi < 4; mi++)
                ldm_x4(a[mi], sa + ((a_row + mi * 16) * AS_STR + ks * 16 + a_koff) * 2);
            uint32_t b[2][4];
#pragma unroll
            for (int bt = 0; bt < 2; bt++)
                ldm_x4(b[bt], sbb + ((b_row + bt * 16) * AS_STR + ks * 16 + b_koff) * 2);
#pragma unroll
            for (int mi = 0; mi < 4; mi++)
#pragma unroll
                for (int ni = 0; ni < 4; ni++)
                    mma_bf16(acc[mi][ni], a[mi], b[ni >> 1][(ni & 1) * 2],
                             b[ni >> 1][(ni & 1) * 2 + 1]);
        }
        __syncthreads();
    }

    // Epilogue
    const int gid = lane >> 2, tig = lane & 3;
#pragma unroll
    for (int mi = 0; mi < 4; mi++) {
#pragma unroll
        for (int half = 0; half < 2; half++) {
            const int m = mBase + wm * 64 + mi * 16 + gid + half * 8;
#pragma unroll
            for (int ni = 0; ni < 4; ni++) {
                const int nl = wn * 32 + ni * 8 + tig * 2;
                const int n = nBase + nl;
                float2 val;
                val.x = acc[mi][ni][half * 2 + 0] + bias[n];
                val.y = acc[mi][ni][half * 2 + 1] + bias[n + 1];
                if (MODE == 1) {
                    *(float2*)(Cout + (size_t)m * Ndim + n) = val;
                } else {
                    const int b = m >> 11, srow = m & 2047;
                    const int sec = n >> 10, dd = n & 1023;
                    const int h = dd >> 6, hd = dd & 63;
                    float* base = (sec == 0) ? g_q : (sec == 1) ? g_k : g_v;
                    *(float2*)(base + (((size_t)(b * NHEAD + h)) * SEQ + srow) * HDIM + hd) = val;
                }
            }
        }
    }
}

// ---------------------------------------------------------------------------
// Flash attention (fp32), 64-row Q tile, XOR-swizzled Qt/KPt, 2 CTAs/SM.
// ---------------------------------------------------------------------------
#define FSW(row, col) ((col) ^ ((((row) >> 2) & 15) << 2))

__global__ __launch_bounds__(256, 2) void flash_kernel(const float* __restrict__ mask)
{
    __shared__ float Qt[64][64];    // Qt[d][r], swizzled
    __shared__ float KPt[64][64];   // Kt[d][c] then Pt[k][r], swizzled
    __shared__ float Vs[64][64];    // Vs[k][c]

    const int qb = blockIdx.x * 64;
    const int h  = blockIdx.y;
    const int b  = blockIdx.z;
    const int tid = threadIdx.x;
    const int tx = tid & 15;
    const int ty = tid >> 4;

    const size_t headBase = ((size_t)(b * NHEAD + h)) * SEQ * HDIM;
    const float* Qg = g_q + headBase;
    const float* Kg = g_k + headBase;
    const float* Vg = g_v + headBase;
    const float* maskb = mask + (size_t)b * SEQ;

    for (int i = tid; i < 64 * 16; i += 256) {
        int r  = i >> 4;
        int d4 = (i & 15) << 2;
        float4 v = *(const float4*)(Qg + (size_t)(qb + r) * HDIM + d4);
        Qt[d4 + 0][FSW(d4 + 0, r)] = v.x;
        Qt[d4 + 1][FSW(d4 + 1, r)] = v.y;
        Qt[d4 + 2][FSW(d4 + 2, r)] = v.z;
        Qt[d4 + 3][FSW(d4 + 3, r)] = v.w;
    }

    float m_i[4], l_i[4], o[4][4];
#pragma unroll
    for (int i = 0; i < 4; i++) {
        m_i[i] = -INFINITY;
        l_i[i] = 0.f;
#pragma unroll
        for (int j = 0; j < 4; j++) o[i][j] = 0.f;
    }

    for (int kb = 0; kb < SEQ; kb += 64) {
        __syncthreads();
        for (int i = tid; i < 64 * 16; i += 256) {
            int r  = i >> 4;
            int d4 = (i & 15) << 2;
            float4 kv = *(const float4*)(Kg + (size_t)(kb + r) * HDIM + d4);
            KPt[d4 + 0][FSW(d4 + 0, r)] = kv.x;
            KPt[d4 + 1][FSW(d4 + 1, r)] = kv.y;
            KPt[d4 + 2][FSW(d4 + 2, r)] = kv.z;
            KPt[d4 + 3][FSW(d4 + 3, r)] = kv.w;
            float4 vv = *(const float4*)(Vg + (size_t)(kb + r) * HDIM + d4);
            *(float4*)&Vs[r][d4] = vv;
        }
        __syncthreads();

        float s[4][4];
#pragma unroll
        for (int i = 0; i < 4; i++)
#pragma unroll
            for (int j = 0; j < 4; j++) s[i][j] = 0.f;

#pragma unroll 8
        for (int d = 0; d < 64; d++) {
            float4 qv = *(const float4*)&Qt[d][FSW(d, ty << 2)];
            float4 kv = *(const float4*)&KPt[d][FSW(d, tx << 2)];
            float qa[4] = {qv.x, qv.y, qv.z, qv.w};
            float ka[4] = {kv.x, kv.y, kv.z, kv.w};
#pragma unroll
            for (int i = 0; i < 4; i++)
#pragma unroll
                for (int j = 0; j < 4; j++)
                    s[i][j] = fmaf(qa[i], ka[j], s[i][j]);
        }

        float mk[4];
#pragma unroll
        for (int j = 0; j < 4; j++) mk[j] = maskb[kb + (tx << 2) + j];

#pragma unroll
        for (int i = 0; i < 4; i++) {
            float tmax = -INFINITY;
#pragma unroll
            for (int j = 0; j < 4; j++) {
                s[i][j] = fmaf(s[i][j], INV_SCALE, mk[j]);
                tmax = fmaxf(tmax, s[i][j]);
            }
#pragma unroll
            for (int off = 8; off >= 1; off >>= 1)
                tmax = fmaxf(tmax, __shfl_xor_sync(0xffffffffu, tmax, off, 16));
            float mnew  = fmaxf(m_i[i], tmax);
            float alpha = __expf(m_i[i] - mnew);
            m_i[i] = mnew;
            float ts = 0.f;
#pragma unroll
            for (int j = 0; j < 4; j++) {
                s[i][j] = __expf(s[i][j] - mnew);
                ts += s[i][j];
            }
#pragma unroll
            for (int off = 8; off >= 1; off >>= 1)
                ts += __shfl_xor_sync(0xffffffffu, ts, off, 16);
            l_i[i] = l_i[i] * alpha + ts;
#pragma unroll
            for (int j = 0; j < 4; j++) o[i][j] *= alpha;
        }

        __syncthreads();
#pragma unroll
        for (int i = 0; i < 4; i++)
#pragma unroll
            for (int j = 0; j < 4; j++)
                KPt[(tx << 2) + j][FSW((tx << 2) + j, (ty << 2) + i)] = s[i][j];
        __syncthreads();

#pragma unroll 8
        for (int k = 0; k < 64; k++) {
            float4 pv = *(const float4*)&KPt[k][FSW(k, ty << 2)];
            float4 vv = *(const float4*)&Vs[k][tx << 2];
            float pa[4] = {pv.x, pv.y, pv.z, pv.w};
            float va[4] = {vv.x, vv.y, vv.z, vv.w};
#pragma unroll
            for (int i = 0; i < 4; i++)
#pragma unroll
                for (int j = 0; j < 4; j++)
                    o[i][j] = fmaf(pa[i], va[j], o[i][j]);
        }
    }

#pragma unroll
    for (int i = 0; i < 4; i++) {
        float inv = 1.f / l_i[i];
        size_t row = (size_t)b * SEQ + qb + (ty << 2) + i;
        float* dst = g_att + row * DMODEL + h * HDIM + (tx << 2);
#pragma unroll
        for (int j = 0; j < 4; j++) dst[j] = o[i][j] * inv;
    }
}

// ---------------------------------------------------------------------------
extern "C" void kernel_launch(void* const* d_in, const int* in_sizes, int n_in,
                              void* d_out, int out_size)
{
    (void)in_sizes; (void)n_in; (void)out_size;
    const float* x       = (const float*)d_in[0];
    const float* mask    = (const float*)d_in[1];
    const float* w_attn  = (const float*)d_in[2];
    const float* b_attn  = (const float*)d_in[3];
    const float* w_proj  = (const float*)d_in[4];
    const float* b_proj  = (const float*)d_in[5];
    float* out = (float*)d_out;

    __nv_bfloat16 *xh, *xl, *ah, *al, *wqh, *wql, *wph, *wpl;
    cudaGetSymbolAddress((void**)&xh,  g_xh);  cudaGetSymbolAddress((void**)&xl,  g_xl);
    cudaGetSymbolAddress((void**)&ah,  g_ah);  cudaGetSymbolAddress((void**)&al,  g_al);
    cudaGetSymbolAddress((void**)&wqh, g_wqh); cudaGetSymbolAddress((void**)&wql, g_wql);
    cudaGetSymbolAddress((void**)&wph, g_wph); cudaGetSymbolAddress((void**)&wpl, g_wpl);
    float* att; cudaGetSymbolAddress((void**)&att, g_att);

    // 1) splits + weight transposes
    {
        int n4 = (M_ROWS * DMODEL) / 4;
        split_kernel<<<(n4 + 255) / 256, 256>>>(x, xh, xl, n4);
        transpose_split_kernel<<<dim3(N_QKV / 32, DMODEL / 32), dim3(32, 8)>>>(
            w_attn, wqh, wql, DMODEL, N_QKV);
        transpose_split_kernel<<<dim3(DMODEL / 32, DMODEL / 32), dim3(32, 8)>>>(
            w_proj, wph, wpl, DMODEL, DMODEL);
    }
    // 2) QKV GEMM (mma.sync bf16 3-pass) -> g_q/g_k/g_v
    gemm_kernel<0><<<dim3(N_QKV / 128, M_ROWS / 128), 256>>>(b_attn, nullptr, N_QKV);
    // 3) Flash attention -> g_att
    flash_kernel<<<dim3(SEQ / 64, NHEAD, BATCH), 256>>>(mask);
    // 4) split g_att for proj GEMM
    {
        int n4 = (M_ROWS * DMODEL) / 4;
        split_kernel<<<(n4 + 255) / 256, 256>>>(att, ah, al, n4);
    }
    // 5) proj GEMM -> out
    gemm_kernel<1><<<dim3(DMODEL / 128, M_ROWS / 128), 256>>>(b_proj, out, DMODEL);
}

// round 6
// speedup vs baseline: 2.9458x; 1.7689x over previous
#include <cuda_runtime.h>
#include <cuda_bf16.h>
#include <math.h>
#include <stdint.h>

// Problem constants
#define BATCH 2
#define SEQ   2048
#define DMODEL 1024
#define NHEAD 16
#define HDIM  64
#define M_ROWS (BATCH * SEQ)          // 4096
#define N_QKV  (3 * DMODEL)           // 3072
#define INV_SCALE 0.125f

// ---------------------------------------------------------------------------
// Scratch buffers
// ---------------------------------------------------------------------------
__device__ __align__(256) float g_v[BATCH * NHEAD * SEQ * HDIM];
__device__ __align__(256) float g_att[M_ROWS * DMODEL];
__device__ __align__(256) __nv_bfloat16 g_xh[M_ROWS * DMODEL], g_xl[M_ROWS * DMODEL];
__device__ __align__(256) __nv_bfloat16 g_ah[M_ROWS * DMODEL], g_al[M_ROWS * DMODEL];
__device__ __align__(256) __nv_bfloat16 g_wqh[N_QKV * DMODEL], g_wql[N_QKV * DMODEL];
__device__ __align__(256) __nv_bfloat16 g_wph[DMODEL * DMODEL], g_wpl[DMODEL * DMODEL];
__device__ __align__(256) __nv_bfloat16 g_qh[BATCH * NHEAD * SEQ * HDIM], g_ql[BATCH * NHEAD * SEQ * HDIM];
__device__ __align__(256) __nv_bfloat16 g_kh[BATCH * NHEAD * SEQ * HDIM], g_kl[BATCH * NHEAD * SEQ * HDIM];
__device__ __align__(256) __nv_bfloat16 g_vth[BATCH * NHEAD * SEQ * HDIM], g_vtl[BATCH * NHEAD * SEQ * HDIM];

// ---------------------------------------------------------------------------
// PTX helpers (sm_80-era: valid on compute_100 base target)
// ---------------------------------------------------------------------------
__device__ __forceinline__ uint32_t smem_u32(const void* p) {
    uint32_t a;
    asm("{ .reg .u64 t; cvta.to.shared.u64 t, %1; cvt.u32.u64 %0, t; }" : "=r"(a) : "l"(p));
    return a;
}
__device__ __forceinline__ void cp16(uint32_t saddr, const void* gaddr) {
    asm volatile("cp.async.cg.shared.global [%0], [%1], 16;" :: "r"(saddr), "l"(gaddr) : "memory");
}
__device__ __forceinline__ void cp_commit() { asm volatile("cp.async.commit_group;" ::: "memory"); }
__device__ __forceinline__ void cp_wait0()  { asm volatile("cp.async.wait_group 0;" ::: "memory"); }

__device__ __forceinline__ void ldm_x4(uint32_t* r, uint32_t addr) {
    asm volatile("ldmatrix.sync.aligned.m8n8.x4.shared.b16 {%0,%1,%2,%3}, [%4];"
        : "=r"(r[0]), "=r"(r[1]), "=r"(r[2]), "=r"(r[3]) : "r"(addr));
}
__device__ __forceinline__ void mma_bf16(float* c, const uint32_t* a, uint32_t b0, uint32_t b1) {
    asm volatile("mma.sync.aligned.m16n8k16.row.col.f32.bf16.bf16.f32 "
        "{%0,%1,%2,%3}, {%4,%5,%6,%7}, {%8,%9}, {%0,%1,%2,%3};"
        : "+f"(c[0]), "+f"(c[1]), "+f"(c[2]), "+f"(c[3])
        : "r"(a[0]), "r"(a[1]), "r"(a[2]), "r"(a[3]), "r"(b0), "r"(b1));
}

// ---------------------------------------------------------------------------
// fp32 -> (hi, lo) bf16 split, vectorized x4
// ---------------------------------------------------------------------------
__global__ void split_kernel(const float* __restrict__ src,
                             __nv_bfloat16* __restrict__ hi,
                             __nv_bfloat16* __restrict__ lo, int n4)
{
    int i = blockIdx.x * blockDim.x + threadIdx.x;
    if (i >= n4) return;
    float4 v = ((const float4*)src)[i];
    __nv_bfloat16 h0 = __float2bfloat16_rn(v.x), h1 = __float2bfloat16_rn(v.y);
    __nv_bfloat16 h2 = __float2bfloat16_rn(v.z), h3 = __float2bfloat16_rn(v.w);
    __nv_bfloat16 l0 = __float2bfloat16_rn(v.x - __bfloat162float(h0));
    __nv_bfloat16 l1 = __float2bfloat16_rn(v.y - __bfloat162float(h1));
    __nv_bfloat16 l2 = __float2bfloat16_rn(v.z - __bfloat162float(h2));
    __nv_bfloat16 l3 = __float2bfloat16_rn(v.w - __bfloat162float(h3));
    ((__nv_bfloat162*)hi)[i * 2 + 0] = __nv_bfloat162(h0, h1);
    ((__nv_bfloat162*)hi)[i * 2 + 1] = __nv_bfloat162(h2, h3);
    ((__nv_bfloat162*)lo)[i * 2 + 0] = __nv_bfloat162(l0, l1);
    ((__nv_bfloat162*)lo)[i * 2 + 1] = __nv_bfloat162(l2, l3);
}

// ---------------------------------------------------------------------------
// W[K][N] fp32 -> Th/Tl[N][K] bf16 (transpose + split), 32x32 tiles
// ---------------------------------------------------------------------------
__global__ void transpose_split_kernel(const float* __restrict__ W,
                                       __nv_bfloat16* __restrict__ Th,
                                       __nv_bfloat16* __restrict__ Tl,
                                       int K, int N)
{
    __shared__ float t[32][33];
    int nb = blockIdx.x * 32, kb = blockIdx.y * 32;
    int tx = threadIdx.x, ty = threadIdx.y;   // 32 x 8
#pragma unroll
    for (int i = 0; i < 32; i += 8)
        t[ty + i][tx] = W[(size_t)(kb + ty + i) * N + nb + tx];
    __syncthreads();
#pragma unroll
    for (int i = 0; i < 32; i += 8) {
        float v = t[tx][ty + i];
        __nv_bfloat16 h = __float2bfloat16_rn(v);
        __nv_bfloat16 l = __float2bfloat16_rn(v - __bfloat162float(h));
        size_t o = (size_t)(nb + ty + i) * K + kb + tx;
        Th[o] = h;  Tl[o] = l;
    }
}

// ---------------------------------------------------------------------------
// V [b,h,s,hd] fp32 -> V^T [b,h,hd,s] bf16 hi/lo
// ---------------------------------------------------------------------------
__global__ void transpose_split_v(int dummy)
{
    __shared__ float tt[32][33];
    const int sb = blockIdx.x * 32, hb = blockIdx.y * 32;
    const size_t base = (size_t)blockIdx.z * SEQ * HDIM;
    const int tx = threadIdx.x, ty = threadIdx.y;   // 32 x 8
#pragma unroll
    for (int i = 0; i < 32; i += 8)
        tt[ty + i][tx] = g_v[base + (size_t)(sb + ty + i) * HDIM + hb + tx];
    __syncthreads();
#pragma unroll
    for (int i = 0; i < 32; i += 8) {
        float v = tt[tx][ty + i];                       // s=sb+tx, hd=hb+ty+i
        __nv_bfloat16 h = __float2bfloat16_rn(v);
        __nv_bfloat16 l = __float2bfloat16_rn(v - __bfloat162float(h));
        size_t o = base + (size_t)(hb + ty + i) * SEQ + sb + tx;
        g_vth[o] = h;  g_vtl[o] = l;
    }
    (void)dummy;
}

// ---------------------------------------------------------------------------
// bf16 mma.sync GEMM, 3-pass split (unchanged from R4; passing).
// MODE 0: epilogue -> q/k bf16 hi/lo + v fp32.  MODE 1: -> Cout fp32.
// ---------------------------------------------------------------------------
#define AS_STR 40

template <int MODE>
__global__ __launch_bounds__(256, 2) void gemm_kernel(const float* __restrict__ bias,
                                                      float* __restrict__ Cout, int Ndim)
{
    __shared__ __align__(16) __nv_bfloat16 As[2][128 * AS_STR];
    __shared__ __align__(16) __nv_bfloat16 Bs[2][128 * AS_STR];

    const int tid = threadIdx.x;
    const int wid = tid >> 5, lane = tid & 31;
    const int wm = wid >> 2, wn = wid & 3;
    const int mBase = blockIdx.y * 128;
    const int nBase = blockIdx.x * 128;

    const __nv_bfloat16* Ah = (MODE == 0) ? g_xh : g_ah;
    const __nv_bfloat16* Al = (MODE == 0) ? g_xl : g_al;
    const __nv_bfloat16* Bh = (MODE == 0) ? g_wqh : g_wph;
    const __nv_bfloat16* Bl = (MODE == 0) ? g_wql : g_wpl;
    const __nv_bfloat16* Aps[3] = {Ah, Al, Ah};
    const __nv_bfloat16* Bps[3] = {Bh, Bh, Bl};

    const int r0 = tid >> 2, kb0 = (tid & 3);
    const int r1 = (tid + 256) >> 2, kb1 = ((tid + 256) & 3);
    const uint32_t sA = smem_u32(As), sB = smem_u32(Bs);

    auto load_stage = [&](int cc, int st) {
        const int pass = cc >> 5;
        const int k0 = (cc & 31) * 32;
        const __nv_bfloat16* Ag = Aps[pass] + (size_t)mBase * DMODEL + k0;
        const __nv_bfloat16* Bg = Bps[pass] + (size_t)nBase * DMODEL + k0;
        uint32_t sa = sA + st * (128 * AS_STR * 2);
        uint32_t sbb = sB + st * (128 * AS_STR * 2);
        cp16(sa + (r0 * AS_STR + kb0 * 8) * 2, Ag + (size_t)r0 * DMODEL + kb0 * 8);
        cp16(sa + (r1 * AS_STR + kb1 * 8) * 2, Ag + (size_t)r1 * DMODEL + kb1 * 8);
        cp16(sbb + (r0 * AS_STR + kb0 * 8) * 2, Bg + (size_t)r0 * DMODEL + kb0 * 8);
        cp16(sbb + (r1 * AS_STR + kb1 * 8) * 2, Bg + (size_t)r1 * DMODEL + kb1 * 8);
        cp_commit();
    };

    float acc[4][4][4];
#pragma unroll
    for (int mi = 0; mi < 4; mi++)
#pragma unroll
        for (int ni = 0; ni < 4; ni++)
#pragma unroll
            for (int e = 0; e < 4; e++) acc[mi][ni][e] = 0.f;

    const int a_row = wm * 64 + (lane & 15);
    const int a_koff = (lane >> 4) * 8;
    const int b_row = wn * 32 + ((lane >> 4) & 1) * 8 + (lane & 7);
    const int b_koff = ((lane >> 3) & 1) * 8;

    load_stage(0, 0);

    for (int cc = 0; cc < 96; ++cc) {
        const int st = cc & 1;
        cp_wait0();
        __syncthreads();
        if (cc + 1 < 96) load_stage(cc + 1, 1 - st);

        const uint32_t sa = sA + st * (128 * AS_STR * 2);
        const uint32_t sbb = sB + st * (128 * AS_STR * 2);
#pragma unroll
        for (int ks = 0; ks < 2; ++ks) {
            uint32_t a[4][4];
#pragma unroll
            for (int mi = 0; mi < 4; mi++)
                ldm_x4(a[mi], sa + ((a_row + mi * 16) * AS_STR + ks * 16 + a_koff) * 2);
            uint32_t b[2][4];
#pragma unroll
            for (int bt = 0; bt < 2; bt++)
                ldm_x4(b[bt], sbb + ((b_row + bt * 16) * AS_STR + ks * 16 + b_koff) * 2);
#pragma unroll
            for (int mi = 0; mi < 4; mi++)
#pragma unroll
                for (int ni = 0; ni < 4; ni++)
                    mma_bf16(acc[mi][ni], a[mi], b[ni >> 1][(ni & 1) * 2],
                             b[ni >> 1][(ni & 1) * 2 + 1]);
        }
        __syncthreads();
    }

    const int gid = lane >> 2, tig = lane & 3;
#pragma unroll
    for (int mi = 0; mi < 4; mi++) {
#pragma unroll
        for (int half = 0; half < 2; half++) {
            const int m = mBase + wm * 64 + mi * 16 + gid + half * 8;
#pragma unroll
            for (int ni = 0; ni < 4; ni++) {
                const int n = nBase + wn * 32 + ni * 8 + tig * 2;
                float2 val;
                val.x = acc[mi][ni][half * 2 + 0] + bias[n];
                val.y = acc[mi][ni][half * 2 + 1] + bias[n + 1];
                if (MODE == 1) {
                    *(float2*)(Cout + (size_t)m * Ndim + n) = val;
                } else {
                    const int b = m >> 11, srow = m & 2047;
                    const int sec = n >> 10, dd = n & 1023;
                    const int hh = dd >> 6, hd = dd & 63;
                    const size_t idx = (((size_t)(b * NHEAD + hh)) * SEQ + srow) * HDIM + hd;
                    if (sec == 2) {
                        *(float2*)(g_v + idx) = val;
                    } else {
                        __nv_bfloat16 hx = __float2bfloat16_rn(val.x);
                        __nv_bfloat16 hy = __float2bfloat16_rn(val.y);
                        __nv_bfloat16 lx = __float2bfloat16_rn(val.x - __bfloat162float(hx));
                        __nv_bfloat16 ly = __float2bfloat16_rn(val.y - __bfloat162float(hy));
                        __nv_bfloat16* dh = (sec == 0) ? g_qh : g_kh;
                        __nv_bfloat16* dl = (sec == 0) ? g_ql : g_kl;
                        *(__nv_bfloat162*)(dh + idx) = __nv_bfloat162(hx, hy);
                        *(__nv_bfloat162*)(dl + idx) = __nv_bfloat162(lx, ly);
                    }
                }
            }
        }
    }
}

// ---------------------------------------------------------------------------
// Tensor-core flash attention, FIXED warp layout: 8 warps x (16 rows x 64 cols)
// so each softmax row lives entirely inside one warp (quad shuffles suffice).
// bf16 hi/lo 3-pass on QK^T and PV; fp32 accum; online softmax in regs.
// Dynamic smem 144KB: Qh/Ql | K(2 stages, h/l) | V^T(2 stages, h/l) | Ph/Pl.
// Rows stride 72 bf16 (144B) -> ldmatrix + P-store conflict-free.
// ---------------------------------------------------------------------------
#define FL_SMEM 147456

__global__ __launch_bounds__(256, 1) void flash_kernel(const float* __restrict__ mask)
{
    extern __shared__ __align__(16) char fsm[];
    const uint32_t S0 = smem_u32(fsm);
    const uint32_t sQh = S0, sQl = S0 + 18432;
    const uint32_t sK  = S0 + 36864;   // [stage][h/l][64][72]
    const uint32_t sV  = S0 + 73728;   // [stage][h/l][64 hd][72 key]
    char* Phb = fsm + 110592;          // [128][72]
    char* Plb = fsm + 129024;
    const uint32_t sPh = S0 + 110592, sPl = S0 + 129024;

    const int qb = blockIdx.x * 128;
    const int h  = blockIdx.y, b = blockIdx.z;
    const int bh = b * NHEAD + h;
    const int tid = threadIdx.x, wid = tid >> 5, lane = tid & 31;

    const __nv_bfloat16* Qhg = g_qh + (size_t)bh * SEQ * HDIM;
    const __nv_bfloat16* Qlg = g_ql + (size_t)bh * SEQ * HDIM;
    const __nv_bfloat16* Khg = g_kh + (size_t)bh * SEQ * HDIM;
    const __nv_bfloat16* Klg = g_kl + (size_t)bh * SEQ * HDIM;
    const __nv_bfloat16* Vhg = g_vth + (size_t)bh * SEQ * HDIM;  // [hd][s]
    const __nv_bfloat16* Vlg = g_vtl + (size_t)bh * SEQ * HDIM;
    const float* maskb = mask + (size_t)b * SEQ;

    // Q tile (128 x 64, hi+lo)
    for (int i = tid; i < 1024; i += 256) {
        int r = i >> 3, cb = i & 7;
        uint32_t so = (r * 72 + cb * 8) * 2;
        cp16(sQh + so, Qhg + (size_t)(qb + r) * HDIM + cb * 8);
        cp16(sQl + so, Qlg + (size_t)(qb + r) * HDIM + cb * 8);
    }
    // K/V tile 0 -> stage 0
    for (int i = tid; i < 512; i += 256) {
        int r = i >> 3, cb = i & 7;
        uint32_t so = (r * 72 + cb * 8) * 2;
        cp16(sK + so,        Khg + (size_t)r * HDIM + cb * 8);
        cp16(sK + 9216 + so, Klg + (size_t)r * HDIM + cb * 8);
        cp16(sV + so,        Vhg + (size_t)r * SEQ + cb * 8);
        cp16(sV + 9216 + so, Vlg + (size_t)r * SEQ + cb * 8);
    }
    cp_commit();

    float m_s[2], l_s[2], oacc[8][4];
#pragma unroll
    for (int i = 0; i < 2; i++) { m_s[i] = -INFINITY; l_s[i] = 0.f; }
#pragma unroll
    for (int ni = 0; ni < 8; ni++)
#pragma unroll
        for (int e = 0; e < 4; e++) oacc[ni][e] = 0.f;

    const int a_base = lane & 15, a_koff = (lane >> 4) * 8;
    const int b_base = ((lane >> 4) & 1) * 8 + (lane & 7), b_koff = ((lane >> 3) & 1) * 8;
    const int g = lane >> 2, tig = lane & 3;
    const int arow_off = wid * 16 + a_base;   // this warp's A rows (Q and P)

    for (int t = 0; t < 32; ++t) {
        const int st = t & 1;
        cp_wait0();
        __syncthreads();
        if (t + 1 < 32) {
            const int kb2 = (t + 1) * 64;
            const uint32_t kof = (1 - st) * 18432;
            for (int i = tid; i < 512; i += 256) {
                int r = i >> 3, cb = i & 7;
                uint32_t so = (r * 72 + cb * 8) * 2;
                cp16(sK + kof + so,        Khg + (size_t)(kb2 + r) * HDIM + cb * 8);
                cp16(sK + kof + 9216 + so, Klg + (size_t)(kb2 + r) * HDIM + cb * 8);
                cp16(sV + kof + so,        Vhg + (size_t)r * SEQ + kb2 + cb * 8);
                cp16(sV + kof + 9216 + so, Vlg + (size_t)r * SEQ + kb2 + cb * 8);
            }
            cp_commit();
        }

        // ---- S = Q @ K^T (3 split passes); warp owns rows wid*16..+15, all 64 cols
        float sacc[8][4];
#pragma unroll
        for (int ni = 0; ni < 8; ni++)
#pragma unroll
            for (int e = 0; e < 4; e++) sacc[ni][e] = 0.f;

        const uint32_t kst = sK + st * 18432;
#pragma unroll
        for (int p = 0; p < 3; ++p) {
            const uint32_t sa = (p == 1) ? sQl : sQh;
            const uint32_t sb = kst + ((p == 2) ? 9216u : 0u);
#pragma unroll
            for (int ks = 0; ks < 4; ++ks) {
                uint32_t af[4];
                ldm_x4(af, sa + (arow_off * 72 + ks * 16 + a_koff) * 2);
                uint32_t bf[4][4];
#pragma unroll
                for (int bt = 0; bt < 4; bt++)
                    ldm_x4(bf[bt], sb + ((bt * 16 + b_base) * 72 + ks * 16 + b_koff) * 2);
#pragma unroll
                for (int ni = 0; ni < 8; ni++)
                    mma_bf16(sacc[ni], af, bf[ni >> 1][(ni & 1) * 2],
                             bf[ni >> 1][(ni & 1) * 2 + 1]);
            }
        }

        // ---- online softmax (full row inside this warp) + P split-store ----
        const int kbase = t * 64 + tig * 2;
#pragma unroll
        for (int half = 0; half < 2; ++half) {
            float pv[16];
            float vmax = -INFINITY;
#pragma unroll
            for (int ni = 0; ni < 8; ++ni) {
                float v0 = fmaf(sacc[ni][half * 2 + 0], INV_SCALE, maskb[kbase + ni * 8]);
                float v1 = fmaf(sacc[ni][half * 2 + 1], INV_SCALE, maskb[kbase + ni * 8 + 1]);
                pv[ni * 2] = v0; pv[ni * 2 + 1] = v1;
                vmax = fmaxf(vmax, fmaxf(v0, v1));
            }
            vmax = fmaxf(vmax, __shfl_xor_sync(0xffffffffu, vmax, 1));
            vmax = fmaxf(vmax, __shfl_xor_sync(0xffffffffu, vmax, 2));
            float mnew = fmaxf(m_s[half], vmax);
            float alpha = __expf(m_s[half] - mnew);
            m_s[half] = mnew;
            float sum = 0.f;
            const int prow = wid * 16 + g + half * 8;
#pragma unroll
            for (int ni = 0; ni < 8; ++ni) {
                float p0 = __expf(pv[ni * 2] - mnew);
                float p1 = __expf(pv[ni * 2 + 1] - mnew);
                sum += p0 + p1;
                __nv_bfloat16 h0 = __float2bfloat16_rn(p0), h1 = __float2bfloat16_rn(p1);
                __nv_bfloat16 q0 = __float2bfloat16_rn(p0 - __bfloat162float(h0));
                __nv_bfloat16 q1 = __float2bfloat16_rn(p1 - __bfloat162float(h1));
                const uint32_t po = (prow * 72 + ni * 8 + tig * 2) * 2;
                *(__nv_bfloat162*)(Phb + po) = __nv_bfloat162(h0, h1);
                *(__nv_bfloat162*)(Plb + po) = __nv_bfloat162(q0, q1);
            }
            sum += __shfl_xor_sync(0xffffffffu, sum, 1);
            sum += __shfl_xor_sync(0xffffffffu, sum, 2);
            l_s[half] = l_s[half] * alpha + sum;
#pragma unroll
            for (int ni = 0; ni < 8; ++ni) {
                oacc[ni][half * 2 + 0] *= alpha;
                oacc[ni][half * 2 + 1] *= alpha;
            }
        }
        __syncthreads();

        // ---- O += P @ V (3 split passes); B = V^T rows hd, cols key ----
        const uint32_t vst = sV + st * 18432;
#pragma unroll
        for (int p = 0; p < 3; ++p) {
            const uint32_t sa = (p == 1) ? sPl : sPh;
            const uint32_t sb = vst + ((p == 2) ? 9216u : 0u);
#pragma unroll
            for (int ks = 0; ks < 4; ++ks) {
                uint32_t af[4];
                ldm_x4(af, sa + (arow_off * 72 + ks * 16 + a_koff) * 2);
                uint32_t bf[4][4];
#pragma unroll
                for (int bt = 0; bt < 4; bt++)
                    ldm_x4(bf[bt], sb + ((bt * 16 + b_base) * 72 + ks * 16 + b_koff) * 2);
#pragma unroll
                for (int ni = 0; ni < 8; ni++)
                    mma_bf16(oacc[ni], af, bf[ni >> 1][(ni & 1) * 2],
                             bf[ni >> 1][(ni & 1) * 2 + 1]);
            }
        }
    }

    // ---- epilogue: O / l -> g_att ----
#pragma unroll
    for (int half = 0; half < 2; ++half) {
        const float inv = 1.f / l_s[half];
        const int srow = qb + wid * 16 + g + half * 8;
        float* dst = g_att + ((size_t)b * SEQ + srow) * DMODEL + h * HDIM + tig * 2;
#pragma unroll
        for (int ni = 0; ni < 8; ++ni) {
            float2 val;
            val.x = oacc[ni][half * 2 + 0] * inv;
            val.y = oacc[ni][half * 2 + 1] * inv;
            *(float2*)(dst + ni * 8) = val;
        }
    }
}

// ---------------------------------------------------------------------------
extern "C" void kernel_launch(void* const* d_in, const int* in_sizes, int n_in,
                              void* d_out, int out_size)
{
    (void)in_sizes; (void)n_in; (void)out_size;
    const float* x       = (const float*)d_in[0];
    const float* mask    = (const float*)d_in[1];
    const float* w_attn  = (const float*)d_in[2];
    const float* b_attn  = (const float*)d_in[3];
    const float* w_proj  = (const float*)d_in[4];
    const float* b_proj  = (const float*)d_in[5];
    float* out = (float*)d_out;

    cudaFuncSetAttribute(flash_kernel, cudaFuncAttributeMaxDynamicSharedMemorySize, FL_SMEM);

    __nv_bfloat16 *xh, *xl, *ah, *al, *wqh, *wql, *wph, *wpl;
    cudaGetSymbolAddress((void**)&xh,  g_xh);  cudaGetSymbolAddress((void**)&xl,  g_xl);
    cudaGetSymbolAddress((void**)&ah,  g_ah);  cudaGetSymbolAddress((void**)&al,  g_al);
    cudaGetSymbolAddress((void**)&wqh, g_wqh); cudaGetSymbolAddress((void**)&wql, g_wql);
    cudaGetSymbolAddress((void**)&wph, g_wph); cudaGetSymbolAddress((void**)&wpl, g_wpl);
    float* att; cudaGetSymbolAddress((void**)&att, g_att);

    // 1) input split + weight transposes
    {
        int n4 = (M_ROWS * DMODEL) / 4;
        split_kernel<<<(n4 + 255) / 256, 256>>>(x, xh, xl, n4);
        transpose_split_kernel<<<dim3(N_QKV / 32, DMODEL / 32), dim3(32, 8)>>>(
            w_attn, wqh, wql, DMODEL, N_QKV);
        transpose_split_kernel<<<dim3(DMODEL / 32, DMODEL / 32), dim3(32, 8)>>>(
            w_proj, wph, wpl, DMODEL, DMODEL);
    }
    // 2) QKV GEMM -> q/k bf16 hi/lo + v fp32
    gemm_kernel<0><<<dim3(N_QKV / 128, M_ROWS / 128), 256>>>(b_attn, nullptr, N_QKV);
    // 3) V transpose+split -> [b,h,hd,s] bf16 hi/lo
    transpose_split_v<<<dim3(SEQ / 32, HDIM / 32, BATCH * NHEAD), dim3(32, 8)>>>(0);
    // 4) tensor-core flash attention -> g_att
    flash_kernel<<<dim3(SEQ / 128, NHEAD, BATCH), 256, FL_SMEM>>>(mask);
    // 5) split g_att, proj GEMM -> out
    {
        int n4 = (M_ROWS * DMODEL) / 4;
        split_kernel<<<(n4 + 255) / 256, 256>>>(att, ah, al, n4);
    }
    gemm_kernel<1><<<dim3(DMODEL / 128, M_ROWS / 128), 256>>>(b_proj, out, DMODEL);
}

// round 7
// speedup vs baseline: 3.0278x; 1.0278x over previous
#include <cuda_runtime.h>
#include <cuda_bf16.h>
#include <math.h>
#include <stdint.h>

// Problem constants
#define BATCH 2
#define SEQ   2048
#define DMODEL 1024
#define NHEAD 16
#define HDIM  64
#define M_ROWS (BATCH * SEQ)          // 4096
#define N_QKV  (3 * DMODEL)           // 3072
#define INV_SCALE 0.125f

// ---------------------------------------------------------------------------
// Scratch buffers
// ---------------------------------------------------------------------------
__device__ __align__(256) float g_v[BATCH * NHEAD * SEQ * HDIM];
__device__ __align__(256) __nv_bfloat16 g_xh[M_ROWS * DMODEL], g_xl[M_ROWS * DMODEL];
__device__ __align__(256) __nv_bfloat16 g_ah[M_ROWS * DMODEL], g_al[M_ROWS * DMODEL];
__device__ __align__(256) __nv_bfloat16 g_wqh[N_QKV * DMODEL], g_wql[N_QKV * DMODEL];
__device__ __align__(256) __nv_bfloat16 g_wph[DMODEL * DMODEL], g_wpl[DMODEL * DMODEL];
__device__ __align__(256) __nv_bfloat16 g_qh[BATCH * NHEAD * SEQ * HDIM], g_ql[BATCH * NHEAD * SEQ * HDIM];
__device__ __align__(256) __nv_bfloat16 g_kh[BATCH * NHEAD * SEQ * HDIM], g_kl[BATCH * NHEAD * SEQ * HDIM];
__device__ __align__(256) __nv_bfloat16 g_vth[BATCH * NHEAD * SEQ * HDIM], g_vtl[BATCH * NHEAD * SEQ * HDIM];

// ---------------------------------------------------------------------------
// PTX helpers (sm_80-era: valid on compute_100 base target)
// ---------------------------------------------------------------------------
__device__ __forceinline__ uint32_t smem_u32(const void* p) {
    uint32_t a;
    asm("{ .reg .u64 t; cvta.to.shared.u64 t, %1; cvt.u32.u64 %0, t; }" : "=r"(a) : "l"(p));
    return a;
}
__device__ __forceinline__ void cp16(uint32_t saddr, const void* gaddr) {
    asm volatile("cp.async.cg.shared.global [%0], [%1], 16;" :: "r"(saddr), "l"(gaddr) : "memory");
}
__device__ __forceinline__ void cp_commit() { asm volatile("cp.async.commit_group;" ::: "memory"); }
__device__ __forceinline__ void cp_wait0()  { asm volatile("cp.async.wait_group 0;" ::: "memory"); }
__device__ __forceinline__ void cp_wait1()  { asm volatile("cp.async.wait_group 1;" ::: "memory"); }

__device__ __forceinline__ void ldm_x4(uint32_t* r, uint32_t addr) {
    asm volatile("ldmatrix.sync.aligned.m8n8.x4.shared.b16 {%0,%1,%2,%3}, [%4];"
        : "=r"(r[0]), "=r"(r[1]), "=r"(r[2]), "=r"(r[3]) : "r"(addr));
}
__device__ __forceinline__ void mma_bf16(float* c, const uint32_t* a, uint32_t b0, uint32_t b1) {
    asm volatile("mma.sync.aligned.m16n8k16.row.col.f32.bf16.bf16.f32 "
        "{%0,%1,%2,%3}, {%4,%5,%6,%7}, {%8,%9}, {%0,%1,%2,%3};"
        : "+f"(c[0]), "+f"(c[1]), "+f"(c[2]), "+f"(c[3])
        : "r"(a[0]), "r"(a[1]), "r"(a[2]), "r"(a[3]), "r"(b0), "r"(b1));
}

// ---------------------------------------------------------------------------
// fp32 -> (hi, lo) bf16 split, vectorized x4
// ---------------------------------------------------------------------------
__global__ void split_kernel(const float* __restrict__ src,
                             __nv_bfloat16* __restrict__ hi,
                             __nv_bfloat16* __restrict__ lo, int n4)
{
    int i = blockIdx.x * blockDim.x + threadIdx.x;
    if (i >= n4) return;
    float4 v = ((const float4*)src)[i];
    __nv_bfloat16 h0 = __float2bfloat16_rn(v.x), h1 = __float2bfloat16_rn(v.y);
    __nv_bfloat16 h2 = __float2bfloat16_rn(v.z), h3 = __float2bfloat16_rn(v.w);
    __nv_bfloat16 l0 = __float2bfloat16_rn(v.x - __bfloat162float(h0));
    __nv_bfloat16 l1 = __float2bfloat16_rn(v.y - __bfloat162float(h1));
    __nv_bfloat16 l2 = __float2bfloat16_rn(v.z - __bfloat162float(h2));
    __nv_bfloat16 l3 = __float2bfloat16_rn(v.w - __bfloat162float(h3));
    ((__nv_bfloat162*)hi)[i * 2 + 0] = __nv_bfloat162(h0, h1);
    ((__nv_bfloat162*)hi)[i * 2 + 1] = __nv_bfloat162(h2, h3);
    ((__nv_bfloat162*)lo)[i * 2 + 0] = __nv_bfloat162(l0, l1);
    ((__nv_bfloat162*)lo)[i * 2 + 1] = __nv_bfloat162(l2, l3);
}

// ---------------------------------------------------------------------------
// W[K][N] fp32 -> Th/Tl[N][K] bf16 (transpose + split), 32x32 tiles
// ---------------------------------------------------------------------------
__global__ void transpose_split_kernel(const float* __restrict__ W,
                                       __nv_bfloat16* __restrict__ Th,
                                       __nv_bfloat16* __restrict__ Tl,
                                       int K, int N)
{
    __shared__ float t[32][33];
    int nb = blockIdx.x * 32, kb = blockIdx.y * 32;
    int tx = threadIdx.x, ty = threadIdx.y;   // 32 x 8
#pragma unroll
    for (int i = 0; i < 32; i += 8)
        t[ty + i][tx] = W[(size_t)(kb + ty + i) * N + nb + tx];
    __syncthreads();
#pragma unroll
    for (int i = 0; i < 32; i += 8) {
        float v = t[tx][ty + i];
        __nv_bfloat16 h = __float2bfloat16_rn(v);
        __nv_bfloat16 l = __float2bfloat16_rn(v - __bfloat162float(h));
        size_t o = (size_t)(nb + ty + i) * K + kb + tx;
        Th[o] = h;  Tl[o] = l;
    }
}

// ---------------------------------------------------------------------------
// V [b,h,s,hd] fp32 -> V^T [b,h,hd,s] bf16 hi/lo
// ---------------------------------------------------------------------------
__global__ void transpose_split_v(int dummy)
{
    __shared__ float tt[32][33];
    const int sb = blockIdx.x * 32, hb = blockIdx.y * 32;
    const size_t base = (size_t)blockIdx.z * SEQ * HDIM;
    const int tx = threadIdx.x, ty = threadIdx.y;   // 32 x 8
#pragma unroll
    for (int i = 0; i < 32; i += 8)
        tt[ty + i][tx] = g_v[base + (size_t)(sb + ty + i) * HDIM + hb + tx];
    __syncthreads();
#pragma unroll
    for (int i = 0; i < 32; i += 8) {
        float v = tt[tx][ty + i];                       // s=sb+tx, hd=hb+ty+i
        __nv_bfloat16 h = __float2bfloat16_rn(v);
        __nv_bfloat16 l = __float2bfloat16_rn(v - __bfloat162float(h));
        size_t o = base + (size_t)(hb + ty + i) * SEQ + sb + tx;
        g_vth[o] = h;  g_vtl[o] = l;
    }
    (void)dummy;
}

// ---------------------------------------------------------------------------
// bf16 mma.sync GEMM, FUSED 3-pass split: per K-chunk load Ah,Al,Bh,Bl once,
// run AhBh + AlBh + AhBl. Block 128x128, Kc=32, 2-stage pipeline (80KB dyn),
// 8 warps as 2(M)x4(N). MODE 0: epilogue -> q/k hi/lo + v.  MODE 1: Cout.
// ---------------------------------------------------------------------------
#define AS_STR 40
#define GM_TILE_B 10240                 // one 128x32 bf16 tile (stride 40)
#define GM_STAGE_B (4 * GM_TILE_B)      // Ah|Al|Bh|Bl
#define GM_SMEM (2 * GM_STAGE_B)        // 81920

template <int MODE>
__global__ __launch_bounds__(256, 2) void gemm_kernel(const float* __restrict__ bias,
                                                      float* __restrict__ Cout, int Ndim)
{
    extern __shared__ __align__(16) char gsm[];
    const uint32_t sS = smem_u32(gsm);

    const int tid = threadIdx.x;
    const int wid = tid >> 5, lane = tid & 31;
    const int wm = wid >> 2, wn = wid & 3;
    const int mBase = blockIdx.y * 128;
    const int nBase = blockIdx.x * 128;

    const __nv_bfloat16* Ah = (MODE == 0) ? g_xh : g_ah;
    const __nv_bfloat16* Al = (MODE == 0) ? g_xl : g_al;
    const __nv_bfloat16* Bh = (MODE == 0) ? g_wqh : g_wph;
    const __nv_bfloat16* Bl = (MODE == 0) ? g_wql : g_wpl;

    auto load_stage = [&](int kc, int st) {
        const int k0 = kc * 32;
        const __nv_bfloat16* base[4] = {
            Ah + (size_t)mBase * DMODEL + k0,
            Al + (size_t)mBase * DMODEL + k0,
            Bh + (size_t)nBase * DMODEL + k0,
            Bl + (size_t)nBase * DMODEL + k0 };
        const uint32_t stg = sS + st * GM_STAGE_B;
#pragma unroll
        for (int i = 0; i < 8; ++i) {
            int c = i * 256 + tid;
            int tile = c >> 9, w = c & 511, r = w >> 2, cb = w & 3;
            cp16(stg + tile * GM_TILE_B + (r * AS_STR + cb * 8) * 2,
                 base[tile] + (size_t)r * DMODEL + cb * 8);
        }
        cp_commit();
    };

    float acc[4][4][4];
#pragma unroll
    for (int mi = 0; mi < 4; mi++)
#pragma unroll
        for (int ni = 0; ni < 4; ni++)
#pragma unroll
            for (int e = 0; e < 4; e++) acc[mi][ni][e] = 0.f;

    const int a_row = wm * 64 + (lane & 15);
    const int a_koff = (lane >> 4) * 8;
    const int b_row = wn * 32 + ((lane >> 4) & 1) * 8 + (lane & 7);
    const int b_koff = ((lane >> 3) & 1) * 8;

    load_stage(0, 0);

    for (int cc = 0; cc < 32; ++cc) {
        const int st = cc & 1;
        cp_wait0();
        __syncthreads();
        if (cc + 1 < 32) load_stage(cc + 1, 1 - st);

        const uint32_t stg = sS + st * GM_STAGE_B;
#pragma unroll
        for (int p = 0; p < 3; ++p) {
            const uint32_t sa = stg + ((p == 1) ? GM_TILE_B : 0);
            const uint32_t sbb = stg + 2 * GM_TILE_B + ((p == 2) ? GM_TILE_B : 0);
#pragma unroll
            for (int ks = 0; ks < 2; ++ks) {
                uint32_t a[4][4];
#pragma unroll
                for (int mi = 0; mi < 4; mi++)
                    ldm_x4(a[mi], sa + ((a_row + mi * 16) * AS_STR + ks * 16 + a_koff) * 2);
                uint32_t b[2][4];
#pragma unroll
                for (int bt = 0; bt < 2; bt++)
                    ldm_x4(b[bt], sbb + ((b_row + bt * 16) * AS_STR + ks * 16 + b_koff) * 2);
#pragma unroll
                for (int mi = 0; mi < 4; mi++)
#pragma unroll
                    for (int ni = 0; ni < 4; ni++)
                        mma_bf16(acc[mi][ni], a[mi], b[ni >> 1][(ni & 1) * 2],
                                 b[ni >> 1][(ni & 1) * 2 + 1]);
            }
        }
        __syncthreads();
    }

    const int gid = lane >> 2, tig = lane & 3;
#pragma unroll
    for (int mi = 0; mi < 4; mi++) {
#pragma unroll
        for (int half = 0; half < 2; half++) {
            const int m = mBase + wm * 64 + mi * 16 + gid + half * 8;
#pragma unroll
            for (int ni = 0; ni < 4; ni++) {
                const int n = nBase + wn * 32 + ni * 8 + tig * 2;
                float2 val;
                val.x = acc[mi][ni][half * 2 + 0] + bias[n];
                val.y = acc[mi][ni][half * 2 + 1] + bias[n + 1];
                if (MODE == 1) {
                    *(float2*)(Cout + (size_t)m * Ndim + n) = val;
                } else {
                    const int b = m >> 11, srow = m & 2047;
                    const int sec = n >> 10, dd = n & 1023;
                    const int hh = dd >> 6, hd = dd & 63;
                    const size_t idx = (((size_t)(b * NHEAD + hh)) * SEQ + srow) * HDIM + hd;
                    if (sec == 2) {
                        *(float2*)(g_v + idx) = val;
                    } else {
                        __nv_bfloat16 hx = __float2bfloat16_rn(val.x);
                        __nv_bfloat16 hy = __float2bfloat16_rn(val.y);
                        __nv_bfloat16 lx = __float2bfloat16_rn(val.x - __bfloat162float(hx));
                        __nv_bfloat16 ly = __float2bfloat16_rn(val.y - __bfloat162float(hy));
                        __nv_bfloat16* dh = (sec == 0) ? g_qh : g_kh;
                        __nv_bfloat16* dl = (sec == 0) ? g_ql : g_kl;
                        *(__nv_bfloat162*)(dh + idx) = __nv_bfloat162(hx, hy);
                        *(__nv_bfloat162*)(dl + idx) = __nv_bfloat162(lx, ly);
                    }
                }
            }
        }
    }
}

// ---------------------------------------------------------------------------
// Tensor-core flash attention. 8 warps x (16 rows x 64 cols) (R6 layout, passing).
// Single-buffered K and V (110.6KB smem -> 2 CTAs/SM); overlap via commit
// groups: V_t loads during QK+softmax, K_{t+1} loads during PV.
// Epilogue writes bf16 hi/lo directly to g_ah/g_al (no fp32 g_att).
// ---------------------------------------------------------------------------
#define FL_SMEM 110592

__global__ __launch_bounds__(256, 2) void flash_kernel(const float* __restrict__ mask)
{
    extern __shared__ __align__(16) char fsm[];
    const uint32_t S0 = smem_u32(fsm);
    const uint32_t sQh = S0,          sQl = S0 + 18432;
    const uint32_t sKh = S0 + 36864,  sKl = S0 + 46080;
    const uint32_t sVh = S0 + 55296,  sVl = S0 + 64512;
    char* Phb = fsm + 73728;
    char* Plb = fsm + 92160;
    const uint32_t sPh = S0 + 73728,  sPl = S0 + 92160;

    const int qb = blockIdx.x * 128;
    const int h  = blockIdx.y, b = blockIdx.z;
    const int bh = b * NHEAD + h;
    const int tid = threadIdx.x, wid = tid >> 5, lane = tid & 31;

    const __nv_bfloat16* Qhg = g_qh + (size_t)bh * SEQ * HDIM;
    const __nv_bfloat16* Qlg = g_ql + (size_t)bh * SEQ * HDIM;
    const __nv_bfloat16* Khg = g_kh + (size_t)bh * SEQ * HDIM;
    const __nv_bfloat16* Klg = g_kl + (size_t)bh * SEQ * HDIM;
    const __nv_bfloat16* Vhg = g_vth + (size_t)bh * SEQ * HDIM;  // [hd][s]
    const __nv_bfloat16* Vlg = g_vtl + (size_t)bh * SEQ * HDIM;
    const float* maskb = mask + (size_t)b * SEQ;

    auto load_K = [&](int kb) {
        for (int i = tid; i < 512; i += 256) {
            int r = i >> 3, cb = i & 7;
            uint32_t so = (r * 72 + cb * 8) * 2;
            cp16(sKh + so, Khg + (size_t)(kb + r) * HDIM + cb * 8);
            cp16(sKl + so, Klg + (size_t)(kb + r) * HDIM + cb * 8);
        }
    };
    auto load_V = [&](int kb) {
        for (int i = tid; i < 512; i += 256) {
            int r = i >> 3, cb = i & 7;
            uint32_t so = (r * 72 + cb * 8) * 2;
            cp16(sVh + so, Vhg + (size_t)r * SEQ + kb + cb * 8);
            cp16(sVl + so, Vlg + (size_t)r * SEQ + kb + cb * 8);
        }
    };

    // prologue: Q tile + K tile 0 as one commit group
    for (int i = tid; i < 1024; i += 256) {
        int r = i >> 3, cb = i & 7;
        uint32_t so = (r * 72 + cb * 8) * 2;
        cp16(sQh + so, Qhg + (size_t)(qb + r) * HDIM + cb * 8);
        cp16(sQl + so, Qlg + (size_t)(qb + r) * HDIM + cb * 8);
    }
    load_K(0);
    cp_commit();

    float m_s[2], l_s[2], oacc[8][4];
#pragma unroll
    for (int i = 0; i < 2; i++) { m_s[i] = -INFINITY; l_s[i] = 0.f; }
#pragma unroll
    for (int ni = 0; ni < 8; ni++)
#pragma unroll
        for (int e = 0; e < 4; e++) oacc[ni][e] = 0.f;

    const int a_base = lane & 15, a_koff = (lane >> 4) * 8;
    const int b_base = ((lane >> 4) & 1) * 8 + (lane & 7), b_koff = ((lane >> 3) & 1) * 8;
    const int g = lane >> 2, tig = lane & 3;
    const int arow_off = wid * 16 + a_base;

    for (int t = 0; t < 32; ++t) {
        load_V(t * 64);
        cp_commit();                 // groups: [K_t(+Q), V_t]
        cp_wait1();                  // K_t (and Q) ready
        __syncthreads();

        // ---- S = Q @ K^T (3 split passes) ----
        float sacc[8][4];
#pragma unroll
        for (int ni = 0; ni < 8; ni++)
#pragma unroll
            for (int e = 0; e < 4; e++) sacc[ni][e] = 0.f;

#pragma unroll
        for (int p = 0; p < 3; ++p) {
            const uint32_t sa = (p == 1) ? sQl : sQh;
            const uint32_t sb = (p == 2) ? sKl : sKh;
#pragma unroll
            for (int ks = 0; ks < 4; ++ks) {
                uint32_t af[4];
                ldm_x4(af, sa + (arow_off * 72 + ks * 16 + a_koff) * 2);
                uint32_t bf[4][4];
#pragma unroll
                for (int bt = 0; bt < 4; bt++)
                    ldm_x4(bf[bt], sb + ((bt * 16 + b_base) * 72 + ks * 16 + b_koff) * 2);
#pragma unroll
                for (int ni = 0; ni < 8; ni++)
                    mma_bf16(sacc[ni], af, bf[ni >> 1][(ni & 1) * 2],
                             bf[ni >> 1][(ni & 1) * 2 + 1]);
            }
        }

        // ---- online softmax (in-place in sacc) + P split-store ----
        const int kbase = t * 64 + tig * 2;
#pragma unroll
        for (int half = 0; half < 2; ++half) {
            float vmax = -INFINITY;
#pragma unroll
            for (int ni = 0; ni < 8; ++ni) {
                float v0 = fmaf(sacc[ni][half * 2 + 0], INV_SCALE, maskb[kbase + ni * 8]);
                float v1 = fmaf(sacc[ni][half * 2 + 1], INV_SCALE, maskb[kbase + ni * 8 + 1]);
                sacc[ni][half * 2 + 0] = v0; sacc[ni][half * 2 + 1] = v1;
                vmax = fmaxf(vmax, fmaxf(v0, v1));
            }
            vmax = fmaxf(vmax, __shfl_xor_sync(0xffffffffu, vmax, 1));
            vmax = fmaxf(vmax, __shfl_xor_sync(0xffffffffu, vmax, 2));
            float mnew = fmaxf(m_s[half], vmax);
            float alpha = __expf(m_s[half] - mnew);
            m_s[half] = mnew;
            float sum = 0.f;
            const int prow = wid * 16 + g + half * 8;
#pragma unroll
            for (int ni = 0; ni < 8; ++ni) {
                float p0 = __expf(sacc[ni][half * 2 + 0] - mnew);
                float p1 = __expf(sacc[ni][half * 2 + 1] - mnew);
                sum += p0 + p1;
                __nv_bfloat16 h0 = __float2bfloat16_rn(p0), h1 = __float2bfloat16_rn(p1);
                __nv_bfloat16 q0 = __float2bfloat16_rn(p0 - __bfloat162float(h0));
                __nv_bfloat16 q1 = __float2bfloat16_rn(p1 - __bfloat162float(h1));
                const uint32_t po = (prow * 72 + ni * 8 + tig * 2) * 2;
                *(__nv_bfloat162*)(Phb + po) = __nv_bfloat162(h0, h1);
                *(__nv_bfloat162*)(Plb + po) = __nv_bfloat162(q0, q1);
            }
            sum += __shfl_xor_sync(0xffffffffu, sum, 1);
            sum += __shfl_xor_sync(0xffffffffu, sum, 2);
            l_s[half] = l_s[half] * alpha + sum;
#pragma unroll
            for (int ni = 0; ni < 8; ++ni) {
                oacc[ni][half * 2 + 0] *= alpha;
                oacc[ni][half * 2 + 1] *= alpha;
            }
        }
        __syncthreads();             // all warps done reading K

        load_K(((t + 1) & 31) * 64); // prefetch next K during PV (clamped)
        cp_commit();                 // groups: [V_t, K_{t+1}]
        cp_wait1();                  // V_t ready
        __syncthreads();

        // ---- O += P @ V (3 split passes) ----
#pragma unroll
        for (int p = 0; p < 3; ++p) {
            const uint32_t sa = (p == 1) ? sPl : sPh;
            const uint32_t sb = (p == 2) ? sVl : sVh;
#pragma unroll
            for (int ks = 0; ks < 4; ++ks) {
                uint32_t af[4];
                ldm_x4(af, sa + (arow_off * 72 + ks * 16 + a_koff) * 2);
                uint32_t bf[4][4];
#pragma unroll
                for (int bt = 0; bt < 4; bt++)
                    ldm_x4(bf[bt], sb + ((bt * 16 + b_base) * 72 + ks * 16 + b_koff) * 2);
#pragma unroll
                for (int ni = 0; ni < 8; ni++)
                    mma_bf16(oacc[ni], af, bf[ni >> 1][(ni & 1) * 2],
                             bf[ni >> 1][(ni & 1) * 2 + 1]);
            }
        }
        __syncthreads();             // all warps done reading V before next V load
    }

    // ---- epilogue: O / l -> g_ah/g_al (pre-split for proj GEMM) ----
#pragma unroll
    for (int half = 0; half < 2; ++half) {
        const float inv = 1.f / l_s[half];
        const int srow = qb + wid * 16 + g + half * 8;
        const size_t rowoff = ((size_t)b * SEQ + srow) * DMODEL + h * HDIM + tig * 2;
#pragma unroll
        for (int ni = 0; ni < 8; ++ni) {
            float v0 = oacc[ni][half * 2 + 0] * inv;
            float v1 = oacc[ni][half * 2 + 1] * inv;
            __nv_bfloat16 h0 = __float2bfloat16_rn(v0), h1 = __float2bfloat16_rn(v1);
            __nv_bfloat16 l0 = __float2bfloat16_rn(v0 - __bfloat162float(h0));
            __nv_bfloat16 l1 = __float2bfloat16_rn(v1 - __bfloat162float(h1));
            *(__nv_bfloat162*)(g_ah + rowoff + ni * 8) = __nv_bfloat162(h0, h1);
            *(__nv_bfloat162*)(g_al + rowoff + ni * 8) = __nv_bfloat162(l0, l1);
        }
    }
}

// ---------------------------------------------------------------------------
extern "C" void kernel_launch(void* const* d_in, const int* in_sizes, int n_in,
                              void* d_out, int out_size)
{
    (void)in_sizes; (void)n_in; (void)out_size;
    const float* x       = (const float*)d_in[0];
    const float* mask    = (const float*)d_in[1];
    const float* w_attn  = (const float*)d_in[2];
    const float* b_attn  = (const float*)d_in[3];
    const float* w_proj  = (const float*)d_in[4];
    const float* b_proj  = (const float*)d_in[5];
    float* out = (float*)d_out;

    cudaFuncSetAttribute(flash_kernel, cudaFuncAttributeMaxDynamicSharedMemorySize, FL_SMEM);
    cudaFuncSetAttribute(gemm_kernel<0>, cudaFuncAttributeMaxDynamicSharedMemorySize, GM_SMEM);
    cudaFuncSetAttribute(gemm_kernel<1>, cudaFuncAttributeMaxDynamicSharedMemorySize, GM_SMEM);

    __nv_bfloat16 *xh, *xl, *wqh, *wql, *wph, *wpl;
    cudaGetSymbolAddress((void**)&xh,  g_xh);  cudaGetSymbolAddress((void**)&xl,  g_xl);
    cudaGetSymbolAddress((void**)&wqh, g_wqh); cudaGetSymbolAddress((void**)&wql, g_wql);
    cudaGetSymbolAddress((void**)&wph, g_wph); cudaGetSymbolAddress((void**)&wpl, g_wpl);

    // 1) input split + weight transposes
    {
        int n4 = (M_ROWS * DMODEL) / 4;
        split_kernel<<<(n4 + 255) / 256, 256>>>(x, xh, xl, n4);
        transpose_split_kernel<<<dim3(N_QKV / 32, DMODEL / 32), dim3(32, 8)>>>(
            w_attn, wqh, wql, DMODEL, N_QKV);
        transpose_split_kernel<<<dim3(DMODEL / 32, DMODEL / 32), dim3(32, 8)>>>(
            w_proj, wph, wpl, DMODEL, DMODEL);
    }
    // 2) QKV GEMM -> q/k bf16 hi/lo + v fp32
    gemm_kernel<0><<<dim3(N_QKV / 128, M_ROWS / 128), 256, GM_SMEM>>>(b_attn, nullptr, N_QKV);
    // 3) V transpose+split -> [b,h,hd,s] bf16 hi/lo
    transpose_split_v<<<dim3(SEQ / 32, HDIM / 32, BATCH * NHEAD), dim3(32, 8)>>>(0);
    // 4) tensor-core flash attention -> g_ah/g_al (pre-split)
    flash_kernel<<<dim3(SEQ / 128, NHEAD, BATCH), 256, FL_SMEM>>>(mask);
    // 5) proj GEMM -> out
    gemm_kernel<1><<<dim3(DMODEL / 128, M_ROWS / 128), 256, GM_SMEM>>>(b_proj, out, DMODEL);
}

// round 9
// speedup vs baseline: 3.4937x; 1.1539x over previous
#include <cuda_runtime.h>
#include <cuda_bf16.h>
#include <math.h>
#include <stdint.h>

// Problem constants
#define BATCH 2
#define SEQ   2048
#define DMODEL 1024
#define NHEAD 16
#define HDIM  64
#define M_ROWS (BATCH * SEQ)          // 4096
#define N_QKV  (3 * DMODEL)           // 3072
#define INV_SCALE 0.125f

// ---------------------------------------------------------------------------
// Scratch buffers
// ---------------------------------------------------------------------------
__device__ __align__(256) float g_v[BATCH * NHEAD * SEQ * HDIM];
__device__ __align__(256) __nv_bfloat16 g_xh[M_ROWS * DMODEL], g_xl[M_ROWS * DMODEL];
__device__ __align__(256) __nv_bfloat16 g_ah[M_ROWS * DMODEL], g_al[M_ROWS * DMODEL];
__device__ __align__(256) __nv_bfloat16 g_wqh[N_QKV * DMODEL], g_wql[N_QKV * DMODEL];
__device__ __align__(256) __nv_bfloat16 g_wph[DMODEL * DMODEL], g_wpl[DMODEL * DMODEL];
__device__ __align__(256) __nv_bfloat16 g_qh[BATCH * NHEAD * SEQ * HDIM], g_ql[BATCH * NHEAD * SEQ * HDIM];
__device__ __align__(256) __nv_bfloat16 g_kh[BATCH * NHEAD * SEQ * HDIM], g_kl[BATCH * NHEAD * SEQ * HDIM];
__device__ __align__(256) __nv_bfloat16 g_vth[BATCH * NHEAD * SEQ * HDIM], g_vtl[BATCH * NHEAD * SEQ * HDIM];

// ---------------------------------------------------------------------------
// PTX helpers (sm_80-era: valid on compute_100 base target)
// ---------------------------------------------------------------------------
__device__ __forceinline__ uint32_t smem_u32(const void* p) {
    uint32_t a;
    asm("{ .reg .u64 t; cvta.to.shared.u64 t, %1; cvt.u32.u64 %0, t; }" : "=r"(a) : "l"(p));
    return a;
}
__device__ __forceinline__ void cp16(uint32_t saddr, const void* gaddr) {
    asm volatile("cp.async.cg.shared.global [%0], [%1], 16;" :: "r"(saddr), "l"(gaddr) : "memory");
}
__device__ __forceinline__ void cp_commit() { asm volatile("cp.async.commit_group;" ::: "memory"); }
__device__ __forceinline__ void cp_wait0()  { asm volatile("cp.async.wait_group 0;" ::: "memory"); }
__device__ __forceinline__ void cp_wait1()  { asm volatile("cp.async.wait_group 1;" ::: "memory"); }

__device__ __forceinline__ void ldm_x4(uint32_t* r, uint32_t addr) {
    asm volatile("ldmatrix.sync.aligned.m8n8.x4.shared.b16 {%0,%1,%2,%3}, [%4];"
        : "=r"(r[0]), "=r"(r[1]), "=r"(r[2]), "=r"(r[3]) : "r"(addr));
}
__device__ __forceinline__ void mma_bf16(float* c, const uint32_t* a, uint32_t b0, uint32_t b1) {
    asm volatile("mma.sync.aligned.m16n8k16.row.col.f32.bf16.bf16.f32 "
        "{%0,%1,%2,%3}, {%4,%5,%6,%7}, {%8,%9}, {%0,%1,%2,%3};"
        : "+f"(c[0]), "+f"(c[1]), "+f"(c[2]), "+f"(c[3])
        : "r"(a[0]), "r"(a[1]), "r"(a[2]), "r"(a[3]), "r"(b0), "r"(b1));
}

// ---------------------------------------------------------------------------
// fp32 -> (hi, lo) bf16 split, vectorized x4
// ---------------------------------------------------------------------------
__global__ void split_kernel(const float* __restrict__ src,
                             __nv_bfloat16* __restrict__ hi,
                             __nv_bfloat16* __restrict__ lo, int n4)
{
    int i = blockIdx.x * blockDim.x + threadIdx.x;
    if (i >= n4) return;
    float4 v = ((const float4*)src)[i];
    __nv_bfloat16 h0 = __float2bfloat16_rn(v.x), h1 = __float2bfloat16_rn(v.y);
    __nv_bfloat16 h2 = __float2bfloat16_rn(v.z), h3 = __float2bfloat16_rn(v.w);
    __nv_bfloat16 l0 = __float2bfloat16_rn(v.x - __bfloat162float(h0));
    __nv_bfloat16 l1 = __float2bfloat16_rn(v.y - __bfloat162float(h1));
    __nv_bfloat16 l2 = __float2bfloat16_rn(v.z - __bfloat162float(h2));
    __nv_bfloat16 l3 = __float2bfloat16_rn(v.w - __bfloat162float(h3));
    ((__nv_bfloat162*)hi)[i * 2 + 0] = __nv_bfloat162(h0, h1);
    ((__nv_bfloat162*)hi)[i * 2 + 1] = __nv_bfloat162(h2, h3);
    ((__nv_bfloat162*)lo)[i * 2 + 0] = __nv_bfloat162(l0, l1);
    ((__nv_bfloat162*)lo)[i * 2 + 1] = __nv_bfloat162(l2, l3);
}

// ---------------------------------------------------------------------------
// W[K][N] fp32 -> Th/Tl[N][K] bf16 (transpose + split), 32x32 tiles
// ---------------------------------------------------------------------------
__global__ void transpose_split_kernel(const float* __restrict__ W,
                                       __nv_bfloat16* __restrict__ Th,
                                       __nv_bfloat16* __restrict__ Tl,
                                       int K, int N)
{
    __shared__ float t[32][33];
    int nb = blockIdx.x * 32, kb = blockIdx.y * 32;
    int tx = threadIdx.x, ty = threadIdx.y;   // 32 x 8
#pragma unroll
    for (int i = 0; i < 32; i += 8)
        t[ty + i][tx] = W[(size_t)(kb + ty + i) * N + nb + tx];
    __syncthreads();
#pragma unroll
    for (int i = 0; i < 32; i += 8) {
        float v = t[tx][ty + i];
        __nv_bfloat16 h = __float2bfloat16_rn(v);
        __nv_bfloat16 l = __float2bfloat16_rn(v - __bfloat162float(h));
        size_t o = (size_t)(nb + ty + i) * K + kb + tx;
        Th[o] = h;  Tl[o] = l;
    }
}

// ---------------------------------------------------------------------------
// V [b,h,s,hd] fp32 -> V^T [b,h,hd,s] bf16 hi/lo
// ---------------------------------------------------------------------------
__global__ void transpose_split_v(int dummy)
{
    __shared__ float tt[32][33];
    const int sb = blockIdx.x * 32, hb = blockIdx.y * 32;
    const size_t base = (size_t)blockIdx.z * SEQ * HDIM;
    const int tx = threadIdx.x, ty = threadIdx.y;   // 32 x 8
#pragma unroll
    for (int i = 0; i < 32; i += 8)
        tt[ty + i][tx] = g_v[base + (size_t)(sb + ty + i) * HDIM + hb + tx];
    __syncthreads();
#pragma unroll
    for (int i = 0; i < 32; i += 8) {
        float v = tt[tx][ty + i];                       // s=sb+tx, hd=hb+ty+i
        __nv_bfloat16 h = __float2bfloat16_rn(v);
        __nv_bfloat16 l = __float2bfloat16_rn(v - __bfloat162float(h));
        size_t o = base + (size_t)(hb + ty + i) * SEQ + sb + tx;
        g_vth[o] = h;  g_vtl[o] = l;
    }
    (void)dummy;
}

// ---------------------------------------------------------------------------
// bf16 mma.sync GEMM, fused 3-pass split with register fragment reuse:
// per ks: ldm Ah,Bh -> mma; ldm Al -> mma(Al,Bh); ldm Bl -> mma(Ah,Bl).
// Block 128x128, Kc=32, 2-stage cp.async pipeline, ONE barrier per chunk.
// MODE 0: epilogue -> q(*1/8)/k hi/lo + v.  MODE 1: Cout.
// ---------------------------------------------------------------------------
#define AS_STR 40
#define GM_TILE_B 10240                 // one 128x32 bf16 tile (stride 40)
#define GM_STAGE_B (4 * GM_TILE_B)      // Ah|Al|Bh|Bl
#define GM_SMEM (2 * GM_STAGE_B)        // 81920

template <int MODE>
__global__ __launch_bounds__(256, 2) void gemm_kernel(const float* __restrict__ bias,
                                                      float* __restrict__ Cout, int Ndim)
{
    extern __shared__ __align__(16) char gsm[];
    const uint32_t sS = smem_u32(gsm);

    const int tid = threadIdx.x;
    const int wid = tid >> 5, lane = tid & 31;
    const int wm = wid >> 2, wn = wid & 3;
    const int mBase = blockIdx.y * 128;
    const int nBase = blockIdx.x * 128;

    const __nv_bfloat16* Ah = (MODE == 0) ? g_xh : g_ah;
    const __nv_bfloat16* Al = (MODE == 0) ? g_xl : g_al;
    const __nv_bfloat16* Bh = (MODE == 0) ? g_wqh : g_wph;
    const __nv_bfloat16* Bl = (MODE == 0) ? g_wql : g_wpl;

    auto load_stage = [&](int kc, int st) {
        const int k0 = kc * 32;
        const __nv_bfloat16* base[4] = {
            Ah + (size_t)mBase * DMODEL + k0,
            Al + (size_t)mBase * DMODEL + k0,
            Bh + (size_t)nBase * DMODEL + k0,
            Bl + (size_t)nBase * DMODEL + k0 };
        const uint32_t stg = sS + st * GM_STAGE_B;
#pragma unroll
        for (int i = 0; i < 8; ++i) {
            int c = i * 256 + tid;
            int tile = c >> 9, w = c & 511, r = w >> 2, cb = w & 3;
            cp16(stg + tile * GM_TILE_B + (r * AS_STR + cb * 8) * 2,
                 base[tile] + (size_t)r * DMODEL + cb * 8);
        }
        cp_commit();
    };

    float acc[4][4][4];
#pragma unroll
    for (int mi = 0; mi < 4; mi++)
#pragma unroll
        for (int ni = 0; ni < 4; ni++)
#pragma unroll
            for (int e = 0; e < 4; e++) acc[mi][ni][e] = 0.f;

    const int a_row = wm * 64 + (lane & 15);
    const int a_koff = (lane >> 4) * 8;
    const int b_row = wn * 32 + ((lane >> 4) & 1) * 8 + (lane & 7);
    const int b_koff = ((lane >> 3) & 1) * 8;

    load_stage(0, 0);

    for (int cc = 0; cc < 32; ++cc) {
        const int st = cc & 1;
        cp_wait0();
        __syncthreads();             // single barrier per chunk
        if (cc + 1 < 32) load_stage(cc + 1, 1 - st);

        const uint32_t stg = sS + st * GM_STAGE_B;
#pragma unroll
        for (int ks = 0; ks < 2; ++ks) {
            uint32_t ah[4][4], al[4][4], bh[2][4], bl[2][4];
#pragma unroll
            for (int mi = 0; mi < 4; mi++)
                ldm_x4(ah[mi], stg + ((a_row + mi * 16) * AS_STR + ks * 16 + a_koff) * 2);
#pragma unroll
            for (int bt = 0; bt < 2; bt++)
                ldm_x4(bh[bt], stg + 2 * GM_TILE_B + ((b_row + bt * 16) * AS_STR + ks * 16 + b_koff) * 2);
#pragma unroll
            for (int mi = 0; mi < 4; mi++)
#pragma unroll
                for (int ni = 0; ni < 4; ni++)
                    mma_bf16(acc[mi][ni], ah[mi], bh[ni >> 1][(ni & 1) * 2],
                             bh[ni >> 1][(ni & 1) * 2 + 1]);
#pragma unroll
            for (int mi = 0; mi < 4; mi++)
                ldm_x4(al[mi], stg + GM_TILE_B + ((a_row + mi * 16) * AS_STR + ks * 16 + a_koff) * 2);
#pragma unroll
            for (int mi = 0; mi < 4; mi++)
#pragma unroll
                for (int ni = 0; ni < 4; ni++)
                    mma_bf16(acc[mi][ni], al[mi], bh[ni >> 1][(ni & 1) * 2],
                             bh[ni >> 1][(ni & 1) * 2 + 1]);
#pragma unroll
            for (int bt = 0; bt < 2; bt++)
                ldm_x4(bl[bt], stg + 3 * GM_TILE_B + ((b_row + bt * 16) * AS_STR + ks * 16 + b_koff) * 2);
#pragma unroll
            for (int mi = 0; mi < 4; mi++)
#pragma unroll
                for (int ni = 0; ni < 4; ni++)
                    mma_bf16(acc[mi][ni], ah[mi], bl[ni >> 1][(ni & 1) * 2],
                             bl[ni >> 1][(ni & 1) * 2 + 1]);
        }
    }

    const int gid = lane >> 2, tig = lane & 3;
#pragma unroll
    for (int mi = 0; mi < 4; mi++) {
#pragma unroll
        for (int half = 0; half < 2; half++) {
            const int m = mBase + wm * 64 + mi * 16 + gid + half * 8;
#pragma unroll
            for (int ni = 0; ni < 4; ni++) {
                const int n = nBase + wn * 32 + ni * 8 + tig * 2;
                float2 val;
                val.x = acc[mi][ni][half * 2 + 0] + bias[n];
                val.y = acc[mi][ni][half * 2 + 1] + bias[n + 1];
                if (MODE == 1) {
                    *(float2*)(Cout + (size_t)m * Ndim + n) = val;
                } else {
                    const int b = m >> 11, srow = m & 2047;
                    const int sec = n >> 10, dd = n & 1023;
                    const int hh = dd >> 6, hd = dd & 63;
                    const size_t idx = (((size_t)(b * NHEAD + hh)) * SEQ + srow) * HDIM + hd;
                    if (sec == 2) {
                        *(float2*)(g_v + idx) = val;
                    } else {
                        if (sec == 0) { val.x *= INV_SCALE; val.y *= INV_SCALE; } // fold 1/sqrt(hd) into Q
                        __nv_bfloat16 hx = __float2bfloat16_rn(val.x);
                        __nv_bfloat16 hy = __float2bfloat16_rn(val.y);
                        __nv_bfloat16 lx = __float2bfloat16_rn(val.x - __bfloat162float(hx));
                        __nv_bfloat16 ly = __float2bfloat16_rn(val.y - __bfloat162float(hy));
                        __nv_bfloat16* dh = (sec == 0) ? g_qh : g_kh;
                        __nv_bfloat16* dl = (sec == 0) ? g_ql : g_kl;
                        *(__nv_bfloat162*)(dh + idx) = __nv_bfloat162(hx, hy);
                        *(__nv_bfloat162*)(dl + idx) = __nv_bfloat162(lx, ly);
                    }
                }
            }
        }
    }
}

// ---------------------------------------------------------------------------
// Tensor-core flash attention, 8 warps x (16 rows x 64 cols), fragment reuse
// across split passes. Single-buffered K/V (110.6KB -> 2 CTAs/SM); overlap
// via commit groups: V_t loads during QK+softmax, K_{t+1} during PV.
// Q pre-scaled by 1/8 in the QKV epilogue.
// ---------------------------------------------------------------------------
#define FL_SMEM 110592

__global__ __launch_bounds__(256, 2) void flash_kernel(const float* __restrict__ mask)
{
    extern __shared__ __align__(16) char fsm[];
    const uint32_t S0 = smem_u32(fsm);
    const uint32_t sQh = S0,          sQl = S0 + 18432;
    const uint32_t sKh = S0 + 36864,  sKl = S0 + 46080;
    const uint32_t sVh = S0 + 55296,  sVl = S0 + 64512;
    char* Phb = fsm + 73728;
    char* Plb = fsm + 92160;
    const uint32_t sPh = S0 + 73728,  sPl = S0 + 92160;

    const int qb = blockIdx.x * 128;
    const int h  = blockIdx.y, b = blockIdx.z;
    const int bh = b * NHEAD + h;
    const int tid = threadIdx.x, wid = tid >> 5, lane = tid & 31;

    const __nv_bfloat16* Qhg = g_qh + (size_t)bh * SEQ * HDIM;
    const __nv_bfloat16* Qlg = g_ql + (size_t)bh * SEQ * HDIM;
    const __nv_bfloat16* Khg = g_kh + (size_t)bh * SEQ * HDIM;
    const __nv_bfloat16* Klg = g_kl + (size_t)bh * SEQ * HDIM;
    const __nv_bfloat16* Vhg = g_vth + (size_t)bh * SEQ * HDIM;  // [hd][s]
    const __nv_bfloat16* Vlg = g_vtl + (size_t)bh * SEQ * HDIM;
    const float* maskb = mask + (size_t)b * SEQ;

    auto load_K = [&](int kb) {
        for (int i = tid; i < 512; i += 256) {
            int r = i >> 3, cb = i & 7;
            uint32_t so = (r * 72 + cb * 8) * 2;
            cp16(sKh + so, Khg + (size_t)(kb + r) * HDIM + cb * 8);
            cp16(sKl + so, Klg + (size_t)(kb + r) * HDIM + cb * 8);
        }
    };
    auto load_V = [&](int kb) {
        for (int i = tid; i < 512; i += 256) {
            int r = i >> 3, cb = i & 7;
            uint32_t so = (r * 72 + cb * 8) * 2;
            cp16(sVh + so, Vhg + (size_t)r * SEQ + kb + cb * 8);
            cp16(sVl + so, Vlg + (size_t)r * SEQ + kb + cb * 8);
        }
    };

    // prologue: Q tile + K tile 0 as one commit group
    for (int i = tid; i < 1024; i += 256) {
        int r = i >> 3, cb = i & 7;
        uint32_t so = (r * 72 + cb * 8) * 2;
        cp16(sQh + so, Qhg + (size_t)(qb + r) * HDIM + cb * 8);
        cp16(sQl + so, Qlg + (size_t)(qb + r) * HDIM + cb * 8);
    }
    load_K(0);
    cp_commit();

    float m_s[2], l_s[2], oacc[8][4];
#pragma unroll
    for (int i = 0; i < 2; i++) { m_s[i] = -INFINITY; l_s[i] = 0.f; }
#pragma unroll
    for (int ni = 0; ni < 8; ni++)
#pragma unroll
        for (int e = 0; e < 4; e++) oacc[ni][e] = 0.f;

    const int a_base = lane & 15, a_koff = (lane >> 4) * 8;
    const int b_base = ((lane >> 4) & 1) * 8 + (lane & 7), b_koff = ((lane >> 3) & 1) * 8;
    const int g = lane >> 2, tig = lane & 3;
    const int arow_off = wid * 16 + a_base;

    for (int t = 0; t < 32; ++t) {
        load_V(t * 64);
        cp_commit();                 // groups: [K_t(+Q), V_t]
        cp_wait1();                  // K_t (and Q) ready
        __syncthreads();

        // ---- S = Q @ K^T, fragment-reuse split passes ----
        float sacc[8][4];
#pragma unroll
        for (int ni = 0; ni < 8; ni++)
#pragma unroll
            for (int e = 0; e < 4; e++) sacc[ni][e] = 0.f;

#pragma unroll
        for (int ks = 0; ks < 4; ++ks) {
            uint32_t aqh[4], aql[4], bf[4][4];
            ldm_x4(aqh, sQh + (arow_off * 72 + ks * 16 + a_koff) * 2);
#pragma unroll
            for (int bt = 0; bt < 4; bt++)
                ldm_x4(bf[bt], sKh + ((bt * 16 + b_base) * 72 + ks * 16 + b_koff) * 2);
#pragma unroll
            for (int ni = 0; ni < 8; ni++)
                mma_bf16(sacc[ni], aqh, bf[ni >> 1][(ni & 1) * 2], bf[ni >> 1][(ni & 1) * 2 + 1]);
            ldm_x4(aql, sQl + (arow_off * 72 + ks * 16 + a_koff) * 2);
#pragma unroll
            for (int ni = 0; ni < 8; ni++)
                mma_bf16(sacc[ni], aql, bf[ni >> 1][(ni & 1) * 2], bf[ni >> 1][(ni & 1) * 2 + 1]);
#pragma unroll
            for (int bt = 0; bt < 4; bt++)
                ldm_x4(bf[bt], sKl + ((bt * 16 + b_base) * 72 + ks * 16 + b_koff) * 2);
#pragma unroll
            for (int ni = 0; ni < 8; ni++)
                mma_bf16(sacc[ni], aqh, bf[ni >> 1][(ni & 1) * 2], bf[ni >> 1][(ni & 1) * 2 + 1]);
        }

        // ---- online softmax (Q pre-scaled; just add mask) + P split-store ----
        const int kbase = t * 64 + tig * 2;
#pragma unroll
        for (int half = 0; half < 2; ++half) {
            float vmax = -INFINITY;
#pragma unroll
            for (int ni = 0; ni < 8; ++ni) {
                float v0 = sacc[ni][half * 2 + 0] + maskb[kbase + ni * 8];
                float v1 = sacc[ni][half * 2 + 1] + maskb[kbase + ni * 8 + 1];
                sacc[ni][half * 2 + 0] = v0; sacc[ni][half * 2 + 1] = v1;
                vmax = fmaxf(vmax, fmaxf(v0, v1));
            }
            vmax = fmaxf(vmax, __shfl_xor_sync(0xffffffffu, vmax, 1));
            vmax = fmaxf(vmax, __shfl_xor_sync(0xffffffffu, vmax, 2));
            float mnew = fmaxf(m_s[half], vmax);
            float alpha = __expf(m_s[half] - mnew);
            m_s[half] = mnew;
            float sum = 0.f;
            const int prow = wid * 16 + g + half * 8;
#pragma unroll
            for (int ni = 0; ni < 8; ++ni) {
                float p0 = __expf(sacc[ni][half * 2 + 0] - mnew);
                float p1 = __expf(sacc[ni][half * 2 + 1] - mnew);
                sum += p0 + p1;
                __nv_bfloat16 h0 = __float2bfloat16_rn(p0), h1 = __float2bfloat16_rn(p1);
                __nv_bfloat16 q0 = __float2bfloat16_rn(p0 - __bfloat162float(h0));
                __nv_bfloat16 q1 = __float2bfloat16_rn(p1 - __bfloat162float(h1));
                const uint32_t po = (prow * 72 + ni * 8 + tig * 2) * 2;
                *(__nv_bfloat162*)(Phb + po) = __nv_bfloat162(h0, h1);
                *(__nv_bfloat162*)(Plb + po) = __nv_bfloat162(q0, q1);
            }
            sum += __shfl_xor_sync(0xffffffffu, sum, 1);
            sum += __shfl_xor_sync(0xffffffffu, sum, 2);
            l_s[half] = l_s[half] * alpha + sum;
#pragma unroll
            for (int ni = 0; ni < 8; ++ni) {
                oacc[ni][half * 2 + 0] *= alpha;
                oacc[ni][half * 2 + 1] *= alpha;
            }
        }
        __syncthreads();             // all warps done reading K

        load_K(((t + 1) & 31) * 64); // prefetch next K during PV (clamped)
        cp_commit();                 // groups: [V_t, K_{t+1}]
        cp_wait1();                  // V_t ready
        __syncthreads();

        // ---- O += P @ V, fragment-reuse split passes ----
#pragma unroll
        for (int ks = 0; ks < 4; ++ks) {
            uint32_t aph[4], apl[4], bf[4][4];
            ldm_x4(aph, sPh + (arow_off * 72 + ks * 16 + a_koff) * 2);
#pragma unroll
            for (int bt = 0; bt < 4; bt++)
                ldm_x4(bf[bt], sVh + ((bt * 16 + b_base) * 72 + ks * 16 + b_koff) * 2);
#pragma unroll
            for (int ni = 0; ni < 8; ni++)
                mma_bf16(oacc[ni], aph, bf[ni >> 1][(ni & 1) * 2], bf[ni >> 1][(ni & 1) * 2 + 1]);
            ldm_x4(apl, sPl + (arow_off * 72 + ks * 16 + a_koff) * 2);
#pragma unroll
            for (int ni = 0; ni < 8; ni++)
                mma_bf16(oacc[ni], apl, bf[ni >> 1][(ni & 1) * 2], bf[ni >> 1][(ni & 1) * 2 + 1]);
#pragma unroll
            for (int bt = 0; bt < 4; bt++)
                ldm_x4(bf[bt], sVl + ((bt * 16 + b_base) * 72 + ks * 16 + b_koff) * 2);
#pragma unroll
            for (int ni = 0; ni < 8; ni++)
                mma_bf16(oacc[ni], aph, bf[ni >> 1][(ni & 1) * 2], bf[ni >> 1][(ni & 1) * 2 + 1]);
        }
        __syncthreads();             // all warps done reading V before next V load
    }

    // ---- epilogue: O / l -> g_ah/g_al (pre-split for proj GEMM) ----
#pragma unroll
    for (int half = 0; half < 2; ++half) {
        const float inv = 1.f / l_s[half];
        const int srow = qb + wid * 16 + g + half * 8;
        const size_t rowoff = ((size_t)b * SEQ + srow) * DMODEL + h * HDIM + tig * 2;
#pragma unroll
        for (int ni = 0; ni < 8; ++ni) {
            float v0 = oacc[ni][half * 2 + 0] * inv;
            float v1 = oacc[ni][half * 2 + 1] * inv;
            __nv_bfloat16 h0 = __float2bfloat16_rn(v0), h1 = __float2bfloat16_rn(v1);
            __nv_bfloat16 l0 = __float2bfloat16_rn(v0 - __bfloat162float(h0));
            __nv_bfloat16 l1 = __float2bfloat16_rn(v1 - __bfloat162float(h1));
            *(__nv_bfloat162*)(g_ah + rowoff + ni * 8) = __nv_bfloat162(h0, h1);
            *(__nv_bfloat162*)(g_al + rowoff + ni * 8) = __nv_bfloat162(l0, l1);
        }
    }
}

// ---------------------------------------------------------------------------
extern "C" void kernel_launch(void* const* d_in, const int* in_sizes, int n_in,
                              void* d_out, int out_size)
{
    (void)in_sizes; (void)n_in; (void)out_size;
    const float* x       = (const float*)d_in[0];
    const float* mask    = (const float*)d_in[1];
    const float* w_attn  = (const float*)d_in[2];
    const float* b_attn  = (const float*)d_in[3];
    const float* w_proj  = (const float*)d_in[4];
    const float* b_proj  = (const float*)d_in[5];
    float* out = (float*)d_out;

    cudaFuncSetAttribute(flash_kernel, cudaFuncAttributeMaxDynamicSharedMemorySize, FL_SMEM);
    cudaFuncSetAttribute(gemm_kernel<0>, cudaFuncAttributeMaxDynamicSharedMemorySize, GM_SMEM);
    cudaFuncSetAttribute(gemm_kernel<1>, cudaFuncAttributeMaxDynamicSharedMemorySize, GM_SMEM);

    __nv_bfloat16 *xh, *xl, *wqh, *wql, *wph, *wpl;
    cudaGetSymbolAddress((void**)&xh,  g_xh);  cudaGetSymbolAddress((void**)&xl,  g_xl);
    cudaGetSymbolAddress((void**)&wqh, g_wqh); cudaGetSymbolAddress((void**)&wql, g_wql);
    cudaGetSymbolAddress((void**)&wph, g_wph); cudaGetSymbolAddress((void**)&wpl, g_wpl);

    // 1) input split + weight transposes
    {
        int n4 = (M_ROWS * DMODEL) / 4;
        split_kernel<<<(n4 + 255) / 256, 256>>>(x, xh, xl, n4);
        transpose_split_kernel<<<dim3(N_QKV / 32, DMODEL / 32), dim3(32, 8)>>>(
            w_attn, wqh, wql, DMODEL, N_QKV);
        transpose_split_kernel<<<dim3(DMODEL / 32, DMODEL / 32), dim3(32, 8)>>>(
            w_proj, wph, wpl, DMODEL, DMODEL);
    }
    // 2) QKV GEMM -> q(*1/8)/k bf16 hi/lo + v fp32
    gemm_kernel<0><<<dim3(N_QKV / 128, M_ROWS / 128), 256, GM_SMEM>>>(b_attn, nullptr, N_QKV);
    // 3) V transpose+split -> [b,h,hd,s] bf16 hi/lo
    transpose_split_v<<<dim3(SEQ / 32, HDIM / 32, BATCH * NHEAD), dim3(32, 8)>>>(0);
    // 4) tensor-core flash attention -> g_ah/g_al (pre-split)
    flash_kernel<<<dim3(SEQ / 128, NHEAD, BATCH), 256, FL_SMEM>>>(mask);
    // 5) proj GEMM -> out
    gemm_kernel<1><<<dim3(DMODEL / 128, M_ROWS / 128), 256, GM_SMEM>>>(b_proj, out, DMODEL);
}

// round 10
// speedup vs baseline: 3.5724x; 1.0225x over previous
#include <cuda_runtime.h>
#include <cuda_bf16.h>
#include <math.h>
#include <stdint.h>

// Problem constants
#define BATCH 2
#define SEQ   2048
#define DMODEL 1024
#define NHEAD 16
#define HDIM  64
#define M_ROWS (BATCH * SEQ)          // 4096
#define N_QKV  (3 * DMODEL)           // 3072
#define INV_SCALE 0.125f

// ---------------------------------------------------------------------------
// Scratch buffers
// ---------------------------------------------------------------------------
__device__ __align__(256) float g_v[BATCH * NHEAD * SEQ * HDIM];
__device__ __align__(256) __nv_bfloat16 g_xh[M_ROWS * DMODEL], g_xl[M_ROWS * DMODEL];
__device__ __align__(256) __nv_bfloat16 g_ah[M_ROWS * DMODEL], g_al[M_ROWS * DMODEL];
__device__ __align__(256) __nv_bfloat16 g_wqh[N_QKV * DMODEL], g_wql[N_QKV * DMODEL];
__device__ __align__(256) __nv_bfloat16 g_wph[DMODEL * DMODEL], g_wpl[DMODEL * DMODEL];
__device__ __align__(256) __nv_bfloat16 g_qh[BATCH * NHEAD * SEQ * HDIM], g_ql[BATCH * NHEAD * SEQ * HDIM];
__device__ __align__(256) __nv_bfloat16 g_kh[BATCH * NHEAD * SEQ * HDIM], g_kl[BATCH * NHEAD * SEQ * HDIM];
__device__ __align__(256) __nv_bfloat16 g_vth[BATCH * NHEAD * SEQ * HDIM], g_vtl[BATCH * NHEAD * SEQ * HDIM];

// ---------------------------------------------------------------------------
// PTX helpers (sm_80-era: valid on compute_100 base target)
// ---------------------------------------------------------------------------
__device__ __forceinline__ uint32_t smem_u32(const void* p) {
    uint32_t a;
    asm("{ .reg .u64 t; cvta.to.shared.u64 t, %1; cvt.u32.u64 %0, t; }" : "=r"(a) : "l"(p));
    return a;
}
__device__ __forceinline__ void cp16(uint32_t saddr, const void* gaddr) {
    asm volatile("cp.async.cg.shared.global [%0], [%1], 16;" :: "r"(saddr), "l"(gaddr) : "memory");
}
__device__ __forceinline__ void cp_commit() { asm volatile("cp.async.commit_group;" ::: "memory"); }
__device__ __forceinline__ void cp_wait0()  { asm volatile("cp.async.wait_group 0;" ::: "memory"); }
__device__ __forceinline__ void cp_wait1()  { asm volatile("cp.async.wait_group 1;" ::: "memory"); }

__device__ __forceinline__ void ldm_x4(uint32_t* r, uint32_t addr) {
    asm volatile("ldmatrix.sync.aligned.m8n8.x4.shared.b16 {%0,%1,%2,%3}, [%4];"
        : "=r"(r[0]), "=r"(r[1]), "=r"(r[2]), "=r"(r[3]) : "r"(addr));
}
__device__ __forceinline__ void mma_bf16(float* c, const uint32_t* a, uint32_t b0, uint32_t b1) {
    asm volatile("mma.sync.aligned.m16n8k16.row.col.f32.bf16.bf16.f32 "
        "{%0,%1,%2,%3}, {%4,%5,%6,%7}, {%8,%9}, {%0,%1,%2,%3};"
        : "+f"(c[0]), "+f"(c[1]), "+f"(c[2]), "+f"(c[3])
        : "r"(a[0]), "r"(a[1]), "r"(a[2]), "r"(a[3]), "r"(b0), "r"(b1));
}

// ---------------------------------------------------------------------------
// fp32 -> (hi, lo) bf16 split, vectorized x4
// ---------------------------------------------------------------------------
__global__ void split_kernel(const float* __restrict__ src,
                             __nv_bfloat16* __restrict__ hi,
                             __nv_bfloat16* __restrict__ lo, int n4)
{
    int i = blockIdx.x * blockDim.x + threadIdx.x;
    if (i >= n4) return;
    float4 v = ((const float4*)src)[i];
    __nv_bfloat16 h0 = __float2bfloat16_rn(v.x), h1 = __float2bfloat16_rn(v.y);
    __nv_bfloat16 h2 = __float2bfloat16_rn(v.z), h3 = __float2bfloat16_rn(v.w);
    __nv_bfloat16 l0 = __float2bfloat16_rn(v.x - __bfloat162float(h0));
    __nv_bfloat16 l1 = __float2bfloat16_rn(v.y - __bfloat162float(h1));
    __nv_bfloat16 l2 = __float2bfloat16_rn(v.z - __bfloat162float(h2));
    __nv_bfloat16 l3 = __float2bfloat16_rn(v.w - __bfloat162float(h3));
    ((__nv_bfloat162*)hi)[i * 2 + 0] = __nv_bfloat162(h0, h1);
    ((__nv_bfloat162*)hi)[i * 2 + 1] = __nv_bfloat162(h2, h3);
    ((__nv_bfloat162*)lo)[i * 2 + 0] = __nv_bfloat162(l0, l1);
    ((__nv_bfloat162*)lo)[i * 2 + 1] = __nv_bfloat162(l2, l3);
}

// ---------------------------------------------------------------------------
// W[K][N] fp32 -> Th/Tl[N][K] bf16 (transpose + split), 32x32 tiles
// ---------------------------------------------------------------------------
__global__ void transpose_split_kernel(const float* __restrict__ W,
                                       __nv_bfloat16* __restrict__ Th,
                                       __nv_bfloat16* __restrict__ Tl,
                                       int K, int N)
{
    __shared__ float t[32][33];
    int nb = blockIdx.x * 32, kb = blockIdx.y * 32;
    int tx = threadIdx.x, ty = threadIdx.y;   // 32 x 8
#pragma unroll
    for (int i = 0; i < 32; i += 8)
        t[ty + i][tx] = W[(size_t)(kb + ty + i) * N + nb + tx];
    __syncthreads();
#pragma unroll
    for (int i = 0; i < 32; i += 8) {
        float v = t[tx][ty + i];
        __nv_bfloat16 h = __float2bfloat16_rn(v);
        __nv_bfloat16 l = __float2bfloat16_rn(v - __bfloat162float(h));
        size_t o = (size_t)(nb + ty + i) * K + kb + tx;
        Th[o] = h;  Tl[o] = l;
    }
}

// ---------------------------------------------------------------------------
// V [b,h,s,hd] fp32 -> V^T [b,h,hd,s] bf16 hi/lo
// ---------------------------------------------------------------------------
__global__ void transpose_split_v(int dummy)
{
    __shared__ float tt[32][33];
    const int sb = blockIdx.x * 32, hb = blockIdx.y * 32;
    const size_t base = (size_t)blockIdx.z * SEQ * HDIM;
    const int tx = threadIdx.x, ty = threadIdx.y;   // 32 x 8
#pragma unroll
    for (int i = 0; i < 32; i += 8)
        tt[ty + i][tx] = g_v[base + (size_t)(sb + ty + i) * HDIM + hb + tx];
    __syncthreads();
#pragma unroll
    for (int i = 0; i < 32; i += 8) {
        float v = tt[tx][ty + i];                       // s=sb+tx, hd=hb+ty+i
        __nv_bfloat16 h = __float2bfloat16_rn(v);
        __nv_bfloat16 l = __float2bfloat16_rn(v - __bfloat162float(h));
        size_t o = base + (size_t)(hb + ty + i) * SEQ + sb + tx;
        g_vth[o] = h;  g_vtl[o] = l;
    }
    (void)dummy;
}

// ---------------------------------------------------------------------------
// bf16 mma.sync GEMM, fused 3-pass split with register fragment reuse
// (unchanged from R9, passing at 259us QKV).
// ---------------------------------------------------------------------------
#define AS_STR 40
#define GM_TILE_B 10240                 // one 128x32 bf16 tile (stride 40)
#define GM_STAGE_B (4 * GM_TILE_B)      // Ah|Al|Bh|Bl
#define GM_SMEM (2 * GM_STAGE_B)        // 81920

template <int MODE>
__global__ __launch_bounds__(256, 2) void gemm_kernel(const float* __restrict__ bias,
                                                      float* __restrict__ Cout, int Ndim)
{
    extern __shared__ __align__(16) char gsm[];
    const uint32_t sS = smem_u32(gsm);

    const int tid = threadIdx.x;
    const int wid = tid >> 5, lane = tid & 31;
    const int wm = wid >> 2, wn = wid & 3;
    const int mBase = blockIdx.y * 128;
    const int nBase = blockIdx.x * 128;

    const __nv_bfloat16* Ah = (MODE == 0) ? g_xh : g_ah;
    const __nv_bfloat16* Al = (MODE == 0) ? g_xl : g_al;
    const __nv_bfloat16* Bh = (MODE == 0) ? g_wqh : g_wph;
    const __nv_bfloat16* Bl = (MODE == 0) ? g_wql : g_wpl;

    auto load_stage = [&](int kc, int st) {
        const int k0 = kc * 32;
        const __nv_bfloat16* base[4] = {
            Ah + (size_t)mBase * DMODEL + k0,
            Al + (size_t)mBase * DMODEL + k0,
            Bh + (size_t)nBase * DMODEL + k0,
            Bl + (size_t)nBase * DMODEL + k0 };
        const uint32_t stg = sS + st * GM_STAGE_B;
#pragma unroll
        for (int i = 0; i < 8; ++i) {
            int c = i * 256 + tid;
            int tile = c >> 9, w = c & 511, r = w >> 2, cb = w & 3;
            cp16(stg + tile * GM_TILE_B + (r * AS_STR + cb * 8) * 2,
                 base[tile] + (size_t)r * DMODEL + cb * 8);
        }
        cp_commit();
    };

    float acc[4][4][4];
#pragma unroll
    for (int mi = 0; mi < 4; mi++)
#pragma unroll
        for (int ni = 0; ni < 4; ni++)
#pragma unroll
            for (int e = 0; e < 4; e++) acc[mi][ni][e] = 0.f;

    const int a_row = wm * 64 + (lane & 15);
    const int a_koff = (lane >> 4) * 8;
    const int b_row = wn * 32 + ((lane >> 4) & 1) * 8 + (lane & 7);
    const int b_koff = ((lane >> 3) & 1) * 8;

    load_stage(0, 0);

    for (int cc = 0; cc < 32; ++cc) {
        const int st = cc & 1;
        cp_wait0();
        __syncthreads();             // single barrier per chunk
        if (cc + 1 < 32) load_stage(cc + 1, 1 - st);

        const uint32_t stg = sS + st * GM_STAGE_B;
#pragma unroll
        for (int ks = 0; ks < 2; ++ks) {
            uint32_t ah[4][4], al[4][4], bh[2][4], bl[2][4];
#pragma unroll
            for (int mi = 0; mi < 4; mi++)
                ldm_x4(ah[mi], stg + ((a_row + mi * 16) * AS_STR + ks * 16 + a_koff) * 2);
#pragma unroll
            for (int bt = 0; bt < 2; bt++)
                ldm_x4(bh[bt], stg + 2 * GM_TILE_B + ((b_row + bt * 16) * AS_STR + ks * 16 + b_koff) * 2);
#pragma unroll
            for (int mi = 0; mi < 4; mi++)
#pragma unroll
                for (int ni = 0; ni < 4; ni++)
                    mma_bf16(acc[mi][ni], ah[mi], bh[ni >> 1][(ni & 1) * 2],
                             bh[ni >> 1][(ni & 1) * 2 + 1]);
#pragma unroll
            for (int mi = 0; mi < 4; mi++)
                ldm_x4(al[mi], stg + GM_TILE_B + ((a_row + mi * 16) * AS_STR + ks * 16 + a_koff) * 2);
#pragma unroll
            for (int mi = 0; mi < 4; mi++)
#pragma unroll
                for (int ni = 0; ni < 4; ni++)
                    mma_bf16(acc[mi][ni], al[mi], bh[ni >> 1][(ni & 1) * 2],
                             bh[ni >> 1][(ni & 1) * 2 + 1]);
#pragma unroll
            for (int bt = 0; bt < 2; bt++)
                ldm_x4(bl[bt], stg + 3 * GM_TILE_B + ((b_row + bt * 16) * AS_STR + ks * 16 + b_koff) * 2);
#pragma unroll
            for (int mi = 0; mi < 4; mi++)
#pragma unroll
                for (int ni = 0; ni < 4; ni++)
                    mma_bf16(acc[mi][ni], ah[mi], bl[ni >> 1][(ni & 1) * 2],
                             bl[ni >> 1][(ni & 1) * 2 + 1]);
        }
    }

    const int gid = lane >> 2, tig = lane & 3;
#pragma unroll
    for (int mi = 0; mi < 4; mi++) {
#pragma unroll
        for (int half = 0; half < 2; half++) {
            const int m = mBase + wm * 64 + mi * 16 + gid + half * 8;
#pragma unroll
            for (int ni = 0; ni < 4; ni++) {
                const int n = nBase + wn * 32 + ni * 8 + tig * 2;
                float2 val;
                val.x = acc[mi][ni][half * 2 + 0] + bias[n];
                val.y = acc[mi][ni][half * 2 + 1] + bias[n + 1];
                if (MODE == 1) {
                    *(float2*)(Cout + (size_t)m * Ndim + n) = val;
                } else {
                    const int b = m >> 11, srow = m & 2047;
                    const int sec = n >> 10, dd = n & 1023;
                    const int hh = dd >> 6, hd = dd & 63;
                    const size_t idx = (((size_t)(b * NHEAD + hh)) * SEQ + srow) * HDIM + hd;
                    if (sec == 2) {
                        *(float2*)(g_v + idx) = val;
                    } else {
                        if (sec == 0) { val.x *= INV_SCALE; val.y *= INV_SCALE; } // fold 1/sqrt(hd) into Q
                        __nv_bfloat16 hx = __float2bfloat16_rn(val.x);
                        __nv_bfloat16 hy = __float2bfloat16_rn(val.y);
                        __nv_bfloat16 lx = __float2bfloat16_rn(val.x - __bfloat162float(hx));
                        __nv_bfloat16 ly = __float2bfloat16_rn(val.y - __bfloat162float(hy));
                        __nv_bfloat16* dh = (sec == 0) ? g_qh : g_kh;
                        __nv_bfloat16* dl = (sec == 0) ? g_ql : g_kl;
                        *(__nv_bfloat162*)(dh + idx) = __nv_bfloat162(hx, hy);
                        *(__nv_bfloat162*)(dl + idx) = __nv_bfloat162(lx, ly);
                    }
                }
            }
        }
    }
}

// ---------------------------------------------------------------------------
// Tensor-core flash attention, FA2-style in-register P:
// S accumulator fragments ARE the PV A-operand fragments (warp owns full rows)
// -> no P smem, 2 barriers/iter. K single-buffered, V double-buffered (92KB,
// 2 CTAs/SM). V_{t+1} prefetch at iter top; K_{t+1} prefetch right after QK.
// Q pre-scaled by 1/8 in the QKV epilogue.
// ---------------------------------------------------------------------------
#define FL_SMEM 92160

__global__ __launch_bounds__(256, 2) void flash_kernel(const float* __restrict__ mask)
{
    extern __shared__ __align__(16) char fsm[];
    const uint32_t S0 = smem_u32(fsm);
    const uint32_t sQh = S0,          sQl = S0 + 18432;
    const uint32_t sKh = S0 + 36864,  sKl = S0 + 46080;
    const uint32_t sV0 = S0 + 55296;   // [stage][h/l][64 hd][72 key], stage stride 18432

    const int qb = blockIdx.x * 128;
    const int h  = blockIdx.y, b = blockIdx.z;
    const int bh = b * NHEAD + h;
    const int tid = threadIdx.x, wid = tid >> 5, lane = tid & 31;

    const __nv_bfloat16* Qhg = g_qh + (size_t)bh * SEQ * HDIM;
    const __nv_bfloat16* Qlg = g_ql + (size_t)bh * SEQ * HDIM;
    const __nv_bfloat16* Khg = g_kh + (size_t)bh * SEQ * HDIM;
    const __nv_bfloat16* Klg = g_kl + (size_t)bh * SEQ * HDIM;
    const __nv_bfloat16* Vhg = g_vth + (size_t)bh * SEQ * HDIM;  // [hd][s]
    const __nv_bfloat16* Vlg = g_vtl + (size_t)bh * SEQ * HDIM;
    const float* maskb = mask + (size_t)b * SEQ;

    auto load_K = [&](int kb) {
        for (int i = tid; i < 512; i += 256) {
            int r = i >> 3, cb = i & 7;
            uint32_t so = (r * 72 + cb * 8) * 2;
            cp16(sKh + so, Khg + (size_t)(kb + r) * HDIM + cb * 8);
            cp16(sKl + so, Klg + (size_t)(kb + r) * HDIM + cb * 8);
        }
    };
    auto load_V = [&](int kb, int st) {
        const uint32_t vh = sV0 + st * 18432, vl = vh + 9216;
        for (int i = tid; i < 512; i += 256) {
            int r = i >> 3, cb = i & 7;
            uint32_t so = (r * 72 + cb * 8) * 2;
            cp16(vh + so, Vhg + (size_t)r * SEQ + kb + cb * 8);
            cp16(vl + so, Vlg + (size_t)r * SEQ + kb + cb * 8);
        }
    };

    // prologue: [Q + K_0] group, then [V_0 -> buf0] group
    for (int i = tid; i < 1024; i += 256) {
        int r = i >> 3, cb = i & 7;
        uint32_t so = (r * 72 + cb * 8) * 2;
        cp16(sQh + so, Qhg + (size_t)(qb + r) * HDIM + cb * 8);
        cp16(sQl + so, Qlg + (size_t)(qb + r) * HDIM + cb * 8);
    }
    load_K(0);
    cp_commit();
    load_V(0, 0);
    cp_commit();

    float m_s[2], l_s[2], oacc[8][4];
#pragma unroll
    for (int i = 0; i < 2; i++) { m_s[i] = -INFINITY; l_s[i] = 0.f; }
#pragma unroll
    for (int ni = 0; ni < 8; ni++)
#pragma unroll
        for (int e = 0; e < 4; e++) oacc[ni][e] = 0.f;

    const int a_base = lane & 15, a_koff = (lane >> 4) * 8;
    const int b_base = ((lane >> 4) & 1) * 8 + (lane & 7), b_koff = ((lane >> 3) & 1) * 8;
    const int g = lane >> 2, tig = lane & 3;
    const int arow_off = wid * 16 + a_base;

    for (int t = 0; t < 32; ++t) {
        const int st = t & 1;
        cp_wait0();                         // K_t and V_t complete
        __syncthreads();                    // data visible; prior PV done (protects V buf st^1)
        load_V(((t + 1) & 31) * 64, st ^ 1);
        cp_commit();                        // group A_t

        // ---- S = Q @ K^T, fragment-reuse split passes ----
        float sacc[8][4];
#pragma unroll
        for (int ni = 0; ni < 8; ni++)
#pragma unroll
            for (int e = 0; e < 4; e++) sacc[ni][e] = 0.f;

#pragma unroll
        for (int ks = 0; ks < 4; ++ks) {
            uint32_t aqh[4], aql[4], bf[4][4];
            ldm_x4(aqh, sQh + (arow_off * 72 + ks * 16 + a_koff) * 2);
#pragma unroll
            for (int bt = 0; bt < 4; bt++)
                ldm_x4(bf[bt], sKh + ((bt * 16 + b_base) * 72 + ks * 16 + b_koff) * 2);
#pragma unroll
            for (int ni = 0; ni < 8; ni++)
                mma_bf16(sacc[ni], aqh, bf[ni >> 1][(ni & 1) * 2], bf[ni >> 1][(ni & 1) * 2 + 1]);
            ldm_x4(aql, sQl + (arow_off * 72 + ks * 16 + a_koff) * 2);
#pragma unroll
            for (int ni = 0; ni < 8; ni++)
                mma_bf16(sacc[ni], aql, bf[ni >> 1][(ni & 1) * 2], bf[ni >> 1][(ni & 1) * 2 + 1]);
#pragma unroll
            for (int bt = 0; bt < 4; bt++)
                ldm_x4(bf[bt], sKl + ((bt * 16 + b_base) * 72 + ks * 16 + b_koff) * 2);
#pragma unroll
            for (int ni = 0; ni < 8; ni++)
                mma_bf16(sacc[ni], aqh, bf[ni >> 1][(ni & 1) * 2], bf[ni >> 1][(ni & 1) * 2 + 1]);
        }

        __syncthreads();                    // all warps done reading K_t
        load_K(((t + 1) & 31) * 64);        // prefetch K_{t+1} during softmax+PV
        cp_commit();                        // group B_t

        // ---- online softmax; pack P hi/lo bf16 IN PLACE into sacc ----
        // slot layout per ni: [0]=h(pair rows g), [1]=l(rows g), [2]=h(rows g+8), [3]=l(rows g+8)
        const int kbase = t * 64 + tig * 2;
#pragma unroll
        for (int half = 0; half < 2; ++half) {
            float vmax = -INFINITY;
#pragma unroll
            for (int ni = 0; ni < 8; ++ni) {
                float v0 = sacc[ni][half * 2 + 0] + maskb[kbase + ni * 8];
                float v1 = sacc[ni][half * 2 + 1] + maskb[kbase + ni * 8 + 1];
                sacc[ni][half * 2 + 0] = v0; sacc[ni][half * 2 + 1] = v1;
                vmax = fmaxf(vmax, fmaxf(v0, v1));
            }
            vmax = fmaxf(vmax, __shfl_xor_sync(0xffffffffu, vmax, 1));
            vmax = fmaxf(vmax, __shfl_xor_sync(0xffffffffu, vmax, 2));
            float mnew = fmaxf(m_s[half], vmax);
            float alpha = __expf(m_s[half] - mnew);
            m_s[half] = mnew;
            float sum = 0.f;
#pragma unroll
            for (int ni = 0; ni < 8; ++ni) {
                float p0 = __expf(sacc[ni][half * 2 + 0] - mnew);
                float p1 = __expf(sacc[ni][half * 2 + 1] - mnew);
                sum += p0 + p1;
                __nv_bfloat16 h0 = __float2bfloat16_rn(p0), h1 = __float2bfloat16_rn(p1);
                __nv_bfloat16 q0 = __float2bfloat16_rn(p0 - __bfloat162float(h0));
                __nv_bfloat16 q1 = __float2bfloat16_rn(p1 - __bfloat162float(h1));
                uint32_t uh = ((uint32_t)__bfloat16_as_ushort(h1) << 16) | (uint32_t)__bfloat16_as_ushort(h0);
                uint32_t ul = ((uint32_t)__bfloat16_as_ushort(q1) << 16) | (uint32_t)__bfloat16_as_ushort(q0);
                sacc[ni][half * 2 + 0] = __uint_as_float(uh);
                sacc[ni][half * 2 + 1] = __uint_as_float(ul);
            }
            sum += __shfl_xor_sync(0xffffffffu, sum, 1);
            sum += __shfl_xor_sync(0xffffffffu, sum, 2);
            l_s[half] = l_s[half] * alpha + sum;
#pragma unroll
            for (int ni = 0; ni < 8; ++ni) {
                oacc[ni][half * 2 + 0] *= alpha;
                oacc[ni][half * 2 + 1] *= alpha;
            }
        }

        // ---- O += P @ V, P A-fragments straight from sacc registers ----
        const uint32_t vh = sV0 + st * 18432, vl = vh + 9216;
#pragma unroll
        for (int ks = 0; ks < 4; ++ks) {
            uint32_t ph[4] = { __float_as_uint(sacc[2 * ks][0]), __float_as_uint(sacc[2 * ks][2]),
                               __float_as_uint(sacc[2 * ks + 1][0]), __float_as_uint(sacc[2 * ks + 1][2]) };
            uint32_t pl[4] = { __float_as_uint(sacc[2 * ks][1]), __float_as_uint(sacc[2 * ks][3]),
                               __float_as_uint(sacc[2 * ks + 1][1]), __float_as_uint(sacc[2 * ks + 1][3]) };
            uint32_t bf[4][4];
#pragma unroll
            for (int bt = 0; bt < 4; bt++)
                ldm_x4(bf[bt], vh + ((bt * 16 + b_base) * 72 + ks * 16 + b_koff) * 2);
#pragma unroll
            for (int ni = 0; ni < 8; ni++)
                mma_bf16(oacc[ni], ph, bf[ni >> 1][(ni & 1) * 2], bf[ni >> 1][(ni & 1) * 2 + 1]);
#pragma unroll
            for (int ni = 0; ni < 8; ni++)
                mma_bf16(oacc[ni], pl, bf[ni >> 1][(ni & 1) * 2], bf[ni >> 1][(ni & 1) * 2 + 1]);
#pragma unroll
            for (int bt = 0; bt < 4; bt++)
                ldm_x4(bf[bt], vl + ((bt * 16 + b_base) * 72 + ks * 16 + b_koff) * 2);
#pragma unroll
            for (int ni = 0; ni < 8; ni++)
                mma_bf16(oacc[ni], ph, bf[ni >> 1][(ni & 1) * 2], bf[ni >> 1][(ni & 1) * 2 + 1]);
        }
    }

    // ---- epilogue: O / l -> g_ah/g_al (pre-split for proj GEMM) ----
#pragma unroll
    for (int half = 0; half < 2; ++half) {
        const float inv = 1.f / l_s[half];
        const int srow = qb + wid * 16 + g + half * 8;
        const size_t rowoff = ((size_t)b * SEQ + srow) * DMODEL + h * HDIM + tig * 2;
#pragma unroll
        for (int ni = 0; ni < 8; ++ni) {
            float v0 = oacc[ni][half * 2 + 0] * inv;
            float v1 = oacc[ni][half * 2 + 1] * inv;
            __nv_bfloat16 h0 = __float2bfloat16_rn(v0), h1 = __float2bfloat16_rn(v1);
            __nv_bfloat16 l0 = __float2bfloat16_rn(v0 - __bfloat162float(h0));
            __nv_bfloat16 l1 = __float2bfloat16_rn(v1 - __bfloat162float(h1));
            *(__nv_bfloat162*)(g_ah + rowoff + ni * 8) = __nv_bfloat162(h0, h1);
            *(__nv_bfloat162*)(g_al + rowoff + ni * 8) = __nv_bfloat162(l0, l1);
        }
    }
}

// ---------------------------------------------------------------------------
extern "C" void kernel_launch(void* const* d_in, const int* in_sizes, int n_in,
                              void* d_out, int out_size)
{
    (void)in_sizes; (void)n_in; (void)out_size;
    const float* x       = (const float*)d_in[0];
    const float* mask    = (const float*)d_in[1];
    const float* w_attn  = (const float*)d_in[2];
    const float* b_attn  = (const float*)d_in[3];
    const float* w_proj  = (const float*)d_in[4];
    const float* b_proj  = (const float*)d_in[5];
    float* out = (float*)d_out;

    cudaFuncSetAttribute(flash_kernel, cudaFuncAttributeMaxDynamicSharedMemorySize, FL_SMEM);
    cudaFuncSetAttribute(gemm_kernel<0>, cudaFuncAttributeMaxDynamicSharedMemorySize, GM_SMEM);
    cudaFuncSetAttribute(gemm_kernel<1>, cudaFuncAttributeMaxDynamicSharedMemorySize, GM_SMEM);

    __nv_bfloat16 *xh, *xl, *wqh, *wql, *wph, *wpl;
    cudaGetSymbolAddress((void**)&xh,  g_xh);  cudaGetSymbolAddress((void**)&xl,  g_xl);
    cudaGetSymbolAddress((void**)&wqh, g_wqh); cudaGetSymbolAddress((void**)&wql, g_wql);
    cudaGetSymbolAddress((void**)&wph, g_wph); cudaGetSymbolAddress((void**)&wpl, g_wpl);

    // 1) input split + weight transposes
    {
        int n4 = (M_ROWS * DMODEL) / 4;
        split_kernel<<<(n4 + 255) / 256, 256>>>(x, xh, xl, n4);
        transpose_split_kernel<<<dim3(N_QKV / 32, DMODEL / 32), dim3(32, 8)>>>(
            w_attn, wqh, wql, DMODEL, N_QKV);
        transpose_split_kernel<<<dim3(DMODEL / 32, DMODEL / 32), dim3(32, 8)>>>(
            w_proj, wph, wpl, DMODEL, DMODEL);
    }
    // 2) QKV GEMM -> q(*1/8)/k bf16 hi/lo + v fp32
    gemm_kernel<0><<<dim3(N_QKV / 128, M_ROWS / 128), 256, GM_SMEM>>>(b_attn, nullptr, N_QKV);
    // 3) V transpose+split -> [b,h,hd,s] bf16 hi/lo
    transpose_split_v<<<dim3(SEQ / 32, HDIM / 32, BATCH * NHEAD), dim3(32, 8)>>>(0);
    // 4) tensor-core flash attention -> g_ah/g_al (pre-split)
    flash_kernel<<<dim3(SEQ / 128, NHEAD, BATCH), 256, FL_SMEM>>>(mask);
    // 5) proj GEMM -> out
    gemm_kernel<1><<<dim3(DMODEL / 128, M_ROWS / 128), 256, GM_SMEM>>>(b_proj, out, DMODEL);
}

// round 11
// speedup vs baseline: 3.6917x; 1.0334x over previous
#include <cuda_runtime.h>
#include <cuda_bf16.h>
#include <math.h>
#include <stdint.h>

// Problem constants
#define BATCH 2
#define SEQ   2048
#define DMODEL 1024
#define NHEAD 16
#define HDIM  64
#define M_ROWS (BATCH * SEQ)          // 4096
#define N_QKV  (3 * DMODEL)           // 3072
#define INV_SCALE 0.125f
#define QK_PRESCALE 0.18033688011f    // (1/8) * log2(e): Q prescale -> exp2-domain scores
#define LOG2E_F 1.4426950408889634f

// ---------------------------------------------------------------------------
// Scratch buffers
// ---------------------------------------------------------------------------
__device__ __align__(256) float g_v[BATCH * NHEAD * SEQ * HDIM];
__device__ __align__(256) __nv_bfloat16 g_xh[M_ROWS * DMODEL], g_xl[M_ROWS * DMODEL];
__device__ __align__(256) __nv_bfloat16 g_ah[M_ROWS * DMODEL], g_al[M_ROWS * DMODEL];
__device__ __align__(256) __nv_bfloat16 g_wqh[N_QKV * DMODEL], g_wql[N_QKV * DMODEL];
__device__ __align__(256) __nv_bfloat16 g_wph[DMODEL * DMODEL], g_wpl[DMODEL * DMODEL];
__device__ __align__(256) __nv_bfloat16 g_qh[BATCH * NHEAD * SEQ * HDIM], g_ql[BATCH * NHEAD * SEQ * HDIM];
__device__ __align__(256) __nv_bfloat16 g_kh[BATCH * NHEAD * SEQ * HDIM], g_kl[BATCH * NHEAD * SEQ * HDIM];
__device__ __align__(256) __nv_bfloat16 g_vth[BATCH * NHEAD * SEQ * HDIM], g_vtl[BATCH * NHEAD * SEQ * HDIM];

// ---------------------------------------------------------------------------
// PTX helpers (sm_80-era: valid on compute_100 base target)
// ---------------------------------------------------------------------------
__device__ __forceinline__ uint32_t smem_u32(const void* p) {
    uint32_t a;
    asm("{ .reg .u64 t; cvta.to.shared.u64 t, %1; cvt.u32.u64 %0, t; }" : "=r"(a) : "l"(p));
    return a;
}
__device__ __forceinline__ void cp16(uint32_t saddr, const void* gaddr) {
    asm volatile("cp.async.cg.shared.global [%0], [%1], 16;" :: "r"(saddr), "l"(gaddr) : "memory");
}
__device__ __forceinline__ void cp_commit() { asm volatile("cp.async.commit_group;" ::: "memory"); }
__device__ __forceinline__ void cp_wait0()  { asm volatile("cp.async.wait_group 0;" ::: "memory"); }

__device__ __forceinline__ void ldm_x4(uint32_t* r, uint32_t addr) {
    asm volatile("ldmatrix.sync.aligned.m8n8.x4.shared.b16 {%0,%1,%2,%3}, [%4];"
        : "=r"(r[0]), "=r"(r[1]), "=r"(r[2]), "=r"(r[3]) : "r"(addr));
}
__device__ __forceinline__ void mma_bf16(float* c, const uint32_t* a, uint32_t b0, uint32_t b1) {
    asm volatile("mma.sync.aligned.m16n8k16.row.col.f32.bf16.bf16.f32 "
        "{%0,%1,%2,%3}, {%4,%5,%6,%7}, {%8,%9}, {%0,%1,%2,%3};"
        : "+f"(c[0]), "+f"(c[1]), "+f"(c[2]), "+f"(c[3])
        : "r"(a[0]), "r"(a[1]), "r"(a[2]), "r"(a[3]), "r"(b0), "r"(b1));
}
__device__ __forceinline__ float ex2(float x) {
    float y; asm("ex2.approx.f32 %0, %1;" : "=f"(y) : "f"(x)); return y;
}

// ---------------------------------------------------------------------------
// fp32 -> (hi, lo) bf16 split, vectorized x4
// ---------------------------------------------------------------------------
__global__ void split_kernel(const float* __restrict__ src,
                             __nv_bfloat16* __restrict__ hi,
                             __nv_bfloat16* __restrict__ lo, int n4)
{
    int i = blockIdx.x * blockDim.x + threadIdx.x;
    if (i >= n4) return;
    float4 v = ((const float4*)src)[i];
    __nv_bfloat16 h0 = __float2bfloat16_rn(v.x), h1 = __float2bfloat16_rn(v.y);
    __nv_bfloat16 h2 = __float2bfloat16_rn(v.z), h3 = __float2bfloat16_rn(v.w);
    __nv_bfloat16 l0 = __float2bfloat16_rn(v.x - __bfloat162float(h0));
    __nv_bfloat16 l1 = __float2bfloat16_rn(v.y - __bfloat162float(h1));
    __nv_bfloat16 l2 = __float2bfloat16_rn(v.z - __bfloat162float(h2));
    __nv_bfloat16 l3 = __float2bfloat16_rn(v.w - __bfloat162float(h3));
    ((__nv_bfloat162*)hi)[i * 2 + 0] = __nv_bfloat162(h0, h1);
    ((__nv_bfloat162*)hi)[i * 2 + 1] = __nv_bfloat162(h2, h3);
    ((__nv_bfloat162*)lo)[i * 2 + 0] = __nv_bfloat162(l0, l1);
    ((__nv_bfloat162*)lo)[i * 2 + 1] = __nv_bfloat162(l2, l3);
}

// ---------------------------------------------------------------------------
// W[K][N] fp32 -> Th/Tl[N][K] bf16 (transpose + split), 32x32 tiles
// ---------------------------------------------------------------------------
__global__ void transpose_split_kernel(const float* __restrict__ W,
                                       __nv_bfloat16* __restrict__ Th,
                                       __nv_bfloat16* __restrict__ Tl,
                                       int K, int N)
{
    __shared__ float t[32][33];
    int nb = blockIdx.x * 32, kb = blockIdx.y * 32;
    int tx = threadIdx.x, ty = threadIdx.y;   // 32 x 8
#pragma unroll
    for (int i = 0; i < 32; i += 8)
        t[ty + i][tx] = W[(size_t)(kb + ty + i) * N + nb + tx];
    __syncthreads();
#pragma unroll
    for (int i = 0; i < 32; i += 8) {
        float v = t[tx][ty + i];
        __nv_bfloat16 h = __float2bfloat16_rn(v);
        __nv_bfloat16 l = __float2bfloat16_rn(v - __bfloat162float(h));
        size_t o = (size_t)(nb + ty + i) * K + kb + tx;
        Th[o] = h;  Tl[o] = l;
    }
}

// ---------------------------------------------------------------------------
// V [b,h,s,hd] fp32 -> V^T [b,h,hd,s] bf16 hi/lo
// ---------------------------------------------------------------------------
__global__ void transpose_split_v(int dummy)
{
    __shared__ float tt[32][33];
    const int sb = blockIdx.x * 32, hb = blockIdx.y * 32;
    const size_t base = (size_t)blockIdx.z * SEQ * HDIM;
    const int tx = threadIdx.x, ty = threadIdx.y;   // 32 x 8
#pragma unroll
    for (int i = 0; i < 32; i += 8)
        tt[ty + i][tx] = g_v[base + (size_t)(sb + ty + i) * HDIM + hb + tx];
    __syncthreads();
#pragma unroll
    for (int i = 0; i < 32; i += 8) {
        float v = tt[tx][ty + i];                       // s=sb+tx, hd=hb+ty+i
        __nv_bfloat16 h = __float2bfloat16_rn(v);
        __nv_bfloat16 l = __float2bfloat16_rn(v - __bfloat162float(h));
        size_t o = base + (size_t)(hb + ty + i) * SEQ + sb + tx;
        g_vth[o] = h;  g_vtl[o] = l;
    }
    (void)dummy;
}

// ---------------------------------------------------------------------------
// bf16 mma.sync GEMM, fused 3-pass split with register fragment reuse
// (unchanged engine; MODE 0 Q prescale now QK_PRESCALE for exp2-domain flash).
// ---------------------------------------------------------------------------
#define AS_STR 40
#define GM_TILE_B 10240                 // one 128x32 bf16 tile (stride 40)
#define GM_STAGE_B (4 * GM_TILE_B)      // Ah|Al|Bh|Bl
#define GM_SMEM (2 * GM_STAGE_B)        // 81920

template <int MODE>
__global__ __launch_bounds__(256, 2) void gemm_kernel(const float* __restrict__ bias,
                                                      float* __restrict__ Cout, int Ndim)
{
    extern __shared__ __align__(16) char gsm[];
    const uint32_t sS = smem_u32(gsm);

    const int tid = threadIdx.x;
    const int wid = tid >> 5, lane = tid & 31;
    const int wm = wid >> 2, wn = wid & 3;
    const int mBase = blockIdx.y * 128;
    const int nBase = blockIdx.x * 128;

    const __nv_bfloat16* Ah = (MODE == 0) ? g_xh : g_ah;
    const __nv_bfloat16* Al = (MODE == 0) ? g_xl : g_al;
    const __nv_bfloat16* Bh = (MODE == 0) ? g_wqh : g_wph;
    const __nv_bfloat16* Bl = (MODE == 0) ? g_wql : g_wpl;

    auto load_stage = [&](int kc, int st) {
        const int k0 = kc * 32;
        const __nv_bfloat16* base[4] = {
            Ah + (size_t)mBase * DMODEL + k0,
            Al + (size_t)mBase * DMODEL + k0,
            Bh + (size_t)nBase * DMODEL + k0,
            Bl + (size_t)nBase * DMODEL + k0 };
        const uint32_t stg = sS + st * GM_STAGE_B;
#pragma unroll
        for (int i = 0; i < 8; ++i) {
            int c = i * 256 + tid;
            int tile = c >> 9, w = c & 511, r = w >> 2, cb = w & 3;
            cp16(stg + tile * GM_TILE_B + (r * AS_STR + cb * 8) * 2,
                 base[tile] + (size_t)r * DMODEL + cb * 8);
        }
        cp_commit();
    };

    float acc[4][4][4];
#pragma unroll
    for (int mi = 0; mi < 4; mi++)
#pragma unroll
        for (int ni = 0; ni < 4; ni++)
#pragma unroll
            for (int e = 0; e < 4; e++) acc[mi][ni][e] = 0.f;

    const int a_row = wm * 64 + (lane & 15);
    const int a_koff = (lane >> 4) * 8;
    const int b_row = wn * 32 + ((lane >> 4) & 1) * 8 + (lane & 7);
    const int b_koff = ((lane >> 3) & 1) * 8;

    load_stage(0, 0);

    for (int cc = 0; cc < 32; ++cc) {
        const int st = cc & 1;
        cp_wait0();
        __syncthreads();             // single barrier per chunk
        if (cc + 1 < 32) load_stage(cc + 1, 1 - st);

        const uint32_t stg = sS + st * GM_STAGE_B;
#pragma unroll
        for (int ks = 0; ks < 2; ++ks) {
            uint32_t ah[4][4], al[4][4], bh[2][4], bl[2][4];
#pragma unroll
            for (int mi = 0; mi < 4; mi++)
                ldm_x4(ah[mi], stg + ((a_row + mi * 16) * AS_STR + ks * 16 + a_koff) * 2);
#pragma unroll
            for (int bt = 0; bt < 2; bt++)
                ldm_x4(bh[bt], stg + 2 * GM_TILE_B + ((b_row + bt * 16) * AS_STR + ks * 16 + b_koff) * 2);
#pragma unroll
            for (int mi = 0; mi < 4; mi++)
#pragma unroll
                for (int ni = 0; ni < 4; ni++)
                    mma_bf16(acc[mi][ni], ah[mi], bh[ni >> 1][(ni & 1) * 2],
                             bh[ni >> 1][(ni & 1) * 2 + 1]);
#pragma unroll
            for (int mi = 0; mi < 4; mi++)
                ldm_x4(al[mi], stg + GM_TILE_B + ((a_row + mi * 16) * AS_STR + ks * 16 + a_koff) * 2);
#pragma unroll
            for (int mi = 0; mi < 4; mi++)
#pragma unroll
                for (int ni = 0; ni < 4; ni++)
                    mma_bf16(acc[mi][ni], al[mi], bh[ni >> 1][(ni & 1) * 2],
                             bh[ni >> 1][(ni & 1) * 2 + 1]);
#pragma unroll
            for (int bt = 0; bt < 2; bt++)
                ldm_x4(bl[bt], stg + 3 * GM_TILE_B + ((b_row + bt * 16) * AS_STR + ks * 16 + b_koff) * 2);
#pragma unroll
            for (int mi = 0; mi < 4; mi++)
#pragma unroll
                for (int ni = 0; ni < 4; ni++)
                    mma_bf16(acc[mi][ni], ah[mi], bl[ni >> 1][(ni & 1) * 2],
                             bl[ni >> 1][(ni & 1) * 2 + 1]);
        }
    }

    const int gid = lane >> 2, tig = lane & 3;
#pragma unroll
    for (int mi = 0; mi < 4; mi++) {
#pragma unroll
        for (int half = 0; half < 2; half++) {
            const int m = mBase + wm * 64 + mi * 16 + gid + half * 8;
#pragma unroll
            for (int ni = 0; ni < 4; ni++) {
                const int n = nBase + wn * 32 + ni * 8 + tig * 2;
                float2 val;
                val.x = acc[mi][ni][half * 2 + 0] + bias[n];
                val.y = acc[mi][ni][half * 2 + 1] + bias[n + 1];
                if (MODE == 1) {
                    *(float2*)(Cout + (size_t)m * Ndim + n) = val;
                } else {
                    const int b = m >> 11, srow = m & 2047;
                    const int sec = n >> 10, dd = n & 1023;
                    const int hh = dd >> 6, hd = dd & 63;
                    const size_t idx = (((size_t)(b * NHEAD + hh)) * SEQ + srow) * HDIM + hd;
                    if (sec == 2) {
                        *(float2*)(g_v + idx) = val;
                    } else {
                        if (sec == 0) { val.x *= QK_PRESCALE; val.y *= QK_PRESCALE; }
                        __nv_bfloat16 hx = __float2bfloat16_rn(val.x);
                        __nv_bfloat16 hy = __float2bfloat16_rn(val.y);
                        __nv_bfloat16 lx = __float2bfloat16_rn(val.x - __bfloat162float(hx));
                        __nv_bfloat16 ly = __float2bfloat16_rn(val.y - __bfloat162float(hy));
                        __nv_bfloat16* dh = (sec == 0) ? g_qh : g_kh;
                        __nv_bfloat16* dl = (sec == 0) ? g_ql : g_kl;
                        *(__nv_bfloat162*)(dh + idx) = __nv_bfloat162(hx, hy);
                        *(__nv_bfloat162*)(dl + idx) = __nv_bfloat162(lx, ly);
                    }
                }
            }
        }
    }
}

// ---------------------------------------------------------------------------
// Tensor-core flash attention, FA2-style in-register P + exp2-domain softmax.
// K AND V double-buffered (110.6KB, 2 CTAs/SM) -> ONE barrier per iter; warps
// free-run so softmax of one warp overlaps mma of another.
// Q pre-scaled by (1/8)*log2e; mask scaled by log2e at read; ex2.approx.
// ---------------------------------------------------------------------------
#define FL_SMEM 110592

__global__ __launch_bounds__(256, 2) void flash_kernel(const float* __restrict__ mask)
{
    extern __shared__ __align__(16) char fsm[];
    const uint32_t S0 = smem_u32(fsm);
    const uint32_t sQh = S0, sQl = S0 + 18432;
    const uint32_t sK  = S0 + 36864;   // [st][h|l], stage stride 18432, l at +9216
    const uint32_t sV  = S0 + 73728;   // [st][h|l], stage stride 18432, l at +9216

    const int qb = blockIdx.x * 128;
    const int h  = blockIdx.y, b = blockIdx.z;
    const int bh = b * NHEAD + h;
    const int tid = threadIdx.x, wid = tid >> 5, lane = tid & 31;

    const __nv_bfloat16* Qhg = g_qh + (size_t)bh * SEQ * HDIM;
    const __nv_bfloat16* Qlg = g_ql + (size_t)bh * SEQ * HDIM;
    const __nv_bfloat16* Khg = g_kh + (size_t)bh * SEQ * HDIM;
    const __nv_bfloat16* Klg = g_kl + (size_t)bh * SEQ * HDIM;
    const __nv_bfloat16* Vhg = g_vth + (size_t)bh * SEQ * HDIM;  // [hd][s]
    const __nv_bfloat16* Vlg = g_vtl + (size_t)bh * SEQ * HDIM;
    const float* maskb = mask + (size_t)b * SEQ;

    auto load_KV = [&](int kb, int st) {
        const uint32_t kh = sK + st * 18432, kl = kh + 9216;
        const uint32_t vh = sV + st * 18432, vl = vh + 9216;
        for (int i = tid; i < 512; i += 256) {
            int r = i >> 3, cb = i & 7;
            uint32_t so = (r * 72 + cb * 8) * 2;
            cp16(kh + so, Khg + (size_t)(kb + r) * HDIM + cb * 8);
            cp16(kl + so, Klg + (size_t)(kb + r) * HDIM + cb * 8);
            cp16(vh + so, Vhg + (size_t)r * SEQ + kb + cb * 8);
            cp16(vl + so, Vlg + (size_t)r * SEQ + kb + cb * 8);
        }
    };

    // prologue: Q + K0 + V0 as one commit group
    for (int i = tid; i < 1024; i += 256) {
        int r = i >> 3, cb = i & 7;
        uint32_t so = (r * 72 + cb * 8) * 2;
        cp16(sQh + so, Qhg + (size_t)(qb + r) * HDIM + cb * 8);
        cp16(sQl + so, Qlg + (size_t)(qb + r) * HDIM + cb * 8);
    }
    load_KV(0, 0);
    cp_commit();

    float m_s[2], l_s[2], oacc[8][4];
#pragma unroll
    for (int i = 0; i < 2; i++) { m_s[i] = -INFINITY; l_s[i] = 0.f; }
#pragma unroll
    for (int ni = 0; ni < 8; ni++)
#pragma unroll
        for (int e = 0; e < 4; e++) oacc[ni][e] = 0.f;

    const int a_base = lane & 15, a_koff = (lane >> 4) * 8;
    const int b_base = ((lane >> 4) & 1) * 8 + (lane & 7), b_koff = ((lane >> 3) & 1) * 8;
    const int g = lane >> 2, tig = lane & 3;
    const int arow_off = wid * 16 + a_base;

    for (int t = 0; t < 32; ++t) {
        const int st = t & 1;
        cp_wait0();                         // K_t, V_t (and Q on t=0) complete
        __syncthreads();                    // all warps done with stage st^1 (iter t-1)
        if (t + 1 < 32) { load_KV((t + 1) * 64, st ^ 1); cp_commit(); }

        const uint32_t kh = sK + st * 18432, kl = kh + 9216;
        const uint32_t vh = sV + st * 18432, vl = vh + 9216;

        // ---- S = Q @ K^T, fragment-reuse split passes ----
        float sacc[8][4];
#pragma unroll
        for (int ni = 0; ni < 8; ni++)
#pragma unroll
            for (int e = 0; e < 4; e++) sacc[ni][e] = 0.f;

#pragma unroll
        for (int ks = 0; ks < 4; ++ks) {
            uint32_t aqh[4], aql[4], bf[4][4];
            ldm_x4(aqh, sQh + (arow_off * 72 + ks * 16 + a_koff) * 2);
#pragma unroll
            for (int bt = 0; bt < 4; bt++)
                ldm_x4(bf[bt], kh + ((bt * 16 + b_base) * 72 + ks * 16 + b_koff) * 2);
#pragma unroll
            for (int ni = 0; ni < 8; ni++)
                mma_bf16(sacc[ni], aqh, bf[ni >> 1][(ni & 1) * 2], bf[ni >> 1][(ni & 1) * 2 + 1]);
            ldm_x4(aql, sQl + (arow_off * 72 + ks * 16 + a_koff) * 2);
#pragma unroll
            for (int ni = 0; ni < 8; ni++)
                mma_bf16(sacc[ni], aql, bf[ni >> 1][(ni & 1) * 2], bf[ni >> 1][(ni & 1) * 2 + 1]);
#pragma unroll
            for (int bt = 0; bt < 4; bt++)
                ldm_x4(bf[bt], kl + ((bt * 16 + b_base) * 72 + ks * 16 + b_koff) * 2);
#pragma unroll
            for (int ni = 0; ni < 8; ni++)
                mma_bf16(sacc[ni], aqh, bf[ni >> 1][(ni & 1) * 2], bf[ni >> 1][(ni & 1) * 2 + 1]);
        }

        // ---- online softmax in exp2 domain; pack P hi/lo IN PLACE into sacc ----
        const int kbase = t * 64 + tig * 2;
#pragma unroll
        for (int half = 0; half < 2; ++half) {
            float vmax = -INFINITY;
#pragma unroll
            for (int ni = 0; ni < 8; ++ni) {
                float v0 = fmaf(maskb[kbase + ni * 8],     LOG2E_F, sacc[ni][half * 2 + 0]);
                float v1 = fmaf(maskb[kbase + ni * 8 + 1], LOG2E_F, sacc[ni][half * 2 + 1]);
                sacc[ni][half * 2 + 0] = v0; sacc[ni][half * 2 + 1] = v1;
                vmax = fmaxf(vmax, fmaxf(v0, v1));
            }
            vmax = fmaxf(vmax, __shfl_xor_sync(0xffffffffu, vmax, 1));
            vmax = fmaxf(vmax, __shfl_xor_sync(0xffffffffu, vmax, 2));
            float mnew = fmaxf(m_s[half], vmax);
            float alpha = ex2(m_s[half] - mnew);
            m_s[half] = mnew;
            float sum = 0.f;
#pragma unroll
            for (int ni = 0; ni < 8; ++ni) {
                float p0 = ex2(sacc[ni][half * 2 + 0] - mnew);
                float p1 = ex2(sacc[ni][half * 2 + 1] - mnew);
                sum += p0 + p1;
                __nv_bfloat162 hh = __float22bfloat162_rn(make_float2(p0, p1));
                uint32_t uh = *(uint32_t*)&hh;
                float f0 = __uint_as_float(uh << 16);
                float f1 = __uint_as_float(uh & 0xFFFF0000u);
                __nv_bfloat162 ll = __float22bfloat162_rn(make_float2(p0 - f0, p1 - f1));
                uint32_t ul = *(uint32_t*)&ll;
                sacc[ni][half * 2 + 0] = __uint_as_float(uh);
                sacc[ni][half * 2 + 1] = __uint_as_float(ul);
            }
            sum += __shfl_xor_sync(0xffffffffu, sum, 1);
            sum += __shfl_xor_sync(0xffffffffu, sum, 2);
            l_s[half] = l_s[half] * alpha + sum;
#pragma unroll
            for (int ni = 0; ni < 8; ++ni) {
                oacc[ni][half * 2 + 0] *= alpha;
                oacc[ni][half * 2 + 1] *= alpha;
            }
        }

        // ---- O += P @ V, P A-fragments straight from sacc registers ----
#pragma unroll
        for (int ks = 0; ks < 4; ++ks) {
            uint32_t ph[4] = { __float_as_uint(sacc[2 * ks][0]), __float_as_uint(sacc[2 * ks][2]),
                               __float_as_uint(sacc[2 * ks + 1][0]), __float_as_uint(sacc[2 * ks + 1][2]) };
            uint32_t pl[4] = { __float_as_uint(sacc[2 * ks][1]), __float_as_uint(sacc[2 * ks][3]),
                               __float_as_uint(sacc[2 * ks + 1][1]), __float_as_uint(sacc[2 * ks + 1][3]) };
            uint32_t bf[4][4];
#pragma unroll
            for (int bt = 0; bt < 4; bt++)
                ldm_x4(bf[bt], vh + ((bt * 16 + b_base) * 72 + ks * 16 + b_koff) * 2);
#pragma unroll
            for (int ni = 0; ni < 8; ni++)
                mma_bf16(oacc[ni], ph, bf[ni >> 1][(ni & 1) * 2], bf[ni >> 1][(ni & 1) * 2 + 1]);
#pragma unroll
            for (int ni = 0; ni < 8; ni++)
                mma_bf16(oacc[ni], pl, bf[ni >> 1][(ni & 1) * 2], bf[ni >> 1][(ni & 1) * 2 + 1]);
#pragma unroll
            for (int bt = 0; bt < 4; bt++)
                ldm_x4(bf[bt], vl + ((bt * 16 + b_base) * 72 + ks * 16 + b_koff) * 2);
#pragma unroll
            for (int ni = 0; ni < 8; ni++)
                mma_bf16(oacc[ni], ph, bf[ni >> 1][(ni & 1) * 2], bf[ni >> 1][(ni & 1) * 2 + 1]);
        }
    }

    // ---- epilogue: O / l -> g_ah/g_al (pre-split for proj GEMM) ----
#pragma unroll
    for (int half = 0; half < 2; ++half) {
        const float inv = 1.f / l_s[half];
        const int srow = qb + wid * 16 + g + half * 8;
        const size_t rowoff = ((size_t)b * SEQ + srow) * DMODEL + h * HDIM + tig * 2;
#pragma unroll
        for (int ni = 0; ni < 8; ++ni) {
            float v0 = oacc[ni][half * 2 + 0] * inv;
            float v1 = oacc[ni][half * 2 + 1] * inv;
            __nv_bfloat162 hh = __float22bfloat162_rn(make_float2(v0, v1));
            uint32_t uh = *(uint32_t*)&hh;
            float f0 = __uint_as_float(uh << 16);
            float f1 = __uint_as_float(uh & 0xFFFF0000u);
            __nv_bfloat162 ll = __float22bfloat162_rn(make_float2(v0 - f0, v1 - f1));
            *(__nv_bfloat162*)(g_ah + rowoff + ni * 8) = hh;
            *(__nv_bfloat162*)(g_al + rowoff + ni * 8) = ll;
        }
    }
}

// ---------------------------------------------------------------------------
extern "C" void kernel_launch(void* const* d_in, const int* in_sizes, int n_in,
                              void* d_out, int out_size)
{
    (void)in_sizes; (void)n_in; (void)out_size;
    const float* x       = (const float*)d_in[0];
    const float* mask    = (const float*)d_in[1];
    const float* w_attn  = (const float*)d_in[2];
    const float* b_attn  = (const float*)d_in[3];
    const float* w_proj  = (const float*)d_in[4];
    const float* b_proj  = (const float*)d_in[5];
    float* out = (float*)d_out;

    cudaFuncSetAttribute(flash_kernel, cudaFuncAttributeMaxDynamicSharedMemorySize, FL_SMEM);
    cudaFuncSetAttribute(gemm_kernel<0>, cudaFuncAttributeMaxDynamicSharedMemorySize, GM_SMEM);
    cudaFuncSetAttribute(gemm_kernel<1>, cudaFuncAttributeMaxDynamicSharedMemorySize, GM_SMEM);

    __nv_bfloat16 *xh, *xl, *wqh, *wql, *wph, *wpl;
    cudaGetSymbolAddress((void**)&xh,  g_xh);  cudaGetSymbolAddress((void**)&xl,  g_xl);
    cudaGetSymbolAddress((void**)&wqh, g_wqh); cudaGetSymbolAddress((void**)&wql, g_wql);
    cudaGetSymbolAddress((void**)&wph, g_wph); cudaGetSymbolAddress((void**)&wpl, g_wpl);

    // 1) input split + weight transposes
    {
        int n4 = (M_ROWS * DMODEL) / 4;
        split_kernel<<<(n4 + 255) / 256, 256>>>(x, xh, xl, n4);
        transpose_split_kernel<<<dim3(N_QKV / 32, DMODEL / 32), dim3(32, 8)>>>(
            w_attn, wqh, wql, DMODEL, N_QKV);
        transpose_split_kernel<<<dim3(DMODEL / 32, DMODEL / 32), dim3(32, 8)>>>(
            w_proj, wph, wpl, DMODEL, DMODEL);
    }
    // 2) QKV GEMM -> q(*prescale)/k bf16 hi/lo + v fp32
    gemm_kernel<0><<<dim3(N_QKV / 128, M_ROWS / 128), 256, GM_SMEM>>>(b_attn, nullptr, N_QKV);
    // 3) V transpose+split -> [b,h,hd,s] bf16 hi/lo
    transpose_split_v<<<dim3(SEQ / 32, HDIM / 32, BATCH * NHEAD), dim3(32, 8)>>>(0);
    // 4) tensor-core flash attention -> g_ah/g_al (pre-split)
    flash_kernel<<<dim3(SEQ / 128, NHEAD, BATCH), 256, FL_SMEM>>>(mask);
    // 5) proj GEMM -> out
    gemm_kernel<1><<<dim3(DMODEL / 128, M_ROWS / 128), 256, GM_SMEM>>>(b_proj, out, DMODEL);
}

// round 12
// speedup vs baseline: 4.3897x; 1.1891x over previous
#include <cuda_runtime.h>
#include <cuda_bf16.h>
#include <cuda_fp16.h>
#include <math.h>
#include <stdint.h>

// Problem constants
#define BATCH 2
#define SEQ   2048
#define DMODEL 1024
#define NHEAD 16
#define HDIM  64
#define M_ROWS (BATCH * SEQ)          // 4096
#define N_QKV  (3 * DMODEL)           // 3072
#define QK_PRESCALE 0.18033688011f    // (1/8) * log2(e): Q prescale -> exp2-domain scores
#define LOG2E_F 1.4426950408889634f

// ---------------------------------------------------------------------------
// Scratch buffers
// ---------------------------------------------------------------------------
__device__ __align__(256) float g_v[BATCH * NHEAD * SEQ * HDIM];
__device__ __align__(256) __half g_xf[M_ROWS * DMODEL];                 // x as fp16
__device__ __align__(256) __half g_af[M_ROWS * DMODEL];                 // attn out as fp16
__device__ __align__(256) __half g_wqh[N_QKV * DMODEL], g_wql[N_QKV * DMODEL];
__device__ __align__(256) __half g_wph[DMODEL * DMODEL], g_wpl[DMODEL * DMODEL];
__device__ __align__(256) __nv_bfloat16 g_qh[BATCH * NHEAD * SEQ * HDIM], g_ql[BATCH * NHEAD * SEQ * HDIM];
__device__ __align__(256) __nv_bfloat16 g_kh[BATCH * NHEAD * SEQ * HDIM], g_kl[BATCH * NHEAD * SEQ * HDIM];
__device__ __align__(256) __nv_bfloat16 g_vth[BATCH * NHEAD * SEQ * HDIM], g_vtl[BATCH * NHEAD * SEQ * HDIM];

// ---------------------------------------------------------------------------
// PTX helpers (sm_80-era: valid on compute_100 base target)
// ---------------------------------------------------------------------------
__device__ __forceinline__ uint32_t smem_u32(const void* p) {
    uint32_t a;
    asm("{ .reg .u64 t; cvta.to.shared.u64 t, %1; cvt.u32.u64 %0, t; }" : "=r"(a) : "l"(p));
    return a;
}
__device__ __forceinline__ void cp16(uint32_t saddr, const void* gaddr) {
    asm volatile("cp.async.cg.shared.global [%0], [%1], 16;" :: "r"(saddr), "l"(gaddr) : "memory");
}
__device__ __forceinline__ void cp_commit() { asm volatile("cp.async.commit_group;" ::: "memory"); }
__device__ __forceinline__ void cp_wait0()  { asm volatile("cp.async.wait_group 0;" ::: "memory"); }

__device__ __forceinline__ void ldm_x4(uint32_t* r, uint32_t addr) {
    asm volatile("ldmatrix.sync.aligned.m8n8.x4.shared.b16 {%0,%1,%2,%3}, [%4];"
        : "=r"(r[0]), "=r"(r[1]), "=r"(r[2]), "=r"(r[3]) : "r"(addr));
}
__device__ __forceinline__ void mma_bf16(float* c, const uint32_t* a, uint32_t b0, uint32_t b1) {
    asm volatile("mma.sync.aligned.m16n8k16.row.col.f32.bf16.bf16.f32 "
        "{%0,%1,%2,%3}, {%4,%5,%6,%7}, {%8,%9}, {%0,%1,%2,%3};"
        : "+f"(c[0]), "+f"(c[1]), "+f"(c[2]), "+f"(c[3])
        : "r"(a[0]), "r"(a[1]), "r"(a[2]), "r"(a[3]), "r"(b0), "r"(b1));
}
__device__ __forceinline__ void mma_f16(float* c, const uint32_t* a, uint32_t b0, uint32_t b1) {
    asm volatile("mma.sync.aligned.m16n8k16.row.col.f32.f16.f16.f32 "
        "{%0,%1,%2,%3}, {%4,%5,%6,%7}, {%8,%9}, {%0,%1,%2,%3};"
        : "+f"(c[0]), "+f"(c[1]), "+f"(c[2]), "+f"(c[3])
        : "r"(a[0]), "r"(a[1]), "r"(a[2]), "r"(a[3]), "r"(b0), "r"(b1));
}
__device__ __forceinline__ float ex2(float x) {
    float y; asm("ex2.approx.f32 %0, %1;" : "=f"(y) : "f"(x)); return y;
}

// ---------------------------------------------------------------------------
// fp32 -> fp16 convert, vectorized x4
// ---------------------------------------------------------------------------
__global__ void cvt_f16_kernel(const float* __restrict__ src,
                               __half* __restrict__ dst, int n4)
{
    int i = blockIdx.x * blockDim.x + threadIdx.x;
    if (i >= n4) return;
    float4 v = ((const float4*)src)[i];
    ((__half2*)dst)[i * 2 + 0] = __floats2half2_rn(v.x, v.y);
    ((__half2*)dst)[i * 2 + 1] = __floats2half2_rn(v.z, v.w);
}

// ---------------------------------------------------------------------------
// W[K][N] fp32 -> Th/Tl[N][K] fp16 (transpose + hi/lo split), 32x32 tiles
// ---------------------------------------------------------------------------
__global__ void transpose_split_kernel(const float* __restrict__ W,
                                       __half* __restrict__ Th,
                                       __half* __restrict__ Tl,
                                       int K, int N)
{
    __shared__ float t[32][33];
    int nb = blockIdx.x * 32, kb = blockIdx.y * 32;
    int tx = threadIdx.x, ty = threadIdx.y;   // 32 x 8
#pragma unroll
    for (int i = 0; i < 32; i += 8)
        t[ty + i][tx] = W[(size_t)(kb + ty + i) * N + nb + tx];
    __syncthreads();
#pragma unroll
    for (int i = 0; i < 32; i += 8) {
        float v = t[tx][ty + i];
        __half h = __float2half_rn(v);
        __half l = __float2half_rn(v - __half2float(h));
        size_t o = (size_t)(nb + ty + i) * K + kb + tx;
        Th[o] = h;  Tl[o] = l;
    }
}

// ---------------------------------------------------------------------------
// V [b,h,s,hd] fp32 -> V^T [b,h,hd,s] bf16 hi/lo
// ---------------------------------------------------------------------------
__global__ void transpose_split_v(int dummy)
{
    __shared__ float tt[32][33];
    const int sb = blockIdx.x * 32, hb = blockIdx.y * 32;
    const size_t base = (size_t)blockIdx.z * SEQ * HDIM;
    const int tx = threadIdx.x, ty = threadIdx.y;   // 32 x 8
#pragma unroll
    for (int i = 0; i < 32; i += 8)
        tt[ty + i][tx] = g_v[base + (size_t)(sb + ty + i) * HDIM + hb + tx];
    __syncthreads();
#pragma unroll
    for (int i = 0; i < 32; i += 8) {
        float v = tt[tx][ty + i];                       // s=sb+tx, hd=hb+ty+i
        __nv_bfloat16 h = __float2bfloat16_rn(v);
        __nv_bfloat16 l = __float2bfloat16_rn(v - __bfloat162float(h));
        size_t o = base + (size_t)(hb + ty + i) * SEQ + sb + tx;
        g_vth[o] = h;  g_vtl[o] = l;
    }
    (void)dummy;
}

// ---------------------------------------------------------------------------
// fp16 mma.sync GEMM, 2-pass hi/lo weight split: C = A@Bh^T + A@Bl^T (+bias)
// A fp16 single, B fp16 hi/lo. Block 128x128, Kc=32, 2-stage cp.async, 61KB.
// MODE 0: epilogue -> q(*prescale)/k bf16 hi/lo + v fp32.  MODE 1: Cout.
// ---------------------------------------------------------------------------
#define AS_STR 40
#define GM_TILE_B 10240                 // one 128x32 fp16 tile (stride 40)
#define GM_STAGE_B (3 * GM_TILE_B)      // A | Bh | Bl
#define GM_SMEM (2 * GM_STAGE_B)        // 61440

template <int MODE>
__global__ __launch_bounds__(256, 2) void gemm_kernel(const float* __restrict__ bias,
                                                      float* __restrict__ Cout, int Ndim)
{
    extern __shared__ __align__(16) char gsm[];
    const uint32_t sS = smem_u32(gsm);

    const int tid = threadIdx.x;
    const int wid = tid >> 5, lane = tid & 31;
    const int wm = wid >> 2, wn = wid & 3;
    const int mBase = blockIdx.y * 128;
    const int nBase = blockIdx.x * 128;

    const __half* Af = (MODE == 0) ? g_xf : g_af;
    const __half* Bh = (MODE == 0) ? g_wqh : g_wph;
    const __half* Bl = (MODE == 0) ? g_wql : g_wpl;

    auto load_stage = [&](int kc, int st) {
        const int k0 = kc * 32;
        const __half* base[3] = {
            Af + (size_t)mBase * DMODEL + k0,
            Bh + (size_t)nBase * DMODEL + k0,
            Bl + (size_t)nBase * DMODEL + k0 };
        const uint32_t stg = sS + st * GM_STAGE_B;
#pragma unroll
        for (int i = 0; i < 6; ++i) {
            int c = i * 256 + tid;                     // 1536 chunks = 3 x 512
            int tile = c >> 9, w = c & 511, r = w >> 2, cb = w & 3;
            cp16(stg + tile * GM_TILE_B + (r * AS_STR + cb * 8) * 2,
                 base[tile] + (size_t)r * DMODEL + cb * 8);
        }
        cp_commit();
    };

    float acc[4][4][4];
#pragma unroll
    for (int mi = 0; mi < 4; mi++)
#pragma unroll
        for (int ni = 0; ni < 4; ni++)
#pragma unroll
            for (int e = 0; e < 4; e++) acc[mi][ni][e] = 0.f;

    const int a_row = wm * 64 + (lane & 15);
    const int a_koff = (lane >> 4) * 8;
    const int b_row = wn * 32 + ((lane >> 4) & 1) * 8 + (lane & 7);
    const int b_koff = ((lane >> 3) & 1) * 8;

    load_stage(0, 0);

    for (int cc = 0; cc < 32; ++cc) {
        const int st = cc & 1;
        cp_wait0();
        __syncthreads();             // single barrier per chunk
        if (cc + 1 < 32) load_stage(cc + 1, 1 - st);

        const uint32_t stg = sS + st * GM_STAGE_B;
#pragma unroll
        for (int ks = 0; ks < 2; ++ks) {
            uint32_t af[4][4], bh[2][4], bl[2][4];
#pragma unroll
            for (int mi = 0; mi < 4; mi++)
                ldm_x4(af[mi], stg + ((a_row + mi * 16) * AS_STR + ks * 16 + a_koff) * 2);
#pragma unroll
            for (int bt = 0; bt < 2; bt++)
                ldm_x4(bh[bt], stg + GM_TILE_B + ((b_row + bt * 16) * AS_STR + ks * 16 + b_koff) * 2);
#pragma unroll
            for (int mi = 0; mi < 4; mi++)
#pragma unroll
                for (int ni = 0; ni < 4; ni++)
                    mma_f16(acc[mi][ni], af[mi], bh[ni >> 1][(ni & 1) * 2],
                            bh[ni >> 1][(ni & 1) * 2 + 1]);
#pragma unroll
            for (int bt = 0; bt < 2; bt++)
                ldm_x4(bl[bt], stg + 2 * GM_TILE_B + ((b_row + bt * 16) * AS_STR + ks * 16 + b_koff) * 2);
#pragma unroll
            for (int mi = 0; mi < 4; mi++)
#pragma unroll
                for (int ni = 0; ni < 4; ni++)
                    mma_f16(acc[mi][ni], af[mi], bl[ni >> 1][(ni & 1) * 2],
                            bl[ni >> 1][(ni & 1) * 2 + 1]);
        }
    }

    const int gid = lane >> 2, tig = lane & 3;
#pragma unroll
    for (int mi = 0; mi < 4; mi++) {
#pragma unroll
        for (int half = 0; half < 2; half++) {
            const int m = mBase + wm * 64 + mi * 16 + gid + half * 8;
#pragma unroll
            for (int ni = 0; ni < 4; ni++) {
                const int n = nBase + wn * 32 + ni * 8 + tig * 2;
                float2 val;
                val.x = acc[mi][ni][half * 2 + 0] + bias[n];
                val.y = acc[mi][ni][half * 2 + 1] + bias[n + 1];
                if (MODE == 1) {
                    *(float2*)(Cout + (size_t)m * Ndim + n) = val;
                } else {
                    const int b = m >> 11, srow = m & 2047;
                    const int sec = n >> 10, dd = n & 1023;
                    const int hh = dd >> 6, hd = dd & 63;
                    const size_t idx = (((size_t)(b * NHEAD + hh)) * SEQ + srow) * HDIM + hd;
                    if (sec == 2) {
                        *(float2*)(g_v + idx) = val;
                    } else {
                        if (sec == 0) { val.x *= QK_PRESCALE; val.y *= QK_PRESCALE; }
                        __nv_bfloat16 hx = __float2bfloat16_rn(val.x);
                        __nv_bfloat16 hy = __float2bfloat16_rn(val.y);
                        __nv_bfloat16 lx = __float2bfloat16_rn(val.x - __bfloat162float(hx));
                        __nv_bfloat16 ly = __float2bfloat16_rn(val.y - __bfloat162float(hy));
                        __nv_bfloat16* dh = (sec == 0) ? g_qh : g_kh;
                        __nv_bfloat16* dl = (sec == 0) ? g_ql : g_kl;
                        *(__nv_bfloat162*)(dh + idx) = __nv_bfloat162(hx, hy);
                        *(__nv_bfloat162*)(dl + idx) = __nv_bfloat162(lx, ly);
                    }
                }
            }
        }
    }
}

// ---------------------------------------------------------------------------
// Tensor-core flash attention (R11 engine, passing): FA2 in-register P,
// exp2-domain softmax, K+V double-buffered, one barrier/iter.
// Epilogue now writes single fp16 g_af for the 2-pass proj GEMM.
// ---------------------------------------------------------------------------
#define FL_SMEM 110592

__global__ __launch_bounds__(256, 2) void flash_kernel(const float* __restrict__ mask)
{
    extern __shared__ __align__(16) char fsm[];
    const uint32_t S0 = smem_u32(fsm);
    const uint32_t sQh = S0, sQl = S0 + 18432;
    const uint32_t sK  = S0 + 36864;   // [st][h|l], stage stride 18432, l at +9216
    const uint32_t sV  = S0 + 73728;   // [st][h|l], stage stride 18432, l at +9216

    const int qb = blockIdx.x * 128;
    const int h  = blockIdx.y, b = blockIdx.z;
    const int bh = b * NHEAD + h;
    const int tid = threadIdx.x, wid = tid >> 5, lane = tid & 31;

    const __nv_bfloat16* Qhg = g_qh + (size_t)bh * SEQ * HDIM;
    const __nv_bfloat16* Qlg = g_ql + (size_t)bh * SEQ * HDIM;
    const __nv_bfloat16* Khg = g_kh + (size_t)bh * SEQ * HDIM;
    const __nv_bfloat16* Klg = g_kl + (size_t)bh * SEQ * HDIM;
    const __nv_bfloat16* Vhg = g_vth + (size_t)bh * SEQ * HDIM;  // [hd][s]
    const __nv_bfloat16* Vlg = g_vtl + (size_t)bh * SEQ * HDIM;
    const float* maskb = mask + (size_t)b * SEQ;

    auto load_KV = [&](int kb, int st) {
        const uint32_t kh = sK + st * 18432, kl = kh + 9216;
        const uint32_t vh = sV + st * 18432, vl = vh + 9216;
        for (int i = tid; i < 512; i += 256) {
            int r = i >> 3, cb = i & 7;
            uint32_t so = (r * 72 + cb * 8) * 2;
            cp16(kh + so, Khg + (size_t)(kb + r) * HDIM + cb * 8);
            cp16(kl + so, Klg + (size_t)(kb + r) * HDIM + cb * 8);
            cp16(vh + so, Vhg + (size_t)r * SEQ + kb + cb * 8);
            cp16(vl + so, Vlg + (size_t)r * SEQ + kb + cb * 8);
        }
    };

    // prologue: Q + K0 + V0 as one commit group
    for (int i = tid; i < 1024; i += 256) {
        int r = i >> 3, cb = i & 7;
        uint32_t so = (r * 72 + cb * 8) * 2;
        cp16(sQh + so, Qhg + (size_t)(qb + r) * HDIM + cb * 8);
        cp16(sQl + so, Qlg + (size_t)(qb + r) * HDIM + cb * 8);
    }
    load_KV(0, 0);
    cp_commit();

    float m_s[2], l_s[2], oacc[8][4];
#pragma unroll
    for (int i = 0; i < 2; i++) { m_s[i] = -INFINITY; l_s[i] = 0.f; }
#pragma unroll
    for (int ni = 0; ni < 8; ni++)
#pragma unroll
        for (int e = 0; e < 4; e++) oacc[ni][e] = 0.f;

    const int a_base = lane & 15, a_koff = (lane >> 4) * 8;
    const int b_base = ((lane >> 4) & 1) * 8 + (lane & 7), b_koff = ((lane >> 3) & 1) * 8;
    const int g = lane >> 2, tig = lane & 3;
    const int arow_off = wid * 16 + a_base;

    for (int t = 0; t < 32; ++t) {
        const int st = t & 1;
        cp_wait0();                         // K_t, V_t (and Q on t=0) complete
        __syncthreads();                    // all warps done with stage st^1 (iter t-1)
        if (t + 1 < 32) { load_KV((t + 1) * 64, st ^ 1); cp_commit(); }

        const uint32_t kh = sK + st * 18432, kl = kh + 9216;
        const uint32_t vh = sV + st * 18432, vl = vh + 9216;

        // ---- S = Q @ K^T, fragment-reuse split passes ----
        float sacc[8][4];
#pragma unroll
        for (int ni = 0; ni < 8; ni++)
#pragma unroll
            for (int e = 0; e < 4; e++) sacc[ni][e] = 0.f;

#pragma unroll
        for (int ks = 0; ks < 4; ++ks) {
            uint32_t aqh[4], aql[4], bf[4][4];
            ldm_x4(aqh, sQh + (arow_off * 72 + ks * 16 + a_koff) * 2);
#pragma unroll
            for (int bt = 0; bt < 4; bt++)
                ldm_x4(bf[bt], kh + ((bt * 16 + b_base) * 72 + ks * 16 + b_koff) * 2);
#pragma unroll
            for (int ni = 0; ni < 8; ni++)
                mma_bf16(sacc[ni], aqh, bf[ni >> 1][(ni & 1) * 2], bf[ni >> 1][(ni & 1) * 2 + 1]);
            ldm_x4(aql, sQl + (arow_off * 72 + ks * 16 + a_koff) * 2);
#pragma unroll
            for (int ni = 0; ni < 8; ni++)
                mma_bf16(sacc[ni], aql, bf[ni >> 1][(ni & 1) * 2], bf[ni >> 1][(ni & 1) * 2 + 1]);
#pragma unroll
            for (int bt = 0; bt < 4; bt++)
                ldm_x4(bf[bt], kl + ((bt * 16 + b_base) * 72 + ks * 16 + b_koff) * 2);
#pragma unroll
            for (int ni = 0; ni < 8; ni++)
                mma_bf16(sacc[ni], aqh, bf[ni >> 1][(ni & 1) * 2], bf[ni >> 1][(ni & 1) * 2 + 1]);
        }

        // ---- online softmax in exp2 domain; pack P hi/lo IN PLACE into sacc ----
        const int kbase = t * 64 + tig * 2;
#pragma unroll
        for (int half = 0; half < 2; ++half) {
            float vmax = -INFINITY;
#pragma unroll
            for (int ni = 0; ni < 8; ++ni) {
                float v0 = fmaf(maskb[kbase + ni * 8],     LOG2E_F, sacc[ni][half * 2 + 0]);
                float v1 = fmaf(maskb[kbase + ni * 8 + 1], LOG2E_F, sacc[ni][half * 2 + 1]);
                sacc[ni][half * 2 + 0] = v0; sacc[ni][half * 2 + 1] = v1;
                vmax = fmaxf(vmax, fmaxf(v0, v1));
            }
            vmax = fmaxf(vmax, __shfl_xor_sync(0xffffffffu, vmax, 1));
            vmax = fmaxf(vmax, __shfl_xor_sync(0xffffffffu, vmax, 2));
            float mnew = fmaxf(m_s[half], vmax);
            float alpha = ex2(m_s[half] - mnew);
            m_s[half] = mnew;
            float sum = 0.f;
#pragma unroll
            for (int ni = 0; ni < 8; ++ni) {
                float p0 = ex2(sacc[ni][half * 2 + 0] - mnew);
                float p1 = ex2(sacc[ni][half * 2 + 1] - mnew);
                sum += p0 + p1;
                __nv_bfloat162 hh = __float22bfloat162_rn(make_float2(p0, p1));
                uint32_t uh = *(uint32_t*)&hh;
                float f0 = __uint_as_float(uh << 16);
                float f1 = __uint_as_float(uh & 0xFFFF0000u);
                __nv_bfloat162 ll = __float22bfloat162_rn(make_float2(p0 - f0, p1 - f1));
                uint32_t ul = *(uint32_t*)&ll;
                sacc[ni][half * 2 + 0] = __uint_as_float(uh);
                sacc[ni][half * 2 + 1] = __uint_as_float(ul);
            }
            sum += __shfl_xor_sync(0xffffffffu, sum, 1);
            sum += __shfl_xor_sync(0xffffffffu, sum, 2);
            l_s[half] = l_s[half] * alpha + sum;
#pragma unroll
            for (int ni = 0; ni < 8; ++ni) {
                oacc[ni][half * 2 + 0] *= alpha;
                oacc[ni][half * 2 + 1] *= alpha;
            }
        }

        // ---- O += P @ V, P A-fragments straight from sacc registers ----
#pragma unroll
        for (int ks = 0; ks < 4; ++ks) {
            uint32_t ph[4] = { __float_as_uint(sacc[2 * ks][0]), __float_as_uint(sacc[2 * ks][2]),
                               __float_as_uint(sacc[2 * ks + 1][0]), __float_as_uint(sacc[2 * ks + 1][2]) };
            uint32_t pl[4] = { __float_as_uint(sacc[2 * ks][1]), __float_as_uint(sacc[2 * ks][3]),
                               __float_as_uint(sacc[2 * ks + 1][1]), __float_as_uint(sacc[2 * ks + 1][3]) };
            uint32_t bf[4][4];
#pragma unroll
            for (int bt = 0; bt < 4; bt++)
                ldm_x4(bf[bt], vh + ((bt * 16 + b_base) * 72 + ks * 16 + b_koff) * 2);
#pragma unroll
            for (int ni = 0; ni < 8; ni++)
                mma_bf16(oacc[ni], ph, bf[ni >> 1][(ni & 1) * 2], bf[ni >> 1][(ni & 1) * 2 + 1]);
#pragma unroll
            for (int ni = 0; ni < 8; ni++)
                mma_bf16(oacc[ni], pl, bf[ni >> 1][(ni & 1) * 2], bf[ni >> 1][(ni & 1) * 2 + 1]);
#pragma unroll
            for (int bt = 0; bt < 4; bt++)
                ldm_x4(bf[bt], vl + ((bt * 16 + b_base) * 72 + ks * 16 + b_koff) * 2);
#pragma unroll
            for (int ni = 0; ni < 8; ni++)
                mma_bf16(oacc[ni], ph, bf[ni >> 1][(ni & 1) * 2], bf[ni >> 1][(ni & 1) * 2 + 1]);
        }
    }

    // ---- epilogue: O / l -> g_af (fp16, for 2-pass proj GEMM) ----
#pragma unroll
    for (int half = 0; half < 2; ++half) {
        const float inv = 1.f / l_s[half];
        const int srow = qb + wid * 16 + g + half * 8;
        const size_t rowoff = ((size_t)b * SEQ + srow) * DMODEL + h * HDIM + tig * 2;
#pragma unroll
        for (int ni = 0; ni < 8; ++ni) {
            float v0 = oacc[ni][half * 2 + 0] * inv;
            float v1 = oacc[ni][half * 2 + 1] * inv;
            *(__half2*)(g_af + rowoff + ni * 8) = __floats2half2_rn(v0, v1);
        }
    }
}

// ---------------------------------------------------------------------------
extern "C" void kernel_launch(void* const* d_in, const int* in_sizes, int n_in,
                              void* d_out, int out_size)
{
    (void)in_sizes; (void)n_in; (void)out_size;
    const float* x       = (const float*)d_in[0];
    const float* mask    = (const float*)d_in[1];
    const float* w_attn  = (const float*)d_in[2];
    const float* b_attn  = (const float*)d_in[3];
    const float* w_proj  = (const float*)d_in[4];
    const float* b_proj  = (const float*)d_in[5];
    float* out = (float*)d_out;

    cudaFuncSetAttribute(flash_kernel, cudaFuncAttributeMaxDynamicSharedMemorySize, FL_SMEM);
    cudaFuncSetAttribute(gemm_kernel<0>, cudaFuncAttributeMaxDynamicSharedMemorySize, GM_SMEM);
    cudaFuncSetAttribute(gemm_kernel<1>, cudaFuncAttributeMaxDynamicSharedMemorySize, GM_SMEM);

    __half *xf, *wqh, *wql, *wph, *wpl;
    cudaGetSymbolAddress((void**)&xf,  g_xf);
    cudaGetSymbolAddress((void**)&wqh, g_wqh); cudaGetSymbolAddress((void**)&wql, g_wql);
    cudaGetSymbolAddress((void**)&wph, g_wph); cudaGetSymbolAddress((void**)&wpl, g_wpl);

    // 1) input fp16 convert + weight transposes (fp16 hi/lo)
    {
        int n4 = (M_ROWS * DMODEL) / 4;
        cvt_f16_kernel<<<(n4 + 255) / 256, 256>>>(x, xf, n4);
        transpose_split_kernel<<<dim3(N_QKV / 32, DMODEL / 32), dim3(32, 8)>>>(
            w_attn, wqh, wql, DMODEL, N_QKV);
        transpose_split_kernel<<<dim3(DMODEL / 32, DMODEL / 32), dim3(32, 8)>>>(
            w_proj, wph, wpl, DMODEL, DMODEL);
    }
    // 2) QKV GEMM (fp16 2-pass) -> q(*prescale)/k bf16 hi/lo + v fp32
    gemm_kernel<0><<<dim3(N_QKV / 128, M_ROWS / 128), 256, GM_SMEM>>>(b_attn, nullptr, N_QKV);
    // 3) V transpose+split -> [b,h,hd,s] bf16 hi/lo
    transpose_split_v<<<dim3(SEQ / 32, HDIM / 32, BATCH * NHEAD), dim3(32, 8)>>>(0);
    // 4) tensor-core flash attention -> g_af (fp16)
    flash_kernel<<<dim3(SEQ / 128, NHEAD, BATCH), 256, FL_SMEM>>>(mask);
    // 5) proj GEMM (fp16 2-pass) -> out
    gemm_kernel<1><<<dim3(DMODEL / 128, M_ROWS / 128), 256, GM_SMEM>>>(b_proj, out, DMODEL);
}

// round 16
// speedup vs baseline: 4.9345x; 1.1241x over previous
#include <cuda_runtime.h>
#include <cuda_bf16.h>
#include <cuda_fp16.h>
#include <math.h>
#include <stdint.h>

// Problem constants
#define BATCH 2
#define SEQ   2048
#define DMODEL 1024
#define NHEAD 16
#define HDIM  64
#define M_ROWS (BATCH * SEQ)          // 4096
#define N_QKV  (3 * DMODEL)           // 3072
#define QK_PRESCALE 0.18033688011f    // (1/8) * log2(e): Q prescale -> exp2-domain scores
#define LOG2E_F 1.4426950408889634f

// ---------------------------------------------------------------------------
// Scratch buffers
// ---------------------------------------------------------------------------
__device__ __align__(256) float g_v[BATCH * NHEAD * SEQ * HDIM];
__device__ __align__(256) __half g_xf[M_ROWS * DMODEL];                 // x as fp16
__device__ __align__(256) __half g_af[M_ROWS * DMODEL];                 // attn out as fp16
__device__ __align__(256) __half g_wqh[N_QKV * DMODEL], g_wql[N_QKV * DMODEL];
__device__ __align__(256) __half g_wph[DMODEL * DMODEL], g_wpl[DMODEL * DMODEL];
__device__ __align__(256) __half g_qf[BATCH * NHEAD * SEQ * HDIM];      // Q fp16 single (prescaled)
__device__ __align__(256) __half g_kh[BATCH * NHEAD * SEQ * HDIM], g_kl[BATCH * NHEAD * SEQ * HDIM];
__device__ __align__(256) __half g_vth[BATCH * NHEAD * SEQ * HDIM], g_vtl[BATCH * NHEAD * SEQ * HDIM];

// ---------------------------------------------------------------------------
// PTX helpers (sm_80-era: valid on compute_100 base target)
// ---------------------------------------------------------------------------
__device__ __forceinline__ uint32_t smem_u32(const void* p) {
    uint32_t a;
    asm("{ .reg .u64 t; cvta.to.shared.u64 t, %1; cvt.u32.u64 %0, t; }" : "=r"(a) : "l"(p));
    return a;
}
__device__ __forceinline__ void cp16(uint32_t saddr, const void* gaddr) {
    asm volatile("cp.async.cg.shared.global [%0], [%1], 16;" :: "r"(saddr), "l"(gaddr) : "memory");
}
__device__ __forceinline__ void cp_commit() { asm volatile("cp.async.commit_group;" ::: "memory"); }
__device__ __forceinline__ void cp_wait0()  { asm volatile("cp.async.wait_group 0;" ::: "memory"); }

__device__ __forceinline__ void ldm_x4(uint32_t* r, uint32_t addr) {
    asm volatile("ldmatrix.sync.aligned.m8n8.x4.shared.b16 {%0,%1,%2,%3}, [%4];"
        : "=r"(r[0]), "=r"(r[1]), "=r"(r[2]), "=r"(r[3]) : "r"(addr));
}
__device__ __forceinline__ void mma_f16(float* c, const uint32_t* a, uint32_t b0, uint32_t b1) {
    asm volatile("mma.sync.aligned.m16n8k16.row.col.f32.f16.f16.f32 "
        "{%0,%1,%2,%3}, {%4,%5,%6,%7}, {%8,%9}, {%0,%1,%2,%3};"
        : "+f"(c[0]), "+f"(c[1]), "+f"(c[2]), "+f"(c[3])
        : "r"(a[0]), "r"(a[1]), "r"(a[2]), "r"(a[3]), "r"(b0), "r"(b1));
}
__device__ __forceinline__ float ex2(float x) {
    float y; asm("ex2.approx.f32 %0, %1;" : "=f"(y) : "f"(x)); return y;
}

// ---------------------------------------------------------------------------
// fp32 -> fp16 convert, vectorized x4
// ---------------------------------------------------------------------------
__global__ void cvt_f16_kernel(const float* __restrict__ src,
                               __half* __restrict__ dst, int n4)
{
    int i = blockIdx.x * blockDim.x + threadIdx.x;
    if (i >= n4) return;
    float4 v = ((const float4*)src)[i];
    ((__half2*)dst)[i * 2 + 0] = __floats2half2_rn(v.x, v.y);
    ((__half2*)dst)[i * 2 + 1] = __floats2half2_rn(v.z, v.w);
}

// ---------------------------------------------------------------------------
// W[K][N] fp32 -> Th/Tl[N][K] fp16 (transpose + hi/lo split), 32x32 tiles
// ---------------------------------------------------------------------------
__global__ void transpose_split_kernel(const float* __restrict__ W,
                                       __half* __restrict__ Th,
                                       __half* __restrict__ Tl,
                                       int K, int N)
{
    __shared__ float t[32][33];
    int nb = blockIdx.x * 32, kb = blockIdx.y * 32;
    int tx = threadIdx.x, ty = threadIdx.y;   // 32 x 8
#pragma unroll
    for (int i = 0; i < 32; i += 8)
        t[ty + i][tx] = W[(size_t)(kb + ty + i) * N + nb + tx];
    __syncthreads();
#pragma unroll
    for (int i = 0; i < 32; i += 8) {
        float v = t[tx][ty + i];
        __half h = __float2half_rn(v);
        __half l = __float2half_rn(v - __half2float(h));
        size_t o = (size_t)(nb + ty + i) * K + kb + tx;
        Th[o] = h;  Tl[o] = l;
    }
}

// ---------------------------------------------------------------------------
// V [b,h,s,hd] fp32 -> V^T [b,h,hd,s] fp16 hi/lo
// ---------------------------------------------------------------------------
__global__ void transpose_split_v(int dummy)
{
    __shared__ float tt[32][33];
    const int sb = blockIdx.x * 32, hb = blockIdx.y * 32;
    const size_t base = (size_t)blockIdx.z * SEQ * HDIM;
    const int tx = threadIdx.x, ty = threadIdx.y;   // 32 x 8
#pragma unroll
    for (int i = 0; i < 32; i += 8)
        tt[ty + i][tx] = g_v[base + (size_t)(sb + ty + i) * HDIM + hb + tx];
    __syncthreads();
#pragma unroll
    for (int i = 0; i < 32; i += 8) {
        float v = tt[tx][ty + i];                       // s=sb+tx, hd=hb+ty+i
        __half h = __float2half_rn(v);
        __half l = __float2half_rn(v - __half2float(h));
        size_t o = base + (size_t)(hb + ty + i) * SEQ + sb + tx;
        g_vth[o] = h;  g_vtl[o] = l;
    }
    (void)dummy;
}

// ---------------------------------------------------------------------------
// fp16 mma.sync GEMM, 2-pass hi/lo weight split (R12 engine, passing).
// MODE 0: epilogue -> q fp16 single (*prescale) / k fp16 hi/lo / v fp32.
// MODE 1: -> Cout.
// ---------------------------------------------------------------------------
#define AS_STR 40
#define GM_TILE_B 10240                 // one 128x32 fp16 tile (stride 40)
#define GM_STAGE_B (3 * GM_TILE_B)      // A | Bh | Bl
#define GM_SMEM (2 * GM_STAGE_B)        // 61440

template <int MODE>
__global__ __launch_bounds__(256, 2) void gemm_kernel(const float* __restrict__ bias,
                                                      float* __restrict__ Cout, int Ndim)
{
    extern __shared__ __align__(16) char gsm[];
    const uint32_t sS = smem_u32(gsm);

    const int tid = threadIdx.x;
    const int wid = tid >> 5, lane = tid & 31;
    const int wm = wid >> 2, wn = wid & 3;
    const int mBase = blockIdx.y * 128;
    const int nBase = blockIdx.x * 128;

    const __half* Af = (MODE == 0) ? g_xf : g_af;
    const __half* Bh = (MODE == 0) ? g_wqh : g_wph;
    const __half* Bl = (MODE == 0) ? g_wql : g_wpl;

    auto load_stage = [&](int kc, int st) {
        const int k0 = kc * 32;
        const __half* base[3] = {
            Af + (size_t)mBase * DMODEL + k0,
            Bh + (size_t)nBase * DMODEL + k0,
            Bl + (size_t)nBase * DMODEL + k0 };
        const uint32_t stg = sS + st * GM_STAGE_B;
#pragma unroll
        for (int i = 0; i < 6; ++i) {
            int c = i * 256 + tid;                     // 1536 chunks = 3 x 512
            int tile = c >> 9, w = c & 511, r = w >> 2, cb = w & 3;
            cp16(stg + tile * GM_TILE_B + (r * AS_STR + cb * 8) * 2,
                 base[tile] + (size_t)r * DMODEL + cb * 8);
        }
        cp_commit();
    };

    float acc[4][4][4];
#pragma unroll
    for (int mi = 0; mi < 4; mi++)
#pragma unroll
        for (int ni = 0; ni < 4; ni++)
#pragma unroll
            for (int e = 0; e < 4; e++) acc[mi][ni][e] = 0.f;

    const int a_row = wm * 64 + (lane & 15);
    const int a_koff = (lane >> 4) * 8;
    const int b_row = wn * 32 + ((lane >> 4) & 1) * 8 + (lane & 7);
    const int b_koff = ((lane >> 3) & 1) * 8;

    load_stage(0, 0);

    for (int cc = 0; cc < 32; ++cc) {
        const int st = cc & 1;
        cp_wait0();
        __syncthreads();             // single barrier per chunk
        if (cc + 1 < 32) load_stage(cc + 1, 1 - st);

        const uint32_t stg = sS + st * GM_STAGE_B;
#pragma unroll
        for (int ks = 0; ks < 2; ++ks) {
            uint32_t af[4][4], bh[2][4], bl[2][4];
#pragma unroll
            for (int mi = 0; mi < 4; mi++)
                ldm_x4(af[mi], stg + ((a_row + mi * 16) * AS_STR + ks * 16 + a_koff) * 2);
#pragma unroll
            for (int bt = 0; bt < 2; bt++)
                ldm_x4(bh[bt], stg + GM_TILE_B + ((b_row + bt * 16) * AS_STR + ks * 16 + b_koff) * 2);
#pragma unroll
            for (int mi = 0; mi < 4; mi++)
#pragma unroll
                for (int ni = 0; ni < 4; ni++)
                    mma_f16(acc[mi][ni], af[mi], bh[ni >> 1][(ni & 1) * 2],
                            bh[ni >> 1][(ni & 1) * 2 + 1]);
#pragma unroll
            for (int bt = 0; bt < 2; bt++)
                ldm_x4(bl[bt], stg + 2 * GM_TILE_B + ((b_row + bt * 16) * AS_STR + ks * 16 + b_koff) * 2);
#pragma unroll
            for (int mi = 0; mi < 4; mi++)
#pragma unroll
                for (int ni = 0; ni < 4; ni++)
                    mma_f16(acc[mi][ni], af[mi], bl[ni >> 1][(ni & 1) * 2],
                            bl[ni >> 1][(ni & 1) * 2 + 1]);
        }
    }

    const int gid = lane >> 2, tig = lane & 3;
#pragma unroll
    for (int mi = 0; mi < 4; mi++) {
#pragma unroll
        for (int half = 0; half < 2; half++) {
            const int m = mBase + wm * 64 + mi * 16 + gid + half * 8;
#pragma unroll
            for (int ni = 0; ni < 4; ni++) {
                const int n = nBase + wn * 32 + ni * 8 + tig * 2;
                float2 val;
                val.x = acc[mi][ni][half * 2 + 0] + bias[n];
                val.y = acc[mi][ni][half * 2 + 1] + bias[n + 1];
                if (MODE == 1) {
                    *(float2*)(Cout + (size_t)m * Ndim + n) = val;
                } else {
                    const int b = m >> 11, srow = m & 2047;
                    const int sec = n >> 10, dd = n & 1023;
                    const int hh = dd >> 6, hd = dd & 63;
                    const size_t idx = (((size_t)(b * NHEAD + hh)) * SEQ + srow) * HDIM + hd;
                    if (sec == 2) {
                        *(float2*)(g_v + idx) = val;
                    } else if (sec == 0) {
                        val.x *= QK_PRESCALE; val.y *= QK_PRESCALE;
                        *(__half2*)(g_qf + idx) = __floats2half2_rn(val.x, val.y);
                    } else {
                        __half hx = __float2half_rn(val.x);
                        __half hy = __float2half_rn(val.y);
                        __half lx = __float2half_rn(val.x - __half2float(hx));
                        __half ly = __float2half_rn(val.y - __half2float(hy));
                        *(__half2*)(g_kh + idx) = __halves2half2(hx, hy);
                        *(__half2*)(g_kl + idx) = __halves2half2(lx, ly);
                    }
                }
            }
        }
    }
}

// ---------------------------------------------------------------------------
// Tensor-core flash attention, fp16 2+2-pass:
//   QK: Qf (single fp16) @ (Kh + Kl);  PV: Pf (single fp16) @ (Vh + Vl).
// FA2 in-register P, exp2-domain softmax, K+V double-buffered, one
// barrier/iter. smem 92160B -> 2 CTAs/SM. 128 warp-mma/iter (was 192).
// FIX vs R14: Q prologue loads ALL 1024 chunks (128 rows), not 512.
// ---------------------------------------------------------------------------
#define FL_SMEM 92160

__global__ __launch_bounds__(256, 2) void flash_kernel(const float* __restrict__ mask)
{
    extern __shared__ __align__(16) char fsm[];
    const uint32_t S0 = smem_u32(fsm);
    const uint32_t sQ = S0;            // Q fp16 single, 128 rows x 72 halfs = 18432B
    const uint32_t sK = S0 + 18432;    // [st][h|l], stage stride 18432, l at +9216
    const uint32_t sV = S0 + 55296;    // [st][h|l], stage stride 18432, l at +9216

    const int qb = blockIdx.x * 128;
    const int h  = blockIdx.y, b = blockIdx.z;
    const int bh = b * NHEAD + h;
    const int tid = threadIdx.x, wid = tid >> 5, lane = tid & 31;

    const __half* Qg  = g_qf + (size_t)bh * SEQ * HDIM;
    const __half* Khg = g_kh + (size_t)bh * SEQ * HDIM;
    const __half* Klg = g_kl + (size_t)bh * SEQ * HDIM;
    const __half* Vhg = g_vth + (size_t)bh * SEQ * HDIM;  // [hd][s]
    const __half* Vlg = g_vtl + (size_t)bh * SEQ * HDIM;
    const float* maskb = mask + (size_t)b * SEQ;

    auto load_KV = [&](int kb, int st) {
        const uint32_t kh = sK + st * 18432, kl = kh + 9216;
        const uint32_t vh = sV + st * 18432, vl = vh + 9216;
        for (int i = tid; i < 512; i += 256) {
            int r = i >> 3, cb = i & 7;
            uint32_t so = (r * 72 + cb * 8) * 2;
            cp16(kh + so, Khg + (size_t)(kb + r) * HDIM + cb * 8);
            cp16(kl + so, Klg + (size_t)(kb + r) * HDIM + cb * 8);
            cp16(vh + so, Vhg + (size_t)r * SEQ + kb + cb * 8);
            cp16(vl + so, Vlg + (size_t)r * SEQ + kb + cb * 8);
        }
    };

    // prologue: FULL Q tile (128 rows = 1024 x 16B chunks) + K0 + V0
    for (int i = tid; i < 1024; i += 256) {
        int r = i >> 3, cb = i & 7;
        cp16(sQ + (r * 72 + cb * 8) * 2, Qg + (size_t)(qb + r) * HDIM + cb * 8);
    }
    load_KV(0, 0);
    cp_commit();

    float m_s[2], l_s[2], oacc[8][4];
#pragma unroll
    for (int i = 0; i < 2; i++) { m_s[i] = -INFINITY; l_s[i] = 0.f; }
#pragma unroll
    for (int ni = 0; ni < 8; ni++)
#pragma unroll
        for (int e = 0; e < 4; e++) oacc[ni][e] = 0.f;

    const int a_base = lane & 15, a_koff = (lane >> 4) * 8;
    const int b_base = ((lane >> 4) & 1) * 8 + (lane & 7), b_koff = ((lane >> 3) & 1) * 8;
    const int g = lane >> 2, tig = lane & 3;
    const int arow_off = wid * 16 + a_base;

    for (int t = 0; t < 32; ++t) {
        const int st = t & 1;
        cp_wait0();                         // K_t, V_t (and Q on t=0) complete
        __syncthreads();                    // all warps done with stage st^1 (iter t-1)
        if (t + 1 < 32) { load_KV((t + 1) * 64, st ^ 1); cp_commit(); }

        const uint32_t kh = sK + st * 18432, kl = kh + 9216;
        const uint32_t vh = sV + st * 18432, vl = vh + 9216;

        // ---- S = Q @ K^T : Qf @ Kh + Qf @ Kl ----
        float sacc[8][4];
#pragma unroll
        for (int ni = 0; ni < 8; ni++)
#pragma unroll
            for (int e = 0; e < 4; e++) sacc[ni][e] = 0.f;

#pragma unroll
        for (int ks = 0; ks < 4; ++ks) {
            uint32_t aq[4], bf[4][4];
            ldm_x4(aq, sQ + (arow_off * 72 + ks * 16 + a_koff) * 2);
#pragma unroll
            for (int bt = 0; bt < 4; bt++)
                ldm_x4(bf[bt], kh + ((bt * 16 + b_base) * 72 + ks * 16 + b_koff) * 2);
#pragma unroll
            for (int ni = 0; ni < 8; ni++)
                mma_f16(sacc[ni], aq, bf[ni >> 1][(ni & 1) * 2], bf[ni >> 1][(ni & 1) * 2 + 1]);
#pragma unroll
            for (int bt = 0; bt < 4; bt++)
                ldm_x4(bf[bt], kl + ((bt * 16 + b_base) * 72 + ks * 16 + b_koff) * 2);
#pragma unroll
            for (int ni = 0; ni < 8; ni++)
                mma_f16(sacc[ni], aq, bf[ni >> 1][(ni & 1) * 2], bf[ni >> 1][(ni & 1) * 2 + 1]);
        }

        // ---- online softmax in exp2 domain; pack P fp16 IN PLACE into sacc ----
        // slots per ni: [0] = packed pair rows g, [2] = packed pair rows g+8
        const int kbase = t * 64 + tig * 2;
#pragma unroll
        for (int half = 0; half < 2; ++half) {
            float vmax = -INFINITY;
#pragma unroll
            for (int ni = 0; ni < 8; ++ni) {
                float v0 = fmaf(maskb[kbase + ni * 8],     LOG2E_F, sacc[ni][half * 2 + 0]);
                float v1 = fmaf(maskb[kbase + ni * 8 + 1], LOG2E_F, sacc[ni][half * 2 + 1]);
                sacc[ni][half * 2 + 0] = v0; sacc[ni][half * 2 + 1] = v1;
                vmax = fmaxf(vmax, fmaxf(v0, v1));
            }
            vmax = fmaxf(vmax, __shfl_xor_sync(0xffffffffu, vmax, 1));
            vmax = fmaxf(vmax, __shfl_xor_sync(0xffffffffu, vmax, 2));
            float mnew = fmaxf(m_s[half], vmax);
            float alpha = ex2(m_s[half] - mnew);
            m_s[half] = mnew;
            float sum = 0.f;
#pragma unroll
            for (int ni = 0; ni < 8; ++ni) {
                float p0 = ex2(sacc[ni][half * 2 + 0] - mnew);
                float p1 = ex2(sacc[ni][half * 2 + 1] - mnew);
                sum += p0 + p1;
                __half2 pp = __floats2half2_rn(make_float2(p0, p1).x, make_float2(p0, p1).y);
                sacc[ni][half * 2 + 0] = __uint_as_float(*(uint32_t*)&pp);
            }
            sum += __shfl_xor_sync(0xffffffffu, sum, 1);
            sum += __shfl_xor_sync(0xffffffffu, sum, 2);
            l_s[half] = l_s[half] * alpha + sum;
#pragma unroll
            for (int ni = 0; ni < 8; ++ni) {
                oacc[ni][half * 2 + 0] *= alpha;
                oacc[ni][half * 2 + 1] *= alpha;
            }
        }

        // ---- O += P @ V : Pf @ Vh + Pf @ Vl ----
#pragma unroll
        for (int ks = 0; ks < 4; ++ks) {
            uint32_t pf[4] = { __float_as_uint(sacc[2 * ks][0]), __float_as_uint(sacc[2 * ks][2]),
                               __float_as_uint(sacc[2 * ks + 1][0]), __float_as_uint(sacc[2 * ks + 1][2]) };
            uint32_t bf[4][4];
#pragma unroll
            for (int bt = 0; bt < 4; bt++)
                ldm_x4(bf[bt], vh + ((bt * 16 + b_base) * 72 + ks * 16 + b_koff) * 2);
#pragma unroll
            for (int ni = 0; ni < 8; ni++)
                mma_f16(oacc[ni], pf, bf[ni >> 1][(ni & 1) * 2], bf[ni >> 1][(ni & 1) * 2 + 1]);
#pragma unroll
            for (int bt = 0; bt < 4; bt++)
                ldm_x4(bf[bt], vl + ((bt * 16 + b_base) * 72 + ks * 16 + b_koff) * 2);
#pragma unroll
            for (int ni = 0; ni < 8; ni++)
                mma_f16(oacc[ni], pf, bf[ni >> 1][(ni & 1) * 2], bf[ni >> 1][(ni & 1) * 2 + 1]);
        }
    }

    // ---- epilogue: O / l -> g_af (fp16, for 2-pass proj GEMM) ----
#pragma unroll
    for (int half = 0; half < 2; ++half) {
        const float inv = 1.f / l_s[half];
        const int srow = qb + wid * 16 + g + half * 8;
        const size_t rowoff = ((size_t)b * SEQ + srow) * DMODEL + h * HDIM + tig * 2;
#pragma unroll
        for (int ni = 0; ni < 8; ++ni) {
            float v0 = oacc[ni][half * 2 + 0] * inv;
            float v1 = oacc[ni][half * 2 + 1] * inv;
            *(__half2*)(g_af + rowoff + ni * 8) = __floats2half2_rn(v0, v1);
        }
    }
}

// ---------------------------------------------------------------------------
extern "C" void kernel_launch(void* const* d_in, const int* in_sizes, int n_in,
                              void* d_out, int out_size)
{
    (void)in_sizes; (void)n_in; (void)out_size;
    const float* x       = (const float*)d_in[0];
    const float* mask    = (const float*)d_in[1];
    const float* w_attn  = (const float*)d_in[2];
    const float* b_attn  = (const float*)d_in[3];
    const float* w_proj  = (const float*)d_in[4];
    const float* b_proj  = (const float*)d_in[5];
    float* out = (float*)d_out;

    cudaFuncSetAttribute(flash_kernel, cudaFuncAttributeMaxDynamicSharedMemorySize, FL_SMEM);
    cudaFuncSetAttribute(gemm_kernel<0>, cudaFuncAttributeMaxDynamicSharedMemorySize, GM_SMEM);
    cudaFuncSetAttribute(gemm_kernel<1>, cudaFuncAttributeMaxDynamicSharedMemorySize, GM_SMEM);

    __half *xf, *wqh, *wql, *wph, *wpl;
    cudaGetSymbolAddress((void**)&xf,  g_xf);
    cudaGetSymbolAddress((void**)&wqh, g_wqh); cudaGetSymbolAddress((void**)&wql, g_wql);
    cudaGetSymbolAddress((void**)&wph, g_wph); cudaGetSymbolAddress((void**)&wpl, g_wpl);

    // 1) input fp16 convert + weight transposes (fp16 hi/lo)
    {
        int n4 = (M_ROWS * DMODEL) / 4;
        cvt_f16_kernel<<<(n4 + 255) / 256, 256>>>(x, xf, n4);
        transpose_split_kernel<<<dim3(N_QKV / 32, DMODEL / 32), dim3(32, 8)>>>(
            w_attn, wqh, wql, DMODEL, N_QKV);
        transpose_split_kernel<<<dim3(DMODEL / 32, DMODEL / 32), dim3(32, 8)>>>(
            w_proj, wph, wpl, DMODEL, DMODEL);
    }
    // 2) QKV GEMM (fp16 2-pass) -> q fp16 (*prescale) / k fp16 hi/lo / v fp32
    gemm_kernel<0><<<dim3(N_QKV / 128, M_ROWS / 128), 256, GM_SMEM>>>(b_attn, nullptr, N_QKV);
    // 3) V transpose+split -> [b,h,hd,s] fp16 hi/lo
    transpose_split_v<<<dim3(SEQ / 32, HDIM / 32, BATCH * NHEAD), dim3(32, 8)>>>(0);
    // 4) tensor-core flash attention (fp16 2+2) -> g_af
    flash_kernel<<<dim3(SEQ / 128, NHEAD, BATCH), 256, FL_SMEM>>>(mask);
    // 5) proj GEMM (fp16 2-pass) -> out
    gemm_kernel<1><<<dim3(DMODEL / 128, M_ROWS / 128), 256, GM_SMEM>>>(b_proj, out, DMODEL);
}